// round 1
// baseline (speedup 1.0000x reference)
#include <cuda_runtime.h>
#include <math.h>
#include <stdint.h>

// ---------------- constants ----------------
static const int TSEQ = 2048;
static const int DMODEL = 1024;
static const int NHEAD = 16;
static const int HDIM = 64;
static const int DFFN = 4096;
static const int NEXP = 8;
static const int HIDX = 4;
static const int DIDX = 64;
static const int KSEL = 512;

// ---------------- device scratch ----------------
__device__ float g_xn[TSEQ * DMODEL];
__device__ float g_qi[TSEQ * HIDX * DIDX];
__device__ float g_ki[TSEQ * DIDX];
__device__ float g_hw[TSEQ * HIDX];
__device__ float g_qb[TSEQ * DMODEL];
__device__ float g_kb[TSEQ * DMODEL];
__device__ float g_vb[TSEQ * DMODEL];
__device__ float g_qh[TSEQ * DMODEL];
__device__ float g_kh[TSEQ * DMODEL];
__device__ float g_vh[TSEQ * DMODEL];
__device__ int   g_top[TSEQ * KSEL];
__device__ float g_av[TSEQ * DMODEL];
__device__ float g_x1[TSEQ * DMODEL];
__device__ float g_x2n[TSEQ * DMODEL];
__device__ float g_probs[TSEQ * NEXP];
__device__ int   g_topE[TSEQ * 2];
__device__ float g_topG[TSEQ * 2];
__device__ int   g_counts[NEXP];
__device__ int   g_segoff[NEXP + 1];
__device__ int   g_rowmap[TSEQ * 2];
__device__ int   g_slotpos[TSEQ * 2];
__device__ float g_mid[(size_t)(TSEQ * 2) * DFFN];
__device__ float g_yy[(size_t)(TSEQ * 2) * DMODEL];

// ---------------- helpers ----------------
__device__ __forceinline__ float gelu_tanh(float x) {
    float x3 = x * x * x;
    float u = 0.7978845608028654f * (x + 0.044715f * x3);
    return 0.5f * x * (1.0f + tanhf(u));
}

__device__ __forceinline__ unsigned int fmono(float f) {
    unsigned int u = __float_as_uint(f);
    return (u & 0x80000000u) ? ~u : (u | 0x80000000u);
}

// ---------------- rmsnorm ----------------
__global__ __launch_bounds__(256) void rmsnorm_kernel(
    const float* __restrict__ x, const float* __restrict__ w, float* __restrict__ y)
{
    int t = blockIdx.x, tid = threadIdx.x;
    __shared__ float red[256];
    const float* xr = x + (size_t)t * DMODEL;
    float s = 0.f;
    for (int d = tid; d < DMODEL; d += 256) { float v = xr[d]; s += v * v; }
    red[tid] = s; __syncthreads();
    for (int o = 128; o > 0; o >>= 1) { if (tid < o) red[tid] += red[tid + o]; __syncthreads(); }
    float rms = rsqrtf(red[0] / (float)DMODEL + 1e-6f);
    float* yr = y + (size_t)t * DMODEL;
    for (int d = tid; d < DMODEL; d += 256) yr[d] = xr[d] * rms * w[d];
}

// ---------------- dense SGEMM: C[M,N] = A[M,K]@B[K,N] (+residual) ----------------
// BM=BN=128, BK=8, 256 threads, TM=TN=8. M multiple of 128, K multiple of 8.
__global__ __launch_bounds__(256) void sgemm_dense(
    const float* __restrict__ A, const float* __restrict__ B,
    const float* __restrict__ residual, float* __restrict__ C,
    int M, int N, int K)
{
    __shared__ float As[8][128];
    __shared__ float Bs[8][128];
    int tid = threadIdx.x;
    int rowStart = blockIdx.y * 128, colStart = blockIdx.x * 128;
    int aRow = tid >> 1, aCol = (tid & 1) * 4;
    int bRow = tid >> 5, bCol = (tid & 31) * 4;
    const int tr = (tid >> 4) * 8, tc = (tid & 15) * 8;
    float acc[8][8];
#pragma unroll
    for (int i = 0; i < 8; i++)
#pragma unroll
        for (int j = 0; j < 8; j++) acc[i][j] = 0.f;

    const float* Aptr = A + (size_t)(rowStart + aRow) * K + aCol;
    for (int k0 = 0; k0 < K; k0 += 8) {
        float4 a4 = *(const float4*)(Aptr + k0);
        As[aCol + 0][aRow] = a4.x; As[aCol + 1][aRow] = a4.y;
        As[aCol + 2][aRow] = a4.z; As[aCol + 3][aRow] = a4.w;
        int bc = colStart + bCol;
        float4 b4;
        if (bc + 3 < N) {
            b4 = *(const float4*)(B + (size_t)(k0 + bRow) * N + bc);
        } else {
            b4.x = (bc + 0 < N) ? B[(size_t)(k0 + bRow) * N + bc + 0] : 0.f;
            b4.y = (bc + 1 < N) ? B[(size_t)(k0 + bRow) * N + bc + 1] : 0.f;
            b4.z = (bc + 2 < N) ? B[(size_t)(k0 + bRow) * N + bc + 2] : 0.f;
            b4.w = (bc + 3 < N) ? B[(size_t)(k0 + bRow) * N + bc + 3] : 0.f;
        }
        *(float4*)&Bs[bRow][bCol] = b4;
        __syncthreads();
#pragma unroll
        for (int kk = 0; kk < 8; kk++) {
            float4 ra0 = *(const float4*)&As[kk][tr];
            float4 ra1 = *(const float4*)&As[kk][tr + 4];
            float4 rb0 = *(const float4*)&Bs[kk][tc];
            float4 rb1 = *(const float4*)&Bs[kk][tc + 4];
            float ra[8] = {ra0.x, ra0.y, ra0.z, ra0.w, ra1.x, ra1.y, ra1.z, ra1.w};
            float rb[8] = {rb0.x, rb0.y, rb0.z, rb0.w, rb1.x, rb1.y, rb1.z, rb1.w};
#pragma unroll
            for (int i = 0; i < 8; i++)
#pragma unroll
                for (int j = 0; j < 8; j++) acc[i][j] += ra[i] * rb[j];
        }
        __syncthreads();
    }
#pragma unroll
    for (int i = 0; i < 8; i++) {
        int row = rowStart + tr + i;
#pragma unroll
        for (int j = 0; j < 8; j++) {
            int col = colStart + tc + j;
            if (col < N) {
                float v = acc[i][j];
                if (residual) v += residual[(size_t)row * N + col];
                C[(size_t)row * N + col] = v;
            }
        }
    }
}

// ---------------- MoE grouped SGEMM (gather rows, per-expert weights, bias, optional gelu) ----------------
__global__ __launch_bounds__(256) void sgemm_moe(
    const float* __restrict__ Abase, int lda,
    const int* __restrict__ rowmap,
    const float* __restrict__ Bbase, long long strideB,
    const float* __restrict__ biasBase, int biasStride,
    float* __restrict__ Cbase, int ldc,
    const int* __restrict__ segoff,
    int N, int K, int doGelu)
{
    int e = blockIdx.z;
    int s0 = segoff[e];
    int nrows = segoff[e + 1] - s0;
    int rt = blockIdx.y;
    if (rt * 128 >= nrows) return;
    const float* B = Bbase + (long long)e * strideB;
    const float* bias = biasBase + (long long)e * biasStride;

    __shared__ float As[8][128];
    __shared__ float Bs[8][128];
    int tid = threadIdx.x;
    int aRow = tid >> 1, aCol = (tid & 1) * 4;
    int bRow = tid >> 5, bCol = (tid & 31) * 4;
    const int tr = (tid >> 4) * 8, tc = (tid & 15) * 8;
    int colStart = blockIdx.x * 128;

    int localRow = rt * 128 + aRow;
    bool aValid = localRow < nrows;
    const float* Aptr = Abase;  // dummy
    if (aValid) {
        int rowIdx = rowmap ? rowmap[s0 + localRow] : (s0 + localRow);
        Aptr = Abase + (size_t)rowIdx * lda + aCol;
    }
    float acc[8][8];
#pragma unroll
    for (int i = 0; i < 8; i++)
#pragma unroll
        for (int j = 0; j < 8; j++) acc[i][j] = 0.f;

    for (int k0 = 0; k0 < K; k0 += 8) {
        float4 a4 = aValid ? *(const float4*)(Aptr + k0) : make_float4(0.f, 0.f, 0.f, 0.f);
        As[aCol + 0][aRow] = a4.x; As[aCol + 1][aRow] = a4.y;
        As[aCol + 2][aRow] = a4.z; As[aCol + 3][aRow] = a4.w;
        float4 b4 = *(const float4*)(B + (size_t)(k0 + bRow) * N + colStart + bCol);
        *(float4*)&Bs[bRow][bCol] = b4;
        __syncthreads();
#pragma unroll
        for (int kk = 0; kk < 8; kk++) {
            float4 ra0 = *(const float4*)&As[kk][tr];
            float4 ra1 = *(const float4*)&As[kk][tr + 4];
            float4 rb0 = *(const float4*)&Bs[kk][tc];
            float4 rb1 = *(const float4*)&Bs[kk][tc + 4];
            float ra[8] = {ra0.x, ra0.y, ra0.z, ra0.w, ra1.x, ra1.y, ra1.z, ra1.w};
            float rb[8] = {rb0.x, rb0.y, rb0.z, rb0.w, rb1.x, rb1.y, rb1.z, rb1.w};
#pragma unroll
            for (int i = 0; i < 8; i++)
#pragma unroll
                for (int j = 0; j < 8; j++) acc[i][j] += ra[i] * rb[j];
        }
        __syncthreads();
    }
#pragma unroll
    for (int i = 0; i < 8; i++) {
        int lr = rt * 128 + tr + i;
        if (lr >= nrows) continue;
        int gr = s0 + lr;
#pragma unroll
        for (int j = 0; j < 8; j++) {
            int col = colStart + tc + j;
            float v = acc[i][j] + bias[col];
            if (doGelu) v = gelu_tanh(v);
            Cbase[(size_t)gr * ldc + col] = v;
        }
    }
}

// ---------------- indexer scores: idx[t][s] = 0.125 * sum_h hw[t][h]*relu(qi[t,h,:].ki[s,:]) ----------------
__global__ __launch_bounds__(256) void idx_kernel(
    const float* __restrict__ qi, const float* __restrict__ ki,
    const float* __restrict__ hw, float* __restrict__ out)
{
    __shared__ float qsh[64][65];
    __shared__ float ksh[64][65];
    __shared__ float hsh[64][4];
    int t0 = blockIdx.y * 64, s0 = blockIdx.x * 64;
    int tid = threadIdx.x;
    const int tr = (tid >> 4) * 4, tc = (tid & 15) * 4;

    hsh[tid >> 2][tid & 3] = hw[(size_t)(t0 + (tid >> 2)) * HIDX + (tid & 3)];
    for (int i = tid; i < 4096; i += 256) {
        int r = i >> 6, c = i & 63;
        ksh[r][c] = ki[(size_t)(s0 + r) * DIDX + c];
    }
    float acc[4][4];
#pragma unroll
    for (int i = 0; i < 4; i++)
#pragma unroll
        for (int j = 0; j < 4; j++) acc[i][j] = 0.f;

    for (int h = 0; h < HIDX; h++) {
        __syncthreads();
        for (int i = tid; i < 4096; i += 256) {
            int r = i >> 6, c = i & 63;
            qsh[r][c] = qi[(size_t)(t0 + r) * (HIDX * DIDX) + h * DIDX + c];
        }
        __syncthreads();
        float dot[4][4];
#pragma unroll
        for (int i = 0; i < 4; i++)
#pragma unroll
            for (int j = 0; j < 4; j++) dot[i][j] = 0.f;
        for (int kk = 0; kk < 64; kk++) {
            float a[4], b[4];
#pragma unroll
            for (int i = 0; i < 4; i++) a[i] = qsh[tr + i][kk];
#pragma unroll
            for (int j = 0; j < 4; j++) b[j] = ksh[tc + j][kk];
#pragma unroll
            for (int i = 0; i < 4; i++)
#pragma unroll
                for (int j = 0; j < 4; j++) dot[i][j] += a[i] * b[j];
        }
#pragma unroll
        for (int i = 0; i < 4; i++)
#pragma unroll
            for (int j = 0; j < 4; j++)
                acc[i][j] += hsh[tr + i][h] * fmaxf(dot[i][j], 0.f);
    }
#pragma unroll
    for (int i = 0; i < 4; i++)
#pragma unroll
        for (int j = 0; j < 4; j++)
            out[(size_t)(t0 + tr + i) * TSEQ + (s0 + tc + j)] = acc[i][j] * 0.125f;
}

// ---------------- top-512 per row via bitonic sort (stable: value desc, index asc) ----------------
__global__ __launch_bounds__(1024) void topk_kernel(
    const float* __restrict__ idxs, int* __restrict__ topIdx)
{
    __shared__ unsigned long long key[2048];
    int t = blockIdx.x, tid = threadIdx.x;
    for (int i = tid; i < 2048; i += 1024) {
        unsigned long long kk = 0ull;
        if (i <= t) {
            float v = idxs[(size_t)t * TSEQ + i];
            kk = ((unsigned long long)fmono(v) << 32) | (unsigned int)(2047 - i);
        }
        key[i] = kk;
    }
    __syncthreads();
    for (int k = 2; k <= 2048; k <<= 1) {
        for (int j = k >> 1; j > 0; j >>= 1) {
            for (int i = tid; i < 2048; i += 1024) {
                int ixj = i ^ j;
                if (ixj > i) {
                    unsigned long long a = key[i], b = key[ixj];
                    bool descSeg = ((i & k) == 0);
                    if (descSeg ? (a < b) : (a > b)) { key[i] = b; key[ixj] = a; }
                }
            }
            __syncthreads();
        }
    }
    if (tid < KSEL)
        topIdx[(size_t)t * KSEL + tid] = 2047 - (int)(key[tid] & 0xFFFFFFFFu);
}

// ---------------- RoPE + transpose to [h][t][d] ----------------
__global__ __launch_bounds__(256) void rope_kernel(
    const float* __restrict__ qb, const float* __restrict__ kb, const float* __restrict__ vb,
    float* __restrict__ qh, float* __restrict__ kh, float* __restrict__ vh)
{
    int idx = blockIdx.x * 256 + threadIdx.x;  // over TSEQ*DMODEL
    int t = idx >> 10;
    int hd = idx & 1023;
    int h = hd >> 6, d = hd & 63;
    int j = d & 31;
    double invd = exp(-((double)(2 * j) / 64.0) * log(10000.0));
    float ang = (float)((double)t * invd);
    float c = cosf(ang), s = sinf(ang);
    float q = qb[idx], k = kb[idx];
    float qr, kr;
    if (d < 32) {
        qr = q * c - qb[idx + 32] * s;
        kr = k * c - kb[idx + 32] * s;
    } else {
        qr = q * c + qb[idx - 32] * s;
        kr = k * c + kb[idx - 32] * s;
    }
    int o = ((h * TSEQ) + t) * HDIM + d;
    qh[o] = qr; kh[o] = kr; vh[o] = vb[idx];
}

// ---------------- sparse attention: one block per (t,h) ----------------
__global__ __launch_bounds__(256) void attn_kernel(
    const float* __restrict__ qh, const float* __restrict__ kh, const float* __restrict__ vh,
    const int* __restrict__ topIdx, float* __restrict__ av)
{
    int t = blockIdx.x, h = blockIdx.y;
    __shared__ float qs[64];
    __shared__ float sc[512];
    __shared__ int   ss[512];
    __shared__ float red[256];
    __shared__ float outp[4][64];
    int tid = threadIdx.x, lane = tid & 31, w = tid >> 5;

    if (tid < 64) qs[tid] = qh[((size_t)(h * TSEQ) + t) * HDIM + tid];
    for (int j = tid; j < 512; j += 256) {
        int s = topIdx[(size_t)t * KSEL + j];
        ss[j] = (s <= t) ? s : -1;
    }
    __syncthreads();

    const float* kbase = kh + (size_t)h * TSEQ * HDIM;
    for (int j = w; j < 512; j += 8) {
        int s = ss[j];
        float dres = -INFINITY;
        if (s >= 0) {
            const float* kr = kbase + (size_t)s * HDIM;
            float p = qs[lane] * kr[lane] + qs[lane + 32] * kr[lane + 32];
#pragma unroll
            for (int o = 16; o > 0; o >>= 1) p += __shfl_xor_sync(0xFFFFFFFFu, p, o);
            dres = p * 0.125f;
        }
        if (lane == 0) sc[j] = dres;
    }
    __syncthreads();

    // max
    float m = -INFINITY;
    for (int j = tid; j < 512; j += 256) m = fmaxf(m, sc[j]);
    red[tid] = m; __syncthreads();
    for (int o = 128; o > 0; o >>= 1) { if (tid < o) red[tid] = fmaxf(red[tid], red[tid + o]); __syncthreads(); }
    m = red[0]; __syncthreads();

    // exp + sum
    float sum = 0.f;
    for (int j = tid; j < 512; j += 256) {
        float e = expf(sc[j] - m);  // exp(-inf - m) = 0
        sc[j] = e;
        sum += e;
    }
    red[tid] = sum; __syncthreads();
    for (int o = 128; o > 0; o >>= 1) { if (tid < o) red[tid] += red[tid + o]; __syncthreads(); }
    float inv = 1.f / red[0];
    __syncthreads();

    // AV
    int d0 = tid & 63, g = tid >> 6;
    float a = 0.f;
    const float* vbase = vh + (size_t)h * TSEQ * HDIM;
    for (int j = g; j < 512; j += 4) {
        int s = ss[j];
        if (s >= 0) a += sc[j] * vbase[(size_t)s * HDIM + d0];
    }
    outp[g][d0] = a;
    __syncthreads();
    if (tid < 64) {
        float r = (outp[0][tid] + outp[1][tid]) + (outp[2][tid] + outp[3][tid]);
        av[(size_t)t * DMODEL + h * HDIM + tid] = r * inv;
    }
}

// ---------------- router: logits -> softmax -> stable top-2 ----------------
__global__ __launch_bounds__(256) void router_kernel(
    const float* __restrict__ x2n, const float* __restrict__ rw, const float* __restrict__ rb,
    float* __restrict__ probs, int* __restrict__ topE, float* __restrict__ topG)
{
    int t = blockIdx.x, tid = threadIdx.x;
    __shared__ float red[256];
    __shared__ float lg[8];
    float acc[8];
#pragma unroll
    for (int e = 0; e < 8; e++) acc[e] = 0.f;
    const float* xr = x2n + (size_t)t * DMODEL;
    for (int d = tid; d < DMODEL; d += 256) {
        float xv = xr[d];
#pragma unroll
        for (int e = 0; e < 8; e++) acc[e] += xv * rw[(size_t)d * NEXP + e];
    }
    for (int e = 0; e < 8; e++) {
        red[tid] = acc[e]; __syncthreads();
        for (int o = 128; o > 0; o >>= 1) { if (tid < o) red[tid] += red[tid + o]; __syncthreads(); }
        if (tid == 0) lg[e] = red[0] + rb[e];
        __syncthreads();
    }
    if (tid == 0) {
        float m = lg[0];
        for (int e = 1; e < 8; e++) m = fmaxf(m, lg[e]);
        float p[8], s = 0.f;
        for (int e = 0; e < 8; e++) { p[e] = expf(lg[e] - m); s += p[e]; }
        for (int e = 0; e < 8; e++) p[e] /= s;
        int e0 = 0;
        for (int e = 1; e < 8; e++) if (p[e] > p[e0]) e0 = e;
        int e1 = -1;
        for (int e = 0; e < 8; e++) if (e != e0 && (e1 < 0 || p[e] > p[e1])) e1 = e;
        float denom = p[e0] + p[e1];
        for (int e = 0; e < 8; e++) probs[(size_t)t * NEXP + e] = p[e];
        topE[t * 2 + 0] = e0; topE[t * 2 + 1] = e1;
        topG[t * 2 + 0] = p[e0] / denom; topG[t * 2 + 1] = p[e1] / denom;
    }
}

// ---------------- deterministic grouping (serial per expert) ----------------
__global__ void group_kernel(const int* __restrict__ topE, int* __restrict__ counts,
                             int* __restrict__ segoff, int* __restrict__ rowmap,
                             int* __restrict__ slotpos)
{
    int e = threadIdx.x;  // blockDim = 8
    int c = 0;
    for (int t = 0; t < TSEQ; t++)
        for (int s = 0; s < 2; s++)
            if (topE[t * 2 + s] == e) c++;
    counts[e] = c;
    __syncthreads();
    if (e == 0) {
        int o = 0;
        for (int i = 0; i < 8; i++) { segoff[i] = o; o += counts[i]; }
        segoff[8] = o;
    }
    __syncthreads();
    int pos = segoff[e];
    for (int t = 0; t < TSEQ; t++)
        for (int s = 0; s < 2; s++)
            if (topE[t * 2 + s] == e) {
                rowmap[pos] = t;
                slotpos[t * 2 + s] = pos;
                pos++;
            }
}

// ---------------- aux loss ----------------
__global__ __launch_bounds__(256) void aux_kernel(
    const float* __restrict__ probs, const int* __restrict__ counts, float* __restrict__ outAux)
{
    __shared__ float red[256];
    int tid = threadIdx.x;
    float a = 0.f;
    for (int e = 0; e < 8; e++) {
        float s = 0.f;
        for (int t = tid; t < TSEQ; t += 256) s += probs[(size_t)t * NEXP + e];
        red[tid] = s; __syncthreads();
        for (int o = 128; o > 0; o >>= 1) { if (tid < o) red[tid] += red[tid + o]; __syncthreads(); }
        if (tid == 0) a += (float)counts[e] * red[0];
        __syncthreads();
    }
    if (tid == 0) *outAux = 8.f * a / ((float)TSEQ * (float)TSEQ);
}

// ---------------- final combine: out = x1 + g0*y[p0] + g1*y[p1] ----------------
__global__ __launch_bounds__(256) void combine_kernel(
    const float* __restrict__ x1, const float* __restrict__ y,
    const int* __restrict__ slotpos, const float* __restrict__ topG,
    float* __restrict__ out)
{
    int idx = blockIdx.x * 256 + threadIdx.x;  // TSEQ*DMODEL
    int t = idx >> 10, d = idx & 1023;
    int p0 = slotpos[t * 2 + 0], p1 = slotpos[t * 2 + 1];
    float g0 = topG[t * 2 + 0], g1 = topG[t * 2 + 1];
    out[idx] = x1[idx] + g0 * y[(size_t)p0 * DMODEL + d] + g1 * y[(size_t)p1 * DMODEL + d];
}

// ---------------- host launch ----------------
#define GETSYM(ptr, sym) do { void* _p_; cudaGetSymbolAddress(&_p_, sym); ptr = (decltype(ptr))_p_; } while (0)

extern "C" void kernel_launch(void* const* d_in, const int* in_sizes, int n_in,
                              void* d_out, int out_size)
{
    const float* x        = (const float*)d_in[0];
    const float* norm1_w  = (const float*)d_in[1];
    const float* norm2_w  = (const float*)d_in[2];
    const float* wq_idx   = (const float*)d_in[3];
    const float* wk_idx   = (const float*)d_in[4];
    const float* w_head   = (const float*)d_in[5];
    const float* wq       = (const float*)d_in[6];
    const float* wk       = (const float*)d_in[7];
    const float* wv       = (const float*)d_in[8];
    const float* wo       = (const float*)d_in[9];
    const float* router_w = (const float*)d_in[10];
    const float* router_b = (const float*)d_in[11];
    const float* w1       = (const float*)d_in[12];
    const float* b1       = (const float*)d_in[13];
    const float* w2       = (const float*)d_in[14];
    const float* b2       = (const float*)d_in[15];

    float* out    = (float*)d_out;                       // [2048*1024]
    float* auxp   = out + (size_t)TSEQ * DMODEL;         // [1]
    float* idxout = auxp + 1;                            // [2048*2048]

    float *p_xn, *p_qi, *p_ki, *p_hw, *p_qb, *p_kb, *p_vb, *p_qh, *p_kh, *p_vh;
    float *p_av, *p_x1, *p_x2n, *p_probs, *p_topG, *p_mid, *p_y;
    int *p_top, *p_topE, *p_counts, *p_segoff, *p_rowmap, *p_slotpos;
    GETSYM(p_xn, g_xn); GETSYM(p_qi, g_qi); GETSYM(p_ki, g_ki); GETSYM(p_hw, g_hw);
    GETSYM(p_qb, g_qb); GETSYM(p_kb, g_kb); GETSYM(p_vb, g_vb);
    GETSYM(p_qh, g_qh); GETSYM(p_kh, g_kh); GETSYM(p_vh, g_vh);
    GETSYM(p_top, g_top); GETSYM(p_av, g_av); GETSYM(p_x1, g_x1); GETSYM(p_x2n, g_x2n);
    GETSYM(p_probs, g_probs); GETSYM(p_topE, g_topE); GETSYM(p_topG, g_topG);
    GETSYM(p_counts, g_counts); GETSYM(p_segoff, g_segoff);
    GETSYM(p_rowmap, g_rowmap); GETSYM(p_slotpos, g_slotpos);
    GETSYM(p_mid, g_mid); GETSYM(p_y, g_yy);

    // 1. norm1
    rmsnorm_kernel<<<TSEQ, 256>>>(x, norm1_w, p_xn);

    // 2. indexer + attention projections
    sgemm_dense<<<dim3(2, 16), 256>>>(p_xn, wq_idx, nullptr, p_qi, TSEQ, HIDX * DIDX, DMODEL);
    sgemm_dense<<<dim3(1, 16), 256>>>(p_xn, wk_idx, nullptr, p_ki, TSEQ, DIDX, DMODEL);
    sgemm_dense<<<dim3(1, 16), 256>>>(p_xn, w_head, nullptr, p_hw, TSEQ, HIDX, DMODEL);
    sgemm_dense<<<dim3(8, 16), 256>>>(p_xn, wq, nullptr, p_qb, TSEQ, DMODEL, DMODEL);
    sgemm_dense<<<dim3(8, 16), 256>>>(p_xn, wk, nullptr, p_kb, TSEQ, DMODEL, DMODEL);
    sgemm_dense<<<dim3(8, 16), 256>>>(p_xn, wv, nullptr, p_vb, TSEQ, DMODEL, DMODEL);

    // 3. indexer scores (also an output) + top-512
    idx_kernel<<<dim3(32, 32), 256>>>(p_qi, p_ki, p_hw, idxout);
    topk_kernel<<<TSEQ, 1024>>>(idxout, p_top);

    // 4. rope + transpose
    rope_kernel<<<(TSEQ * DMODEL) / 256, 256>>>(p_qb, p_kb, p_vb, p_qh, p_kh, p_vh);

    // 5. sparse attention
    attn_kernel<<<dim3(TSEQ, NHEAD), 256>>>(p_qh, p_kh, p_vh, p_top, p_av);

    // 6. output projection + residual
    sgemm_dense<<<dim3(8, 16), 256>>>(p_av, wo, x, p_x1, TSEQ, DMODEL, DMODEL);

    // 7. norm2 + router + grouping + aux
    rmsnorm_kernel<<<TSEQ, 256>>>(p_x1, norm2_w, p_x2n);
    router_kernel<<<TSEQ, 256>>>(p_x2n, router_w, router_b, p_probs, p_topE, p_topG);
    group_kernel<<<1, 8>>>(p_topE, p_counts, p_segoff, p_rowmap, p_slotpos);
    aux_kernel<<<1, 256>>>(p_probs, p_counts, auxp);

    // 8. MoE grouped GEMMs
    sgemm_moe<<<dim3(DFFN / 128, 16, NEXP), 256>>>(
        p_x2n, DMODEL, p_rowmap, w1, (long long)DMODEL * DFFN, b1, DFFN,
        p_mid, DFFN, p_segoff, DFFN, DMODEL, 1);
    sgemm_moe<<<dim3(DMODEL / 128, 16, NEXP), 256>>>(
        p_mid, DFFN, nullptr, w2, (long long)DFFN * DMODEL, b2, DMODEL,
        p_y, DMODEL, p_segoff, DMODEL, DFFN, 0);

    // 9. combine
    combine_kernel<<<(TSEQ * DMODEL) / 256, 256>>>(p_x1, p_y, p_slotpos, p_topG, out);
}

// round 2
// speedup vs baseline: 1.8699x; 1.8699x over previous
#include <cuda_runtime.h>
#include <math.h>
#include <stdint.h>

// ---------------- constants ----------------
static const int TSEQ = 2048;
static const int DMODEL = 1024;
static const int NHEAD = 16;
static const int HDIM = 64;
static const int DFFN = 4096;
static const int NEXP = 8;
static const int HIDX = 4;
static const int DIDX = 64;
static const int KSEL = 512;

// ---------------- device scratch ----------------
__device__ float g_xn[TSEQ * DMODEL];
__device__ float g_qi[TSEQ * HIDX * DIDX];
__device__ float g_ki[TSEQ * DIDX];
__device__ float g_hw[TSEQ * HIDX];
__device__ float g_qb[TSEQ * DMODEL];
__device__ float g_kb[TSEQ * DMODEL];
__device__ float g_vb[TSEQ * DMODEL];
__device__ float g_qh[TSEQ * DMODEL];
__device__ float g_kh[TSEQ * DMODEL];
__device__ float g_vh[TSEQ * DMODEL];
__device__ int   g_top[TSEQ * KSEL];
__device__ float g_av[TSEQ * DMODEL];
__device__ float g_x1[TSEQ * DMODEL];
__device__ float g_x2n[TSEQ * DMODEL];
__device__ float g_probs[TSEQ * NEXP];
__device__ int   g_topE[TSEQ * 2];
__device__ float g_topG[TSEQ * 2];
__device__ int   g_counts[NEXP];
__device__ int   g_segoff[NEXP + 1];
__device__ int   g_rowmap[TSEQ * 2];
__device__ int   g_slotpos[TSEQ * 2];
__device__ float g_mid[(size_t)(TSEQ * 2) * DFFN];
__device__ float g_yy[(size_t)(TSEQ * 2) * DMODEL];

// ---------------- helpers ----------------
__device__ __forceinline__ float gelu_tanh(float x) {
    float x3 = x * x * x;
    float u = 0.7978845608028654f * (x + 0.044715f * x3);
    return 0.5f * x * (1.0f + tanhf(u));
}

__device__ __forceinline__ unsigned int fmono(float f) {
    unsigned int u = __float_as_uint(f);
    return (u & 0x80000000u) ? ~u : (u | 0x80000000u);
}

__device__ __forceinline__ uint32_t f2tf32(float f) {
    uint32_t r;
    asm("cvt.rna.tf32.f32 %0, %1;" : "=r"(r) : "f"(f));
    return r;
}

__device__ __forceinline__ void cp16(uint32_t dst, const float* src, int sz) {
    asm volatile("cp.async.cg.shared.global [%0], [%1], 16, %2;" :: "r"(dst), "l"(src), "r"(sz));
}

__device__ __forceinline__ void mma_tf32(float* c, const uint32_t* a, const uint32_t* b) {
    asm volatile(
        "mma.sync.aligned.m16n8k8.row.col.f32.tf32.tf32.f32 "
        "{%0,%1,%2,%3}, {%4,%5,%6,%7}, {%8,%9}, {%0,%1,%2,%3};"
        : "+f"(c[0]), "+f"(c[1]), "+f"(c[2]), "+f"(c[3])
        : "r"(a[0]), "r"(a[1]), "r"(a[2]), "r"(a[3]), "r"(b[0]), "r"(b[1]));
}

// ---------------- unified tf32 tensor GEMM ----------------
// C[grow, 0..N) = gather(A) @ B[e]  (+bias, +gelu, +residual)
// BM=BN=128, BK=32, 256 threads, 8 warps of 64x32, 2-stage cp.async pipeline.
#define BKM 128
#define BKN 128
#define BKK 32
#define LDA_S 36
#define LDB_S 132
#define A_STAGE (BKM * LDA_S)
#define B_STAGE (BKK * LDB_S)
#define STAGE_FLOATS (A_STAGE + B_STAGE)
#define TG_SMEM_BYTES (2 * STAGE_FLOATS * 4)

extern __shared__ float smem_dyn[];

__global__ void __launch_bounds__(256, 1) tgemm(
    const float* __restrict__ A, int lda,
    const int* __restrict__ rowmap,
    const float* __restrict__ Bbase, long long strideB,
    const float* __restrict__ biasBase, int biasStride,
    const float* __restrict__ residual,
    float* __restrict__ C, int ldc,
    const int* __restrict__ segoff,
    int M, int N, int K, int doGelu)
{
    int e = blockIdx.z;
    int s0 = 0, nrows = M;
    if (segoff) { s0 = segoff[e]; nrows = segoff[e + 1] - s0; }
    int rowTile = blockIdx.y;
    if (rowTile * BKM >= nrows) return;
    int colStart = blockIdx.x * BKN;
    const float* B = Bbase + (long long)e * strideB;

    int tid = threadIdx.x;
    int warpId = tid >> 5, lane = tid & 31;
    int grp = lane >> 2, tig = lane & 3;
    int wm = (warpId >> 2) * 64;
    int wn = (warpId & 3) * 32;

    uint32_t sbase = (uint32_t)__cvta_generic_to_shared(smem_dyn);

    // --- precompute per-thread load descriptors ---
    const float* aSrc[4]; int aSz[4]; uint32_t aDst[4];
    const float* bSrc[4]; int bSz[4]; uint32_t bDst[4];
#pragma unroll
    for (int i = 0; i < 4; i++) {
        int c = tid + i * 256;
        int arow = c >> 3, akc = (c & 7) * 4;
        int lrow = rowTile * BKM + arow;
        bool v = lrow < nrows;
        int gidx = 0;
        if (v) {
            int base = s0 + lrow;
            gidx = rowmap ? rowmap[base] : base;
        }
        aSrc[i] = A + (size_t)gidx * lda + akc;
        aSz[i] = v ? 16 : 0;
        aDst[i] = (uint32_t)((arow * LDA_S + akc) * 4);

        int brow = c >> 5, bnc = (c & 31) * 4;
        int col = colStart + bnc;
        bool bv = (col + 4 <= N);
        bSz[i] = bv ? 16 : 0;
        bSrc[i] = B + (size_t)brow * N + (bv ? col : 0);
        bDst[i] = (uint32_t)((A_STAGE + brow * LDB_S + bnc) * 4);
    }

    float acc[4][4][4];
#pragma unroll
    for (int mi = 0; mi < 4; mi++)
#pragma unroll
        for (int ni = 0; ni < 4; ni++)
#pragma unroll
            for (int q = 0; q < 4; q++) acc[mi][ni][q] = 0.f;

    int KT = K / BKK;

    // issue stage 0
    {
        uint32_t sb = sbase;
#pragma unroll
        for (int i = 0; i < 4; i++) cp16(sb + aDst[i], aSrc[i], aSz[i]);
#pragma unroll
        for (int i = 0; i < 4; i++) cp16(sb + bDst[i], bSrc[i], bSz[i]);
        asm volatile("cp.async.commit_group;");
    }

    for (int it = 0; it < KT; it++) {
        int s = it & 1;
        if (it + 1 < KT) {
            int k0 = (it + 1) * BKK;
            uint32_t sb = sbase + (uint32_t)(((it + 1) & 1) * STAGE_FLOATS * 4);
#pragma unroll
            for (int i = 0; i < 4; i++) cp16(sb + aDst[i], aSrc[i] + k0, aSz[i]);
#pragma unroll
            for (int i = 0; i < 4; i++) cp16(sb + bDst[i], bSrc[i] + (size_t)k0 * N, bSz[i]);
            asm volatile("cp.async.commit_group;");
            asm volatile("cp.async.wait_group 1;");
        } else {
            asm volatile("cp.async.wait_group 0;");
        }
        __syncthreads();

        const float* Ab = smem_dyn + (size_t)s * STAGE_FLOATS;
        const float* Bb = Ab + A_STAGE;
#pragma unroll
        for (int ks = 0; ks < 4; ks++) {
            int kb = ks * 8;
            uint32_t af[4][4];
#pragma unroll
            for (int mi = 0; mi < 4; mi++) {
                int r = wm + mi * 16 + grp;
                af[mi][0] = f2tf32(Ab[r * LDA_S + kb + tig]);
                af[mi][1] = f2tf32(Ab[(r + 8) * LDA_S + kb + tig]);
                af[mi][2] = f2tf32(Ab[r * LDA_S + kb + tig + 4]);
                af[mi][3] = f2tf32(Ab[(r + 8) * LDA_S + kb + tig + 4]);
            }
            uint32_t bf[4][2];
#pragma unroll
            for (int ni = 0; ni < 4; ni++) {
                int ccol = wn + ni * 8 + grp;
                bf[ni][0] = f2tf32(Bb[(kb + tig) * LDB_S + ccol]);
                bf[ni][1] = f2tf32(Bb[(kb + tig + 4) * LDB_S + ccol]);
            }
#pragma unroll
            for (int mi = 0; mi < 4; mi++)
#pragma unroll
                for (int ni = 0; ni < 4; ni++)
                    mma_tf32(acc[mi][ni], af[mi], bf[ni]);
        }
        __syncthreads();
    }

    // --- epilogue ---
    const float* bias = biasBase ? (biasBase + (long long)e * biasStride) : nullptr;
#pragma unroll
    for (int mi = 0; mi < 4; mi++) {
        int rbase = wm + mi * 16 + grp;
#pragma unroll
        for (int half = 0; half < 2; half++) {
            int r = rbase + half * 8;
            int lrow = rowTile * BKM + r;
            if (lrow >= nrows) continue;
            int grow = s0 + lrow;
#pragma unroll
            for (int ni = 0; ni < 4; ni++) {
                int col = colStart + wn + ni * 8 + tig * 2;
                float v0 = acc[mi][ni][half * 2 + 0];
                float v1 = acc[mi][ni][half * 2 + 1];
                if (bias) { v0 += bias[col]; v1 += bias[col + 1]; }
                if (doGelu) { v0 = gelu_tanh(v0); v1 = gelu_tanh(v1); }
                if (residual) {
                    v0 += residual[(size_t)grow * ldc + col];
                    v1 += residual[(size_t)grow * ldc + col + 1];
                }
                if (col < N)     C[(size_t)grow * ldc + col] = v0;
                if (col + 1 < N) C[(size_t)grow * ldc + col + 1] = v1;
            }
        }
    }
}

// ---------------- rmsnorm ----------------
__global__ __launch_bounds__(256) void rmsnorm_kernel(
    const float* __restrict__ x, const float* __restrict__ w, float* __restrict__ y)
{
    int t = blockIdx.x, tid = threadIdx.x;
    __shared__ float red[256];
    const float* xr = x + (size_t)t * DMODEL;
    float s = 0.f;
    for (int d = tid; d < DMODEL; d += 256) { float v = xr[d]; s += v * v; }
    red[tid] = s; __syncthreads();
    for (int o = 128; o > 0; o >>= 1) { if (tid < o) red[tid] += red[tid + o]; __syncthreads(); }
    float rms = rsqrtf(red[0] / (float)DMODEL + 1e-6f);
    float* yr = y + (size_t)t * DMODEL;
    for (int d = tid; d < DMODEL; d += 256) yr[d] = xr[d] * rms * w[d];
}

// ---------------- indexer scores ----------------
__global__ __launch_bounds__(256) void idx_kernel(
    const float* __restrict__ qi, const float* __restrict__ ki,
    const float* __restrict__ hw, float* __restrict__ out)
{
    __shared__ float qsh[64][65];
    __shared__ float ksh[64][65];
    __shared__ float hsh[64][4];
    int t0 = blockIdx.y * 64, s0 = blockIdx.x * 64;
    int tid = threadIdx.x;
    const int tr = (tid >> 4) * 4, tc = (tid & 15) * 4;

    hsh[tid >> 2][tid & 3] = hw[(size_t)(t0 + (tid >> 2)) * HIDX + (tid & 3)];
    for (int i = tid; i < 4096; i += 256) {
        int r = i >> 6, c = i & 63;
        ksh[r][c] = ki[(size_t)(s0 + r) * DIDX + c];
    }
    float acc[4][4];
#pragma unroll
    for (int i = 0; i < 4; i++)
#pragma unroll
        for (int j = 0; j < 4; j++) acc[i][j] = 0.f;

    for (int h = 0; h < HIDX; h++) {
        __syncthreads();
        for (int i = tid; i < 4096; i += 256) {
            int r = i >> 6, c = i & 63;
            qsh[r][c] = qi[(size_t)(t0 + r) * (HIDX * DIDX) + h * DIDX + c];
        }
        __syncthreads();
        float dot[4][4];
#pragma unroll
        for (int i = 0; i < 4; i++)
#pragma unroll
            for (int j = 0; j < 4; j++) dot[i][j] = 0.f;
        for (int kk = 0; kk < 64; kk++) {
            float a[4], b[4];
#pragma unroll
            for (int i = 0; i < 4; i++) a[i] = qsh[tr + i][kk];
#pragma unroll
            for (int j = 0; j < 4; j++) b[j] = ksh[tc + j][kk];
#pragma unroll
            for (int i = 0; i < 4; i++)
#pragma unroll
                for (int j = 0; j < 4; j++) dot[i][j] += a[i] * b[j];
        }
#pragma unroll
        for (int i = 0; i < 4; i++)
#pragma unroll
            for (int j = 0; j < 4; j++)
                acc[i][j] += hsh[tr + i][h] * fmaxf(dot[i][j], 0.f);
    }
#pragma unroll
    for (int i = 0; i < 4; i++)
#pragma unroll
        for (int j = 0; j < 4; j++)
            out[(size_t)(t0 + tr + i) * TSEQ + (s0 + tc + j)] = acc[i][j] * 0.125f;
}

// ---------------- top-512 per row via bitonic sort ----------------
__global__ __launch_bounds__(1024) void topk_kernel(
    const float* __restrict__ idxs, int* __restrict__ topIdx)
{
    __shared__ unsigned long long key[2048];
    int t = blockIdx.x, tid = threadIdx.x;
    for (int i = tid; i < 2048; i += 1024) {
        unsigned long long kk = 0ull;
        if (i <= t) {
            float v = idxs[(size_t)t * TSEQ + i];
            kk = ((unsigned long long)fmono(v) << 32) | (unsigned int)(2047 - i);
        }
        key[i] = kk;
    }
    __syncthreads();
    for (int k = 2; k <= 2048; k <<= 1) {
        for (int j = k >> 1; j > 0; j >>= 1) {
            for (int i = tid; i < 2048; i += 1024) {
                int ixj = i ^ j;
                if (ixj > i) {
                    unsigned long long a = key[i], b = key[ixj];
                    bool descSeg = ((i & k) == 0);
                    if (descSeg ? (a < b) : (a > b)) { key[i] = b; key[ixj] = a; }
                }
            }
            __syncthreads();
        }
    }
    if (tid < KSEL)
        topIdx[(size_t)t * KSEL + tid] = 2047 - (int)(key[tid] & 0xFFFFFFFFu);
}

// ---------------- RoPE + transpose to [h][t][d] ----------------
__global__ __launch_bounds__(256) void rope_kernel(
    const float* __restrict__ qb, const float* __restrict__ kb, const float* __restrict__ vb,
    float* __restrict__ qh, float* __restrict__ kh, float* __restrict__ vh)
{
    int idx = blockIdx.x * 256 + threadIdx.x;
    int t = idx >> 10;
    int hd = idx & 1023;
    int h = hd >> 6, d = hd & 63;
    int j = d & 31;
    double invd = exp(-((double)(2 * j) / 64.0) * log(10000.0));
    float ang = (float)((double)t * invd);
    float c = cosf(ang), s = sinf(ang);
    float q = qb[idx], k = kb[idx];
    float qr, kr;
    if (d < 32) {
        qr = q * c - qb[idx + 32] * s;
        kr = k * c - kb[idx + 32] * s;
    } else {
        qr = q * c + qb[idx - 32] * s;
        kr = k * c + kb[idx - 32] * s;
    }
    int o = ((h * TSEQ) + t) * HDIM + d;
    qh[o] = qr; kh[o] = kr; vh[o] = vb[idx];
}

// ---------------- sparse attention: one block per (t,h) ----------------
__global__ __launch_bounds__(256) void attn_kernel(
    const float* __restrict__ qh, const float* __restrict__ kh, const float* __restrict__ vh,
    const int* __restrict__ topIdx, float* __restrict__ av)
{
    int t = blockIdx.x, h = blockIdx.y;
    __shared__ float qs[64];
    __shared__ float sc[512];
    __shared__ int   ss[512];
    __shared__ float red[256];
    __shared__ float outp[4][64];
    int tid = threadIdx.x, lane = tid & 31, w = tid >> 5;

    if (tid < 64) qs[tid] = qh[((size_t)(h * TSEQ) + t) * HDIM + tid];
    for (int j = tid; j < 512; j += 256) {
        int s = topIdx[(size_t)t * KSEL + j];
        ss[j] = (s <= t) ? s : -1;
    }
    __syncthreads();

    const float* kbase = kh + (size_t)h * TSEQ * HDIM;
    for (int j = w; j < 512; j += 8) {
        int s = ss[j];
        float dres = -INFINITY;
        if (s >= 0) {
            const float* kr = kbase + (size_t)s * HDIM;
            float p = qs[lane] * kr[lane] + qs[lane + 32] * kr[lane + 32];
#pragma unroll
            for (int o = 16; o > 0; o >>= 1) p += __shfl_xor_sync(0xFFFFFFFFu, p, o);
            dres = p * 0.125f;
        }
        if (lane == 0) sc[j] = dres;
    }
    __syncthreads();

    float m = -INFINITY;
    for (int j = tid; j < 512; j += 256) m = fmaxf(m, sc[j]);
    red[tid] = m; __syncthreads();
    for (int o = 128; o > 0; o >>= 1) { if (tid < o) red[tid] = fmaxf(red[tid], red[tid + o]); __syncthreads(); }
    m = red[0]; __syncthreads();

    float sum = 0.f;
    for (int j = tid; j < 512; j += 256) {
        float e = expf(sc[j] - m);
        sc[j] = e;
        sum += e;
    }
    red[tid] = sum; __syncthreads();
    for (int o = 128; o > 0; o >>= 1) { if (tid < o) red[tid] += red[tid + o]; __syncthreads(); }
    float inv = 1.f / red[0];
    __syncthreads();

    int d0 = tid & 63, g = tid >> 6;
    float a = 0.f;
    const float* vbase = vh + (size_t)h * TSEQ * HDIM;
    for (int j = g; j < 512; j += 4) {
        int s = ss[j];
        if (s >= 0) a += sc[j] * vbase[(size_t)s * HDIM + d0];
    }
    outp[g][d0] = a;
    __syncthreads();
    if (tid < 64) {
        float r = (outp[0][tid] + outp[1][tid]) + (outp[2][tid] + outp[3][tid]);
        av[(size_t)t * DMODEL + h * HDIM + tid] = r * inv;
    }
}

// ---------------- router ----------------
__global__ __launch_bounds__(256) void router_kernel(
    const float* __restrict__ x2n, const float* __restrict__ rw, const float* __restrict__ rb,
    float* __restrict__ probs, int* __restrict__ topE, float* __restrict__ topG)
{
    int t = blockIdx.x, tid = threadIdx.x;
    __shared__ float red[256];
    __shared__ float lg[8];
    float acc[8];
#pragma unroll
    for (int e = 0; e < 8; e++) acc[e] = 0.f;
    const float* xr = x2n + (size_t)t * DMODEL;
    for (int d = tid; d < DMODEL; d += 256) {
        float xv = xr[d];
#pragma unroll
        for (int e = 0; e < 8; e++) acc[e] += xv * rw[(size_t)d * NEXP + e];
    }
    for (int e = 0; e < 8; e++) {
        red[tid] = acc[e]; __syncthreads();
        for (int o = 128; o > 0; o >>= 1) { if (tid < o) red[tid] += red[tid + o]; __syncthreads(); }
        if (tid == 0) lg[e] = red[0] + rb[e];
        __syncthreads();
    }
    if (tid == 0) {
        float m = lg[0];
        for (int e = 1; e < 8; e++) m = fmaxf(m, lg[e]);
        float p[8], s = 0.f;
        for (int e = 0; e < 8; e++) { p[e] = expf(lg[e] - m); s += p[e]; }
        for (int e = 0; e < 8; e++) p[e] /= s;
        int e0 = 0;
        for (int e = 1; e < 8; e++) if (p[e] > p[e0]) e0 = e;
        int e1 = -1;
        for (int e = 0; e < 8; e++) if (e != e0 && (e1 < 0 || p[e] > p[e1])) e1 = e;
        float denom = p[e0] + p[e1];
        for (int e = 0; e < 8; e++) probs[(size_t)t * NEXP + e] = p[e];
        topE[t * 2 + 0] = e0; topE[t * 2 + 1] = e1;
        topG[t * 2 + 0] = p[e0] / denom; topG[t * 2 + 1] = p[e1] / denom;
    }
}

// ---------------- deterministic grouping ----------------
__global__ void group_kernel(const int* __restrict__ topE, int* __restrict__ counts,
                             int* __restrict__ segoff, int* __restrict__ rowmap,
                             int* __restrict__ slotpos)
{
    int e = threadIdx.x;  // blockDim = 8
    int c = 0;
    for (int t = 0; t < TSEQ; t++)
        for (int s = 0; s < 2; s++)
            if (topE[t * 2 + s] == e) c++;
    counts[e] = c;
    __syncthreads();
    if (e == 0) {
        int o = 0;
        for (int i = 0; i < 8; i++) { segoff[i] = o; o += counts[i]; }
        segoff[8] = o;
    }
    __syncthreads();
    int pos = segoff[e];
    for (int t = 0; t < TSEQ; t++)
        for (int s = 0; s < 2; s++)
            if (topE[t * 2 + s] == e) {
                rowmap[pos] = t;
                slotpos[t * 2 + s] = pos;
                pos++;
            }
}

// ---------------- aux loss ----------------
__global__ __launch_bounds__(256) void aux_kernel(
    const float* __restrict__ probs, const int* __restrict__ counts, float* __restrict__ outAux)
{
    __shared__ float red[256];
    int tid = threadIdx.x;
    float a = 0.f;
    for (int e = 0; e < 8; e++) {
        float s = 0.f;
        for (int t = tid; t < TSEQ; t += 256) s += probs[(size_t)t * NEXP + e];
        red[tid] = s; __syncthreads();
        for (int o = 128; o > 0; o >>= 1) { if (tid < o) red[tid] += red[tid + o]; __syncthreads(); }
        if (tid == 0) a += (float)counts[e] * red[0];
        __syncthreads();
    }
    if (tid == 0) *outAux = 8.f * a / ((float)TSEQ * (float)TSEQ);
}

// ---------------- final combine ----------------
__global__ __launch_bounds__(256) void combine_kernel(
    const float* __restrict__ x1, const float* __restrict__ y,
    const int* __restrict__ slotpos, const float* __restrict__ topG,
    float* __restrict__ out)
{
    int idx = blockIdx.x * 256 + threadIdx.x;
    int t = idx >> 10, d = idx & 1023;
    int p0 = slotpos[t * 2 + 0], p1 = slotpos[t * 2 + 1];
    float g0 = topG[t * 2 + 0], g1 = topG[t * 2 + 1];
    out[idx] = x1[idx] + g0 * y[(size_t)p0 * DMODEL + d] + g1 * y[(size_t)p1 * DMODEL + d];
}

// ---------------- host launch ----------------
#define GETSYM(ptr, sym) do { void* _p_; cudaGetSymbolAddress(&_p_, sym); ptr = (decltype(ptr))_p_; } while (0)

extern "C" void kernel_launch(void* const* d_in, const int* in_sizes, int n_in,
                              void* d_out, int out_size)
{
    const float* x        = (const float*)d_in[0];
    const float* norm1_w  = (const float*)d_in[1];
    const float* norm2_w  = (const float*)d_in[2];
    const float* wq_idx   = (const float*)d_in[3];
    const float* wk_idx   = (const float*)d_in[4];
    const float* w_head   = (const float*)d_in[5];
    const float* wq       = (const float*)d_in[6];
    const float* wk       = (const float*)d_in[7];
    const float* wv       = (const float*)d_in[8];
    const float* wo       = (const float*)d_in[9];
    const float* router_w = (const float*)d_in[10];
    const float* router_b = (const float*)d_in[11];
    const float* w1       = (const float*)d_in[12];
    const float* b1       = (const float*)d_in[13];
    const float* w2       = (const float*)d_in[14];
    const float* b2       = (const float*)d_in[15];

    float* out    = (float*)d_out;
    float* auxp   = out + (size_t)TSEQ * DMODEL;
    float* idxout = auxp + 1;

    float *p_xn, *p_qi, *p_ki, *p_hw, *p_qb, *p_kb, *p_vb, *p_qh, *p_kh, *p_vh;
    float *p_av, *p_x1, *p_x2n, *p_probs, *p_topG, *p_mid, *p_y;
    int *p_top, *p_topE, *p_counts, *p_segoff, *p_rowmap, *p_slotpos;
    GETSYM(p_xn, g_xn); GETSYM(p_qi, g_qi); GETSYM(p_ki, g_ki); GETSYM(p_hw, g_hw);
    GETSYM(p_qb, g_qb); GETSYM(p_kb, g_kb); GETSYM(p_vb, g_vb);
    GETSYM(p_qh, g_qh); GETSYM(p_kh, g_kh); GETSYM(p_vh, g_vh);
    GETSYM(p_top, g_top); GETSYM(p_av, g_av); GETSYM(p_x1, g_x1); GETSYM(p_x2n, g_x2n);
    GETSYM(p_probs, g_probs); GETSYM(p_topE, g_topE); GETSYM(p_topG, g_topG);
    GETSYM(p_counts, g_counts); GETSYM(p_segoff, g_segoff);
    GETSYM(p_rowmap, g_rowmap); GETSYM(p_slotpos, g_slotpos);
    GETSYM(p_mid, g_mid); GETSYM(p_y, g_yy);

    cudaFuncSetAttribute(tgemm, cudaFuncAttributeMaxDynamicSharedMemorySize, TG_SMEM_BYTES);

    // 1. norm1
    rmsnorm_kernel<<<TSEQ, 256>>>(x, norm1_w, p_xn);

    // 2. projections (all tf32 tensor GEMM)
    tgemm<<<dim3(2, 16, 1), 256, TG_SMEM_BYTES>>>(p_xn, DMODEL, nullptr, wq_idx, 0, nullptr, 0,
        nullptr, p_qi, HIDX * DIDX, nullptr, TSEQ, HIDX * DIDX, DMODEL, 0);
    tgemm<<<dim3(1, 16, 1), 256, TG_SMEM_BYTES>>>(p_xn, DMODEL, nullptr, wk_idx, 0, nullptr, 0,
        nullptr, p_ki, DIDX, nullptr, TSEQ, DIDX, DMODEL, 0);
    tgemm<<<dim3(1, 16, 1), 256, TG_SMEM_BYTES>>>(p_xn, DMODEL, nullptr, w_head, 0, nullptr, 0,
        nullptr, p_hw, HIDX, nullptr, TSEQ, HIDX, DMODEL, 0);
    tgemm<<<dim3(8, 16, 1), 256, TG_SMEM_BYTES>>>(p_xn, DMODEL, nullptr, wq, 0, nullptr, 0,
        nullptr, p_qb, DMODEL, nullptr, TSEQ, DMODEL, DMODEL, 0);
    tgemm<<<dim3(8, 16, 1), 256, TG_SMEM_BYTES>>>(p_xn, DMODEL, nullptr, wk, 0, nullptr, 0,
        nullptr, p_kb, DMODEL, nullptr, TSEQ, DMODEL, DMODEL, 0);
    tgemm<<<dim3(8, 16, 1), 256, TG_SMEM_BYTES>>>(p_xn, DMODEL, nullptr, wv, 0, nullptr, 0,
        nullptr, p_vb, DMODEL, nullptr, TSEQ, DMODEL, DMODEL, 0);

    // 3. indexer scores + top-512
    idx_kernel<<<dim3(32, 32), 256>>>(p_qi, p_ki, p_hw, idxout);
    topk_kernel<<<TSEQ, 1024>>>(idxout, p_top);

    // 4. rope + transpose
    rope_kernel<<<(TSEQ * DMODEL) / 256, 256>>>(p_qb, p_kb, p_vb, p_qh, p_kh, p_vh);

    // 5. sparse attention
    attn_kernel<<<dim3(TSEQ, NHEAD), 256>>>(p_qh, p_kh, p_vh, p_top, p_av);

    // 6. output projection + residual
    tgemm<<<dim3(8, 16, 1), 256, TG_SMEM_BYTES>>>(p_av, DMODEL, nullptr, wo, 0, nullptr, 0,
        x, p_x1, DMODEL, nullptr, TSEQ, DMODEL, DMODEL, 0);

    // 7. norm2 + router + grouping + aux
    rmsnorm_kernel<<<TSEQ, 256>>>(p_x1, norm2_w, p_x2n);
    router_kernel<<<TSEQ, 256>>>(p_x2n, router_w, router_b, p_probs, p_topE, p_topG);
    group_kernel<<<1, 8>>>(p_topE, p_counts, p_segoff, p_rowmap, p_slotpos);
    aux_kernel<<<1, 256>>>(p_probs, p_counts, auxp);

    // 8. MoE grouped GEMMs
    tgemm<<<dim3(DFFN / 128, 16, NEXP), 256, TG_SMEM_BYTES>>>(
        p_x2n, DMODEL, p_rowmap, w1, (long long)DMODEL * DFFN, b1, DFFN,
        nullptr, p_mid, DFFN, p_segoff, 0, DFFN, DMODEL, 1);
    tgemm<<<dim3(DMODEL / 128, 16, NEXP), 256, TG_SMEM_BYTES>>>(
        p_mid, DFFN, nullptr, w2, (long long)DFFN * DMODEL, b2, DMODEL,
        nullptr, p_y, DMODEL, p_segoff, 0, DMODEL, DFFN, 0);

    // 9. combine
    combine_kernel<<<(TSEQ * DMODEL) / 256, 256>>>(p_x1, p_y, p_slotpos, p_topG, out);
}

// round 3
// speedup vs baseline: 2.6715x; 1.4287x over previous
#include <cuda_runtime.h>
#include <math.h>
#include <stdint.h>

// ---------------- constants ----------------
static const int TSEQ = 2048;
static const int DMODEL = 1024;
static const int NHEAD = 16;
static const int HDIM = 64;
static const int DFFN = 4096;
static const int NEXP = 8;
static const int HIDX = 4;
static const int DIDX = 64;
static const int KSEL = 512;

// ---------------- device scratch ----------------
__device__ float g_xn[TSEQ * DMODEL];
__device__ float g_qi[TSEQ * HIDX * DIDX];
__device__ float g_ki[TSEQ * DIDX];
__device__ float g_hw[TSEQ * HIDX];
__device__ float g_qb[TSEQ * DMODEL];
__device__ float g_kb[TSEQ * DMODEL];
__device__ float g_vb[TSEQ * DMODEL];
__device__ float g_qh[TSEQ * DMODEL];
__device__ float g_kh[TSEQ * DMODEL];
__device__ float g_vh[TSEQ * DMODEL];
__device__ int   g_top[TSEQ * KSEL];
__device__ float g_av[TSEQ * DMODEL];
__device__ float g_x1[TSEQ * DMODEL];
__device__ float g_x2n[TSEQ * DMODEL];
__device__ float g_probs[TSEQ * NEXP];
__device__ int   g_topE[TSEQ * 2];
__device__ float g_topG[TSEQ * 2];
__device__ int   g_counts[NEXP];
__device__ int   g_segoff[NEXP + 1];
__device__ int   g_rowmap[TSEQ * 2];
__device__ int   g_slotpos[TSEQ * 2];
__device__ float g_mid[(size_t)(TSEQ * 2) * DFFN];
__device__ float g_yy[(size_t)(TSEQ * 2) * DMODEL];
__device__ unsigned int g_mask[TSEQ * (TSEQ / 32)];   // [t][64 words]

// ---------------- helpers ----------------
__device__ __forceinline__ float gelu_tanh(float x) {
    float x3 = x * x * x;
    float u = 0.7978845608028654f * (x + 0.044715f * x3);
    return 0.5f * x * (1.0f + tanhf(u));
}

__device__ __forceinline__ unsigned int fmono(float f) {
    unsigned int u = __float_as_uint(f);
    return (u & 0x80000000u) ? ~u : (u | 0x80000000u);
}

__device__ __forceinline__ uint32_t f2tf32(float f) {
    uint32_t r;
    asm("cvt.rna.tf32.f32 %0, %1;" : "=r"(r) : "f"(f));
    return r;
}

__device__ __forceinline__ void cp16(uint32_t dst, const float* src, int sz) {
    asm volatile("cp.async.cg.shared.global [%0], [%1], 16, %2;" :: "r"(dst), "l"(src), "r"(sz));
}

__device__ __forceinline__ void mma_tf32(float* c, const uint32_t* a, const uint32_t* b) {
    asm volatile(
        "mma.sync.aligned.m16n8k8.row.col.f32.tf32.tf32.f32 "
        "{%0,%1,%2,%3}, {%4,%5,%6,%7}, {%8,%9}, {%0,%1,%2,%3};"
        : "+f"(c[0]), "+f"(c[1]), "+f"(c[2]), "+f"(c[3])
        : "r"(a[0]), "r"(a[1]), "r"(a[2]), "r"(a[3]), "r"(b[0]), "r"(b[1]));
}

// ---------------- unified tf32 tensor GEMM (3-stage cp.async) ----------------
#define BKM 128
#define BKN 128
#define BKK 32
#define LDA_S 36
#define LDB_S 132
#define A_STAGE (BKM * LDA_S)
#define B_STAGE (BKK * LDB_S)
#define STAGE_FLOATS (A_STAGE + B_STAGE)
#define NSTAGE 3
#define TG_SMEM_BYTES (NSTAGE * STAGE_FLOATS * 4)

extern __shared__ float smem_dyn[];

__global__ void __launch_bounds__(256, 1) tgemm(
    const float* __restrict__ A, int lda,
    const int* __restrict__ rowmap,
    const float* __restrict__ Bbase, long long strideB,
    const float* __restrict__ biasBase, int biasStride,
    const float* __restrict__ residual,
    float* __restrict__ C, int ldc,
    const int* __restrict__ segoff,
    int M, int N, int K, int doGelu)
{
    int e = blockIdx.z;
    int s0 = 0, nrows = M;
    if (segoff) { s0 = segoff[e]; nrows = segoff[e + 1] - s0; }
    int rowTile = blockIdx.y;
    if (rowTile * BKM >= nrows) return;
    int colStart = blockIdx.x * BKN;
    const float* B = Bbase + (long long)e * strideB;

    int tid = threadIdx.x;
    int warpId = tid >> 5, lane = tid & 31;
    int grp = lane >> 2, tig = lane & 3;
    int wm = (warpId >> 2) * 64;
    int wn = (warpId & 3) * 32;

    uint32_t sbase = (uint32_t)__cvta_generic_to_shared(smem_dyn);

    const float* aSrc[4]; int aSz[4]; uint32_t aDst[4];
    const float* bSrc[4]; int bSz[4]; uint32_t bDst[4];
#pragma unroll
    for (int i = 0; i < 4; i++) {
        int c = tid + i * 256;
        int arow = c >> 3, akc = (c & 7) * 4;
        int lrow = rowTile * BKM + arow;
        bool v = lrow < nrows;
        int gidx = 0;
        if (v) {
            int base = s0 + lrow;
            gidx = rowmap ? rowmap[base] : base;
        }
        aSrc[i] = A + (size_t)gidx * lda + akc;
        aSz[i] = v ? 16 : 0;
        aDst[i] = (uint32_t)((arow * LDA_S + akc) * 4);

        int brow = c >> 5, bnc = (c & 31) * 4;
        int col = colStart + bnc;
        bool bv = (col + 4 <= N);
        bSz[i] = bv ? 16 : 0;
        bSrc[i] = B + (size_t)brow * N + (bv ? col : 0);
        bDst[i] = (uint32_t)((A_STAGE + brow * LDB_S + bnc) * 4);
    }

    float acc[4][4][4];
#pragma unroll
    for (int mi = 0; mi < 4; mi++)
#pragma unroll
        for (int ni = 0; ni < 4; ni++)
#pragma unroll
            for (int q = 0; q < 4; q++) acc[mi][ni][q] = 0.f;

    int KT = K / BKK;

    // prologue: issue up to NSTAGE-1 stages
#pragma unroll
    for (int p = 0; p < NSTAGE - 1; p++) {
        if (p < KT) {
            int k0 = p * BKK;
            uint32_t sb = sbase + (uint32_t)((p % NSTAGE) * STAGE_FLOATS * 4);
#pragma unroll
            for (int i = 0; i < 4; i++) cp16(sb + aDst[i], aSrc[i] + k0, aSz[i]);
#pragma unroll
            for (int i = 0; i < 4; i++) cp16(sb + bDst[i], bSrc[i] + (size_t)k0 * N, bSz[i]);
            asm volatile("cp.async.commit_group;");
        }
    }

    for (int it = 0; it < KT; it++) {
        if (it + NSTAGE - 1 < KT) {
            int k0 = (it + NSTAGE - 1) * BKK;
            uint32_t sb = sbase + (uint32_t)(((it + NSTAGE - 1) % NSTAGE) * STAGE_FLOATS * 4);
#pragma unroll
            for (int i = 0; i < 4; i++) cp16(sb + aDst[i], aSrc[i] + k0, aSz[i]);
#pragma unroll
            for (int i = 0; i < 4; i++) cp16(sb + bDst[i], bSrc[i] + (size_t)k0 * N, bSz[i]);
            asm volatile("cp.async.commit_group;");
        }
        int pend = KT - 1 - it;
        if (pend > NSTAGE - 1) pend = NSTAGE - 1;
        if (pend >= 2)      asm volatile("cp.async.wait_group 2;");
        else if (pend == 1) asm volatile("cp.async.wait_group 1;");
        else                asm volatile("cp.async.wait_group 0;");
        __syncthreads();

        const float* Ab = smem_dyn + (size_t)(it % NSTAGE) * STAGE_FLOATS;
        const float* Bb = Ab + A_STAGE;
#pragma unroll
        for (int ks = 0; ks < 4; ks++) {
            int kb = ks * 8;
            uint32_t af[4][4];
#pragma unroll
            for (int mi = 0; mi < 4; mi++) {
                int r = wm + mi * 16 + grp;
                af[mi][0] = f2tf32(Ab[r * LDA_S + kb + tig]);
                af[mi][1] = f2tf32(Ab[(r + 8) * LDA_S + kb + tig]);
                af[mi][2] = f2tf32(Ab[r * LDA_S + kb + tig + 4]);
                af[mi][3] = f2tf32(Ab[(r + 8) * LDA_S + kb + tig + 4]);
            }
            uint32_t bf[4][2];
#pragma unroll
            for (int ni = 0; ni < 4; ni++) {
                int ccol = wn + ni * 8 + grp;
                bf[ni][0] = f2tf32(Bb[(kb + tig) * LDB_S + ccol]);
                bf[ni][1] = f2tf32(Bb[(kb + tig + 4) * LDB_S + ccol]);
            }
#pragma unroll
            for (int mi = 0; mi < 4; mi++)
#pragma unroll
                for (int ni = 0; ni < 4; ni++)
                    mma_tf32(acc[mi][ni], af[mi], bf[ni]);
        }
        __syncthreads();
    }

    const float* bias = biasBase ? (biasBase + (long long)e * biasStride) : nullptr;
#pragma unroll
    for (int mi = 0; mi < 4; mi++) {
        int rbase = wm + mi * 16 + grp;
#pragma unroll
        for (int half = 0; half < 2; half++) {
            int r = rbase + half * 8;
            int lrow = rowTile * BKM + r;
            if (lrow >= nrows) continue;
            int grow = s0 + lrow;
#pragma unroll
            for (int ni = 0; ni < 4; ni++) {
                int col = colStart + wn + ni * 8 + tig * 2;
                float v0 = acc[mi][ni][half * 2 + 0];
                float v1 = acc[mi][ni][half * 2 + 1];
                if (bias) { v0 += bias[col]; v1 += bias[col + 1]; }
                if (doGelu) { v0 = gelu_tanh(v0); v1 = gelu_tanh(v1); }
                if (residual) {
                    v0 += residual[(size_t)grow * ldc + col];
                    v1 += residual[(size_t)grow * ldc + col + 1];
                }
                if (col < N)     C[(size_t)grow * ldc + col] = v0;
                if (col + 1 < N) C[(size_t)grow * ldc + col + 1] = v1;
            }
        }
    }
}

// ---------------- rmsnorm ----------------
__global__ __launch_bounds__(256) void rmsnorm_kernel(
    const float* __restrict__ x, const float* __restrict__ w, float* __restrict__ y)
{
    int t = blockIdx.x, tid = threadIdx.x;
    __shared__ float red[256];
    const float* xr = x + (size_t)t * DMODEL;
    float s = 0.f;
    for (int d = tid; d < DMODEL; d += 256) { float v = xr[d]; s += v * v; }
    red[tid] = s; __syncthreads();
    for (int o = 128; o > 0; o >>= 1) { if (tid < o) red[tid] += red[tid + o]; __syncthreads(); }
    float rms = rsqrtf(red[0] / (float)DMODEL + 1e-6f);
    float* yr = y + (size_t)t * DMODEL;
    for (int d = tid; d < DMODEL; d += 256) yr[d] = xr[d] * rms * w[d];
}

// ---------------- indexer scores ----------------
__global__ __launch_bounds__(256) void idx_kernel(
    const float* __restrict__ qi, const float* __restrict__ ki,
    const float* __restrict__ hw, float* __restrict__ out)
{
    __shared__ float qsh[64][65];
    __shared__ float ksh[64][65];
    __shared__ float hsh[64][4];
    int t0 = blockIdx.y * 64, s0 = blockIdx.x * 64;
    int tid = threadIdx.x;
    const int tr = (tid >> 4) * 4, tc = (tid & 15) * 4;

    hsh[tid >> 2][tid & 3] = hw[(size_t)(t0 + (tid >> 2)) * HIDX + (tid & 3)];
    for (int i = tid; i < 4096; i += 256) {
        int r = i >> 6, c = i & 63;
        ksh[r][c] = ki[(size_t)(s0 + r) * DIDX + c];
    }
    float acc[4][4];
#pragma unroll
    for (int i = 0; i < 4; i++)
#pragma unroll
        for (int j = 0; j < 4; j++) acc[i][j] = 0.f;

    for (int h = 0; h < HIDX; h++) {
        __syncthreads();
        for (int i = tid; i < 4096; i += 256) {
            int r = i >> 6, c = i & 63;
            qsh[r][c] = qi[(size_t)(t0 + r) * (HIDX * DIDX) + h * DIDX + c];
        }
        __syncthreads();
        float dot[4][4];
#pragma unroll
        for (int i = 0; i < 4; i++)
#pragma unroll
            for (int j = 0; j < 4; j++) dot[i][j] = 0.f;
        for (int kk = 0; kk < 64; kk++) {
            float a[4], b[4];
#pragma unroll
            for (int i = 0; i < 4; i++) a[i] = qsh[tr + i][kk];
#pragma unroll
            for (int j = 0; j < 4; j++) b[j] = ksh[tc + j][kk];
#pragma unroll
            for (int i = 0; i < 4; i++)
#pragma unroll
                for (int j = 0; j < 4; j++) dot[i][j] += a[i] * b[j];
        }
#pragma unroll
        for (int i = 0; i < 4; i++)
#pragma unroll
            for (int j = 0; j < 4; j++)
                acc[i][j] += hsh[tr + i][h] * fmaxf(dot[i][j], 0.f);
    }
#pragma unroll
    for (int i = 0; i < 4; i++)
#pragma unroll
        for (int j = 0; j < 4; j++)
            out[(size_t)(t0 + tr + i) * TSEQ + (s0 + tc + j)] = acc[i][j] * 0.125f;
}

// ---------------- top-512 per row via bitonic sort ----------------
__global__ __launch_bounds__(1024) void topk_kernel(
    const float* __restrict__ idxs, int* __restrict__ topIdx)
{
    __shared__ unsigned long long key[2048];
    int t = blockIdx.x, tid = threadIdx.x;
    for (int i = tid; i < 2048; i += 1024) {
        unsigned long long kk = 0ull;
        if (i <= t) {
            float v = idxs[(size_t)t * TSEQ + i];
            kk = ((unsigned long long)fmono(v) << 32) | (unsigned int)(2047 - i);
        }
        key[i] = kk;
    }
    __syncthreads();
    for (int k = 2; k <= 2048; k <<= 1) {
        for (int j = k >> 1; j > 0; j >>= 1) {
            for (int i = tid; i < 2048; i += 1024) {
                int ixj = i ^ j;
                if (ixj > i) {
                    unsigned long long a = key[i], b = key[ixj];
                    bool descSeg = ((i & k) == 0);
                    if (descSeg ? (a < b) : (a > b)) { key[i] = b; key[ixj] = a; }
                }
            }
            __syncthreads();
        }
    }
    if (tid < KSEL)
        topIdx[(size_t)t * KSEL + tid] = 2047 - (int)(key[tid] & 0xFFFFFFFFu);
}

// ---------------- mask build ----------------
__global__ __launch_bounds__(256) void mask_zero_kernel(unsigned int* __restrict__ mask)
{
    int i = blockIdx.x * 256 + threadIdx.x;
    mask[i] = 0u;
}

__global__ __launch_bounds__(512) void mask_scatter_kernel(
    const int* __restrict__ topIdx, unsigned int* __restrict__ mask)
{
    int t = blockIdx.x, j = threadIdx.x;
    int s = topIdx[(size_t)t * KSEL + j];
    if (s <= t) atomicOr(&mask[t * 64 + (s >> 5)], 1u << (s & 31));
}

// ---------------- RoPE + transpose to [h][t][d] ----------------
__global__ __launch_bounds__(256) void rope_kernel(
    const float* __restrict__ qb, const float* __restrict__ kb, const float* __restrict__ vb,
    float* __restrict__ qh, float* __restrict__ kh, float* __restrict__ vh)
{
    int idx = blockIdx.x * 256 + threadIdx.x;
    int t = idx >> 10;
    int hd = idx & 1023;
    int h = hd >> 6, d = hd & 63;
    int j = d & 31;
    double invd = exp(-((double)(2 * j) / 64.0) * log(10000.0));
    float ang = (float)((double)t * invd);
    float c = cosf(ang), s = sinf(ang);
    float q = qb[idx], k = kb[idx];
    float qr, kr;
    if (d < 32) {
        qr = q * c - qb[idx + 32] * s;
        kr = k * c - kb[idx + 32] * s;
    } else {
        qr = q * c + qb[idx - 32] * s;
        kr = k * c + kb[idx - 32] * s;
    }
    int o = ((h * TSEQ) + t) * HDIM + d;
    qh[o] = qr; kh[o] = kr; vh[o] = vb[idx];
}

// ---------------- dense masked flash attention (tf32 mma) ----------------
// grid (TSEQ/64, NHEAD), 256 threads (8 warps: 4 m-groups x 2 n-groups)
__global__ void __launch_bounds__(256, 2) attn_flash(
    const float* __restrict__ qh, const float* __restrict__ kh, const float* __restrict__ vh,
    const unsigned int* __restrict__ mask, float* __restrict__ av)
{
    __shared__ float Ks[64][68];
    __shared__ float Vs[64][68];
    __shared__ float Ps[64][68];
    __shared__ float rowM[64], rowL[64], rowScale[64];

    int qt = blockIdx.x, h = blockIdx.y;
    int t0 = qt * 64;
    int tid = threadIdx.x;
    int warpId = tid >> 5, lane = tid & 31;
    int grp = lane >> 2, tig = lane & 3;
    int wm = (warpId >> 1) * 16;
    int wn = (warpId & 1) * 32;

    // load Q frags (kept in regs for whole block)
    const float* Q0 = qh + ((size_t)h * TSEQ + t0) * HDIM;
    uint32_t qf[8][4];
#pragma unroll
    for (int ks = 0; ks < 8; ks++) {
        int kb = ks * 8;
        qf[ks][0] = f2tf32(Q0[(wm + grp) * HDIM + kb + tig]);
        qf[ks][1] = f2tf32(Q0[(wm + grp + 8) * HDIM + kb + tig]);
        qf[ks][2] = f2tf32(Q0[(wm + grp) * HDIM + kb + tig + 4]);
        qf[ks][3] = f2tf32(Q0[(wm + grp + 8) * HDIM + kb + tig + 4]);
    }

    if (tid < 64) { rowM[tid] = -INFINITY; rowL[tid] = 0.f; }

    float oacc[4][4];
#pragma unroll
    for (int ni = 0; ni < 4; ni++)
#pragma unroll
        for (int q = 0; q < 4; q++) oacc[ni][q] = 0.f;

    const float* Kb = kh + (size_t)h * TSEQ * HDIM;
    const float* Vb = vh + (size_t)h * TSEQ * HDIM;

    for (int kt = 0; kt <= qt; kt++) {
        __syncthreads();
        // load K,V tiles (64x64)
        for (int i = tid; i < 1024; i += 256) {
            int row = i >> 4, c4 = (i & 15) * 4;
            *(float4*)&Ks[row][c4] = *(const float4*)(Kb + (size_t)(kt * 64 + row) * HDIM + c4);
            *(float4*)&Vs[row][c4] = *(const float4*)(Vb + (size_t)(kt * 64 + row) * HDIM + c4);
        }
        __syncthreads();

        // S = Q @ K^T
        float sacc[4][4];
#pragma unroll
        for (int ni = 0; ni < 4; ni++)
#pragma unroll
            for (int q = 0; q < 4; q++) sacc[ni][q] = 0.f;
#pragma unroll
        for (int ks = 0; ks < 8; ks++) {
            int kb = ks * 8;
#pragma unroll
            for (int ni = 0; ni < 4; ni++) {
                int n = wn + ni * 8 + grp;
                uint32_t bf[2];
                bf[0] = f2tf32(Ks[n][kb + tig]);
                bf[1] = f2tf32(Ks[n][kb + tig + 4]);
                mma_tf32(sacc[ni], qf[ks], bf);
            }
        }

        // masked, scaled scores -> Ps
        int r0 = wm + grp, r1 = wm + grp + 8;
        unsigned int mw0 = mask[(t0 + r0) * 64 + kt * 2 + (wn >> 5)];
        unsigned int mw1 = mask[(t0 + r1) * 64 + kt * 2 + (wn >> 5)];
#pragma unroll
        for (int ni = 0; ni < 4; ni++) {
            int c = wn + ni * 8 + tig * 2;
            int b = ni * 8 + tig * 2;
            Ps[r0][c]     = ((mw0 >> b) & 1u)       ? sacc[ni][0] * 0.125f : -INFINITY;
            Ps[r0][c + 1] = ((mw0 >> (b + 1)) & 1u) ? sacc[ni][1] * 0.125f : -INFINITY;
            Ps[r1][c]     = ((mw1 >> b) & 1u)       ? sacc[ni][2] * 0.125f : -INFINITY;
            Ps[r1][c + 1] = ((mw1 >> (b + 1)) & 1u) ? sacc[ni][3] * 0.125f : -INFINITY;
        }
        __syncthreads();

        // online softmax: 4 threads per row
        {
            int row = tid >> 2, seg = tid & 3;
            float m_old = rowM[row];
            float tmax = -INFINITY;
#pragma unroll
            for (int j = 0; j < 16; j++) tmax = fmaxf(tmax, Ps[row][seg * 16 + j]);
            tmax = fmaxf(tmax, __shfl_xor_sync(0xFFFFFFFFu, tmax, 1));
            tmax = fmaxf(tmax, __shfl_xor_sync(0xFFFFFFFFu, tmax, 2));
            float mnew = fmaxf(m_old, tmax);
            bool inval = (mnew == -INFINITY);
            float tsum = 0.f;
#pragma unroll
            for (int j = 0; j < 16; j++) {
                float v = Ps[row][seg * 16 + j];
                float p = inval ? 0.f : expf(v - mnew);
                Ps[row][seg * 16 + j] = p;
                tsum += p;
            }
            tsum += __shfl_xor_sync(0xFFFFFFFFu, tsum, 1);
            tsum += __shfl_xor_sync(0xFFFFFFFFu, tsum, 2);
            if (seg == 0) {
                float sc = inval ? 1.f : expf(m_old - mnew);
                rowScale[row] = sc;
                rowM[row] = mnew;
                rowL[row] = rowL[row] * sc + tsum;
            }
        }
        __syncthreads();

        // rescale O, accumulate P @ V
        float s0 = rowScale[wm + grp], s1 = rowScale[wm + grp + 8];
#pragma unroll
        for (int ni = 0; ni < 4; ni++) {
            oacc[ni][0] *= s0; oacc[ni][1] *= s0;
            oacc[ni][2] *= s1; oacc[ni][3] *= s1;
        }
#pragma unroll
        for (int ks = 0; ks < 8; ks++) {
            int kb = ks * 8;
            uint32_t pa[4];
            pa[0] = f2tf32(Ps[wm + grp][kb + tig]);
            pa[1] = f2tf32(Ps[wm + grp + 8][kb + tig]);
            pa[2] = f2tf32(Ps[wm + grp][kb + tig + 4]);
            pa[3] = f2tf32(Ps[wm + grp + 8][kb + tig + 4]);
#pragma unroll
            for (int ni = 0; ni < 4; ni++) {
                int n = wn + ni * 8 + grp;
                uint32_t vf[2];
                vf[0] = f2tf32(Vs[kb + tig][n]);
                vf[1] = f2tf32(Vs[kb + tig + 4][n]);
                mma_tf32(oacc[ni], pa, vf);
            }
        }
    }
    __syncthreads();

    float i0 = 1.f / rowL[wm + grp];
    float i1 = 1.f / rowL[wm + grp + 8];
#pragma unroll
    for (int ni = 0; ni < 4; ni++) {
        int c = wn + ni * 8 + tig * 2;
        size_t o0 = (size_t)(t0 + wm + grp) * DMODEL + h * HDIM + c;
        size_t o1 = (size_t)(t0 + wm + grp + 8) * DMODEL + h * HDIM + c;
        av[o0]     = oacc[ni][0] * i0;
        av[o0 + 1] = oacc[ni][1] * i0;
        av[o1]     = oacc[ni][2] * i1;
        av[o1 + 1] = oacc[ni][3] * i1;
    }
}

// ---------------- router ----------------
__global__ __launch_bounds__(256) void router_kernel(
    const float* __restrict__ x2n, const float* __restrict__ rw, const float* __restrict__ rb,
    float* __restrict__ probs, int* __restrict__ topE, float* __restrict__ topG)
{
    int t = blockIdx.x, tid = threadIdx.x;
    __shared__ float red[256];
    __shared__ float lg[8];
    float acc[8];
#pragma unroll
    for (int e = 0; e < 8; e++) acc[e] = 0.f;
    const float* xr = x2n + (size_t)t * DMODEL;
    for (int d = tid; d < DMODEL; d += 256) {
        float xv = xr[d];
#pragma unroll
        for (int e = 0; e < 8; e++) acc[e] += xv * rw[(size_t)d * NEXP + e];
    }
    for (int e = 0; e < 8; e++) {
        red[tid] = acc[e]; __syncthreads();
        for (int o = 128; o > 0; o >>= 1) { if (tid < o) red[tid] += red[tid + o]; __syncthreads(); }
        if (tid == 0) lg[e] = red[0] + rb[e];
        __syncthreads();
    }
    if (tid == 0) {
        float m = lg[0];
        for (int e = 1; e < 8; e++) m = fmaxf(m, lg[e]);
        float p[8], s = 0.f;
        for (int e = 0; e < 8; e++) { p[e] = expf(lg[e] - m); s += p[e]; }
        for (int e = 0; e < 8; e++) p[e] /= s;
        int e0 = 0;
        for (int e = 1; e < 8; e++) if (p[e] > p[e0]) e0 = e;
        int e1 = -1;
        for (int e = 0; e < 8; e++) if (e != e0 && (e1 < 0 || p[e] > p[e1])) e1 = e;
        float denom = p[e0] + p[e1];
        for (int e = 0; e < 8; e++) probs[(size_t)t * NEXP + e] = p[e];
        topE[t * 2 + 0] = e0; topE[t * 2 + 1] = e1;
        topG[t * 2 + 0] = p[e0] / denom; topG[t * 2 + 1] = p[e1] / denom;
    }
}

// ---------------- deterministic grouping ----------------
__global__ void group_kernel(const int* __restrict__ topE, int* __restrict__ counts,
                             int* __restrict__ segoff, int* __restrict__ rowmap,
                             int* __restrict__ slotpos)
{
    int e = threadIdx.x;  // blockDim = 8
    int c = 0;
    for (int t = 0; t < TSEQ; t++)
        for (int s = 0; s < 2; s++)
            if (topE[t * 2 + s] == e) c++;
    counts[e] = c;
    __syncthreads();
    if (e == 0) {
        int o = 0;
        for (int i = 0; i < 8; i++) { segoff[i] = o; o += counts[i]; }
        segoff[8] = o;
    }
    __syncthreads();
    int pos = segoff[e];
    for (int t = 0; t < TSEQ; t++)
        for (int s = 0; s < 2; s++)
            if (topE[t * 2 + s] == e) {
                rowmap[pos] = t;
                slotpos[t * 2 + s] = pos;
                pos++;
            }
}

// ---------------- aux loss ----------------
__global__ __launch_bounds__(256) void aux_kernel(
    const float* __restrict__ probs, const int* __restrict__ counts, float* __restrict__ outAux)
{
    __shared__ float red[256];
    int tid = threadIdx.x;
    float a = 0.f;
    for (int e = 0; e < 8; e++) {
        float s = 0.f;
        for (int t = tid; t < TSEQ; t += 256) s += probs[(size_t)t * NEXP + e];
        red[tid] = s; __syncthreads();
        for (int o = 128; o > 0; o >>= 1) { if (tid < o) red[tid] += red[tid + o]; __syncthreads(); }
        if (tid == 0) a += (float)counts[e] * red[0];
        __syncthreads();
    }
    if (tid == 0) *outAux = 8.f * a / ((float)TSEQ * (float)TSEQ);
}

// ---------------- final combine ----------------
__global__ __launch_bounds__(256) void combine_kernel(
    const float* __restrict__ x1, const float* __restrict__ y,
    const int* __restrict__ slotpos, const float* __restrict__ topG,
    float* __restrict__ out)
{
    int idx = blockIdx.x * 256 + threadIdx.x;
    int t = idx >> 10, d = idx & 1023;
    int p0 = slotpos[t * 2 + 0], p1 = slotpos[t * 2 + 1];
    float g0 = topG[t * 2 + 0], g1 = topG[t * 2 + 1];
    out[idx] = x1[idx] + g0 * y[(size_t)p0 * DMODEL + d] + g1 * y[(size_t)p1 * DMODEL + d];
}

// ---------------- host launch ----------------
#define GETSYM(ptr, sym) do { void* _p_; cudaGetSymbolAddress(&_p_, sym); ptr = (decltype(ptr))_p_; } while (0)

extern "C" void kernel_launch(void* const* d_in, const int* in_sizes, int n_in,
                              void* d_out, int out_size)
{
    const float* x        = (const float*)d_in[0];
    const float* norm1_w  = (const float*)d_in[1];
    const float* norm2_w  = (const float*)d_in[2];
    const float* wq_idx   = (const float*)d_in[3];
    const float* wk_idx   = (const float*)d_in[4];
    const float* w_head   = (const float*)d_in[5];
    const float* wq       = (const float*)d_in[6];
    const float* wk       = (const float*)d_in[7];
    const float* wv       = (const float*)d_in[8];
    const float* wo       = (const float*)d_in[9];
    const float* router_w = (const float*)d_in[10];
    const float* router_b = (const float*)d_in[11];
    const float* w1       = (const float*)d_in[12];
    const float* b1       = (const float*)d_in[13];
    const float* w2       = (const float*)d_in[14];
    const float* b2       = (const float*)d_in[15];

    float* out    = (float*)d_out;
    float* auxp   = out + (size_t)TSEQ * DMODEL;
    float* idxout = auxp + 1;

    float *p_xn, *p_qi, *p_ki, *p_hw, *p_qb, *p_kb, *p_vb, *p_qh, *p_kh, *p_vh;
    float *p_av, *p_x1, *p_x2n, *p_probs, *p_topG, *p_mid, *p_y;
    int *p_top, *p_topE, *p_counts, *p_segoff, *p_rowmap, *p_slotpos;
    unsigned int *p_mask;
    GETSYM(p_xn, g_xn); GETSYM(p_qi, g_qi); GETSYM(p_ki, g_ki); GETSYM(p_hw, g_hw);
    GETSYM(p_qb, g_qb); GETSYM(p_kb, g_kb); GETSYM(p_vb, g_vb);
    GETSYM(p_qh, g_qh); GETSYM(p_kh, g_kh); GETSYM(p_vh, g_vh);
    GETSYM(p_top, g_top); GETSYM(p_av, g_av); GETSYM(p_x1, g_x1); GETSYM(p_x2n, g_x2n);
    GETSYM(p_probs, g_probs); GETSYM(p_topE, g_topE); GETSYM(p_topG, g_topG);
    GETSYM(p_counts, g_counts); GETSYM(p_segoff, g_segoff);
    GETSYM(p_rowmap, g_rowmap); GETSYM(p_slotpos, g_slotpos);
    GETSYM(p_mid, g_mid); GETSYM(p_y, g_yy); GETSYM(p_mask, g_mask);

    cudaFuncSetAttribute(tgemm, cudaFuncAttributeMaxDynamicSharedMemorySize, TG_SMEM_BYTES);

    // 1. norm1
    rmsnorm_kernel<<<TSEQ, 256>>>(x, norm1_w, p_xn);

    // 2. projections
    tgemm<<<dim3(2, 16, 1), 256, TG_SMEM_BYTES>>>(p_xn, DMODEL, nullptr, wq_idx, 0, nullptr, 0,
        nullptr, p_qi, HIDX * DIDX, nullptr, TSEQ, HIDX * DIDX, DMODEL, 0);
    tgemm<<<dim3(1, 16, 1), 256, TG_SMEM_BYTES>>>(p_xn, DMODEL, nullptr, wk_idx, 0, nullptr, 0,
        nullptr, p_ki, DIDX, nullptr, TSEQ, DIDX, DMODEL, 0);
    tgemm<<<dim3(1, 16, 1), 256, TG_SMEM_BYTES>>>(p_xn, DMODEL, nullptr, w_head, 0, nullptr, 0,
        nullptr, p_hw, HIDX, nullptr, TSEQ, HIDX, DMODEL, 0);
    tgemm<<<dim3(8, 16, 1), 256, TG_SMEM_BYTES>>>(p_xn, DMODEL, nullptr, wq, 0, nullptr, 0,
        nullptr, p_qb, DMODEL, nullptr, TSEQ, DMODEL, DMODEL, 0);
    tgemm<<<dim3(8, 16, 1), 256, TG_SMEM_BYTES>>>(p_xn, DMODEL, nullptr, wk, 0, nullptr, 0,
        nullptr, p_kb, DMODEL, nullptr, TSEQ, DMODEL, DMODEL, 0);
    tgemm<<<dim3(8, 16, 1), 256, TG_SMEM_BYTES>>>(p_xn, DMODEL, nullptr, wv, 0, nullptr, 0,
        nullptr, p_vb, DMODEL, nullptr, TSEQ, DMODEL, DMODEL, 0);

    // 3. indexer scores + top-512 + mask
    idx_kernel<<<dim3(32, 32), 256>>>(p_qi, p_ki, p_hw, idxout);
    topk_kernel<<<TSEQ, 1024>>>(idxout, p_top);
    mask_zero_kernel<<<(TSEQ * 64) / 256, 256>>>(p_mask);
    mask_scatter_kernel<<<TSEQ, KSEL>>>(p_top, p_mask);

    // 4. rope + transpose
    rope_kernel<<<(TSEQ * DMODEL) / 256, 256>>>(p_qb, p_kb, p_vb, p_qh, p_kh, p_vh);

    // 5. dense masked flash attention
    attn_flash<<<dim3(TSEQ / 64, NHEAD), 256>>>(p_qh, p_kh, p_vh, p_mask, p_av);

    // 6. output projection + residual
    tgemm<<<dim3(8, 16, 1), 256, TG_SMEM_BYTES>>>(p_av, DMODEL, nullptr, wo, 0, nullptr, 0,
        x, p_x1, DMODEL, nullptr, TSEQ, DMODEL, DMODEL, 0);

    // 7. norm2 + router + grouping + aux
    rmsnorm_kernel<<<TSEQ, 256>>>(p_x1, norm2_w, p_x2n);
    router_kernel<<<TSEQ, 256>>>(p_x2n, router_w, router_b, p_probs, p_topE, p_topG);
    group_kernel<<<1, 8>>>(p_topE, p_counts, p_segoff, p_rowmap, p_slotpos);
    aux_kernel<<<1, 256>>>(p_probs, p_counts, auxp);

    // 8. MoE grouped GEMMs
    tgemm<<<dim3(DFFN / 128, 16, NEXP), 256, TG_SMEM_BYTES>>>(
        p_x2n, DMODEL, p_rowmap, w1, (long long)DMODEL * DFFN, b1, DFFN,
        nullptr, p_mid, DFFN, p_segoff, 0, DFFN, DMODEL, 1);
    tgemm<<<dim3(DMODEL / 128, 16, NEXP), 256, TG_SMEM_BYTES>>>(
        p_mid, DFFN, nullptr, w2, (long long)DFFN * DMODEL, b2, DMODEL,
        nullptr, p_y, DMODEL, p_segoff, 0, DMODEL, DFFN, 0);

    // 9. combine
    combine_kernel<<<(TSEQ * DMODEL) / 256, 256>>>(p_x1, p_y, p_slotpos, p_topG, out);
}

// round 5
// speedup vs baseline: 2.8404x; 1.0632x over previous
#include <cuda_runtime.h>
#include <math.h>
#include <stdint.h>

// ---------------- constants ----------------
static const int TSEQ = 2048;
static const int DMODEL = 1024;
static const int NHEAD = 16;
static const int HDIM = 64;
static const int DFFN = 4096;
static const int NEXP = 8;
static const int HIDX = 4;
static const int DIDX = 64;
static const int KSEL = 512;
static const int NPROJ_IDX = HIDX * DIDX + DIDX + HIDX;  // 324
static const int NPROJ_QKV = 3 * DMODEL;                 // 3072

// ---------------- device scratch ----------------
__device__ float g_xn[TSEQ * DMODEL];
__device__ float g_proj_idx[TSEQ * NPROJ_IDX];
__device__ float g_qkv[TSEQ * NPROJ_QKV];
__device__ float g_qh[TSEQ * DMODEL];
__device__ float g_kh[TSEQ * DMODEL];
__device__ float g_vh[TSEQ * DMODEL];
__device__ int   g_top[TSEQ * KSEL];
__device__ float g_av[TSEQ * DMODEL];
__device__ float g_x1[TSEQ * DMODEL];
__device__ float g_x2n[TSEQ * DMODEL];   // tf32-rounded (GEMM operand)
__device__ float g_x2f[TSEQ * DMODEL];   // full fp32 (router input)
__device__ float g_probs[TSEQ * NEXP];
__device__ int   g_topE[TSEQ * 2];
__device__ float g_topG[TSEQ * 2];
__device__ int   g_counts[NEXP];
__device__ int   g_segoff[NEXP + 1];
__device__ int   g_rowmap[TSEQ * 2];
__device__ int   g_slotpos[TSEQ * 2];
__device__ float g_mid[(size_t)(TSEQ * 2) * DFFN];
__device__ float g_yy[(size_t)(TSEQ * 2) * DMODEL];
__device__ unsigned int g_mask[TSEQ * (TSEQ / 32)];
// tf32-rounded weight copies
__device__ float g_w1c[(size_t)NEXP * DMODEL * DFFN];
__device__ float g_w2c[(size_t)NEXP * DFFN * DMODEL];
__device__ float g_woc[DMODEL * DMODEL];
__device__ float g_wqkvc[DMODEL * NPROJ_QKV];
__device__ float g_widxc[DMODEL * NPROJ_IDX];

// ---------------- helpers ----------------
__device__ __forceinline__ float gelu_tanh(float x) {
    float x3 = x * x * x;
    float u = 0.7978845608028654f * (x + 0.044715f * x3);
    return 0.5f * x * (1.0f + tanhf(u));
}

__device__ __forceinline__ unsigned int fmono(float f) {
    unsigned int u = __float_as_uint(f);
    return (u & 0x80000000u) ? ~u : (u | 0x80000000u);
}

__device__ __forceinline__ uint32_t f2tf32(float f) {
    uint32_t r;
    asm("cvt.rna.tf32.f32 %0, %1;" : "=r"(r) : "f"(f));
    return r;
}
__device__ __forceinline__ float rtf(float f) { return __uint_as_float(f2tf32(f)); }

__device__ __forceinline__ void cp16(uint32_t dst, const float* src, int sz) {
    asm volatile("cp.async.cg.shared.global [%0], [%1], 16, %2;" :: "r"(dst), "l"(src), "r"(sz));
}

__device__ __forceinline__ void mma_tf32(float* c, const uint32_t* a, const uint32_t* b) {
    asm volatile(
        "mma.sync.aligned.m16n8k8.row.col.f32.tf32.tf32.f32 "
        "{%0,%1,%2,%3}, {%4,%5,%6,%7}, {%8,%9}, {%0,%1,%2,%3};"
        : "+f"(c[0]), "+f"(c[1]), "+f"(c[2]), "+f"(c[3])
        : "r"(a[0]), "r"(a[1]), "r"(a[2]), "r"(a[3]), "r"(b[0]), "r"(b[1]));
}

// ---------------- weight conversion / packing ----------------
__global__ __launch_bounds__(256) void round4_kernel(
    const float4* __restrict__ in, float4* __restrict__ out, int n4)
{
    int i = blockIdx.x * 256 + threadIdx.x;
    if (i < n4) {
        float4 v = in[i];
        v.x = rtf(v.x); v.y = rtf(v.y); v.z = rtf(v.z); v.w = rtf(v.w);
        out[i] = v;
    }
}

__global__ __launch_bounds__(256) void pack_qkv_kernel(
    const float* __restrict__ wq, const float* __restrict__ wk, const float* __restrict__ wv,
    float* __restrict__ out)
{
    int i = blockIdx.x * 256 + threadIdx.x;  // over 1024*1024
    int d = i >> 10, c = i & 1023;
    out[(size_t)d * NPROJ_QKV + c] = rtf(wq[i]);
    out[(size_t)d * NPROJ_QKV + DMODEL + c] = rtf(wk[i]);
    out[(size_t)d * NPROJ_QKV + 2 * DMODEL + c] = rtf(wv[i]);
}

__global__ __launch_bounds__(256) void pack_idx_kernel(
    const float* __restrict__ wq_idx, const float* __restrict__ wk_idx,
    const float* __restrict__ w_head, float* __restrict__ out)
{
    int i = blockIdx.x * 256 + threadIdx.x;  // over 1024*324
    if (i >= DMODEL * NPROJ_IDX) return;
    int d = i / NPROJ_IDX, j = i - d * NPROJ_IDX;
    float v;
    if (j < 256) v = wq_idx[d * 256 + j];
    else if (j < 320) v = wk_idx[d * 64 + (j - 256)];
    else v = w_head[d * 4 + (j - 320)];
    out[i] = rtf(v);
}

// ---------------- unified tf32 tensor GEMM (pre-rounded operands, no in-loop CVT) ----------------
#define BKM 128
#define BKN 128
#define BKK 32
#define LDA_S 36
#define LDB_S 132
#define A_STAGE (BKM * LDA_S)
#define B_STAGE (BKK * LDB_S)
#define STAGE_FLOATS (A_STAGE + B_STAGE)
#define NSTAGE 2
#define TG_SMEM_BYTES (NSTAGE * STAGE_FLOATS * 4)

extern __shared__ float smem_dyn[];

__global__ void __launch_bounds__(256, 2) tgemm(
    const float* __restrict__ A, int lda,
    const int* __restrict__ rowmap,
    const float* __restrict__ Bbase, long long strideB,
    const float* __restrict__ biasBase, int biasStride,
    const float* __restrict__ residual,
    float* __restrict__ C, int ldc,
    const int* __restrict__ segoff,
    int M, int N, int K, int doGelu)
{
    int e = blockIdx.z;
    int s0 = 0, nrows = M;
    if (segoff) { s0 = segoff[e]; nrows = segoff[e + 1] - s0; }
    int rowTile = blockIdx.y;
    if (rowTile * BKM >= nrows) return;
    int colStart = blockIdx.x * BKN;
    const float* B = Bbase + (long long)e * strideB;

    int tid = threadIdx.x;
    int warpId = tid >> 5, lane = tid & 31;
    int grp = lane >> 2, tig = lane & 3;
    int wm = (warpId >> 2) * 64;
    int wn = (warpId & 3) * 32;

    uint32_t sbase = (uint32_t)__cvta_generic_to_shared(smem_dyn);

    const float* aSrc[4]; int aSz[4]; uint32_t aDst[4];
    const float* bSrc[4]; int bSz[4]; uint32_t bDst[4];
#pragma unroll
    for (int i = 0; i < 4; i++) {
        int c = tid + i * 256;
        int arow = c >> 3, akc = (c & 7) * 4;
        int lrow = rowTile * BKM + arow;
        bool v = lrow < nrows;
        int gidx = 0;
        if (v) {
            int base = s0 + lrow;
            gidx = rowmap ? rowmap[base] : base;
        }
        aSrc[i] = A + (size_t)gidx * lda + akc;
        aSz[i] = v ? 16 : 0;
        aDst[i] = (uint32_t)((arow * LDA_S + akc) * 4);

        int brow = c >> 5, bnc = (c & 31) * 4;
        int col = colStart + bnc;
        bool bv = (col + 4 <= N);
        bSz[i] = bv ? 16 : 0;
        bSrc[i] = B + (size_t)brow * N + (bv ? col : 0);
        bDst[i] = (uint32_t)((A_STAGE + brow * LDB_S + bnc) * 4);
    }

    float acc[4][4][4];
#pragma unroll
    for (int mi = 0; mi < 4; mi++)
#pragma unroll
        for (int ni = 0; ni < 4; ni++)
#pragma unroll
            for (int q = 0; q < 4; q++) acc[mi][ni][q] = 0.f;

    int KT = K / BKK;

#pragma unroll
    for (int p = 0; p < NSTAGE - 1; p++) {
        if (p < KT) {
            int k0 = p * BKK;
            uint32_t sb = sbase + (uint32_t)((p % NSTAGE) * STAGE_FLOATS * 4);
#pragma unroll
            for (int i = 0; i < 4; i++) cp16(sb + aDst[i], aSrc[i] + k0, aSz[i]);
#pragma unroll
            for (int i = 0; i < 4; i++) cp16(sb + bDst[i], bSrc[i] + (size_t)k0 * N, bSz[i]);
            asm volatile("cp.async.commit_group;");
        }
    }

    for (int it = 0; it < KT; it++) {
        if (it + NSTAGE - 1 < KT) {
            int k0 = (it + NSTAGE - 1) * BKK;
            uint32_t sb = sbase + (uint32_t)(((it + NSTAGE - 1) % NSTAGE) * STAGE_FLOATS * 4);
#pragma unroll
            for (int i = 0; i < 4; i++) cp16(sb + aDst[i], aSrc[i] + k0, aSz[i]);
#pragma unroll
            for (int i = 0; i < 4; i++) cp16(sb + bDst[i], bSrc[i] + (size_t)k0 * N, bSz[i]);
            asm volatile("cp.async.commit_group;");
            asm volatile("cp.async.wait_group 1;");
        } else {
            asm volatile("cp.async.wait_group 0;");
        }
        __syncthreads();

        const uint32_t* Ab = (const uint32_t*)(smem_dyn + (size_t)(it % NSTAGE) * STAGE_FLOATS);
        const uint32_t* Bb = Ab + A_STAGE;
#pragma unroll
        for (int ks = 0; ks < 4; ks++) {
            int kb = ks * 8;
            uint32_t af[4][4];
#pragma unroll
            for (int mi = 0; mi < 4; mi++) {
                int r = wm + mi * 16 + grp;
                af[mi][0] = Ab[r * LDA_S + kb + tig];
                af[mi][1] = Ab[(r + 8) * LDA_S + kb + tig];
                af[mi][2] = Ab[r * LDA_S + kb + tig + 4];
                af[mi][3] = Ab[(r + 8) * LDA_S + kb + tig + 4];
            }
            uint32_t bf[4][2];
#pragma unroll
            for (int ni = 0; ni < 4; ni++) {
                int ccol = wn + ni * 8 + grp;
                bf[ni][0] = Bb[(kb + tig) * LDB_S + ccol];
                bf[ni][1] = Bb[(kb + tig + 4) * LDB_S + ccol];
            }
#pragma unroll
            for (int mi = 0; mi < 4; mi++)
#pragma unroll
                for (int ni = 0; ni < 4; ni++)
                    mma_tf32(acc[mi][ni], af[mi], bf[ni]);
        }
        __syncthreads();
    }

    const float* bias = biasBase ? (biasBase + (long long)e * biasStride) : nullptr;
#pragma unroll
    for (int mi = 0; mi < 4; mi++) {
        int rbase = wm + mi * 16 + grp;
#pragma unroll
        for (int half = 0; half < 2; half++) {
            int r = rbase + half * 8;
            int lrow = rowTile * BKM + r;
            if (lrow >= nrows) continue;
            int grow = s0 + lrow;
#pragma unroll
            for (int ni = 0; ni < 4; ni++) {
                int col = colStart + wn + ni * 8 + tig * 2;
                float v0 = acc[mi][ni][half * 2 + 0];
                float v1 = acc[mi][ni][half * 2 + 1];
                if (bias) { v0 += bias[col]; v1 += bias[col + 1]; }
                if (doGelu) {
                    v0 = rtf(gelu_tanh(v0));   // gelu output feeds next GEMM: pre-round
                    v1 = rtf(gelu_tanh(v1));
                }
                if (residual) {
                    v0 += residual[(size_t)grow * ldc + col];
                    v1 += residual[(size_t)grow * ldc + col + 1];
                }
                if (col < N)     C[(size_t)grow * ldc + col] = v0;
                if (col + 1 < N) C[(size_t)grow * ldc + col + 1] = v1;
            }
        }
    }
}

// ---------------- rmsnorm (rounded main output; optional full-precision copy) ----------------
__global__ __launch_bounds__(256) void rmsnorm_kernel(
    const float* __restrict__ x, const float* __restrict__ w,
    float* __restrict__ y, float* __restrict__ yfull)
{
    int t = blockIdx.x, tid = threadIdx.x;
    __shared__ float red[256];
    const float* xr = x + (size_t)t * DMODEL;
    float s = 0.f;
    for (int d = tid; d < DMODEL; d += 256) { float v = xr[d]; s += v * v; }
    red[tid] = s; __syncthreads();
    for (int o = 128; o > 0; o >>= 1) { if (tid < o) red[tid] += red[tid + o]; __syncthreads(); }
    float rms = rsqrtf(red[0] / (float)DMODEL + 1e-6f);
    float* yr = y + (size_t)t * DMODEL;
    for (int d = tid; d < DMODEL; d += 256) {
        float v = xr[d] * rms * w[d];
        yr[d] = rtf(v);
        if (yfull) yfull[(size_t)t * DMODEL + d] = v;
    }
}

// ---------------- indexer scores (reads fused proj buffer, stride 324) ----------------
__global__ __launch_bounds__(256) void idx_kernel(
    const float* __restrict__ proj, float* __restrict__ out)
{
    __shared__ float qsh[64][65];
    __shared__ float ksh[64][65];
    __shared__ float hsh[64][4];
    int t0 = blockIdx.y * 64, s0 = blockIdx.x * 64;
    int tid = threadIdx.x;
    const int tr = (tid >> 4) * 4, tc = (tid & 15) * 4;

    hsh[tid >> 2][tid & 3] = proj[(size_t)(t0 + (tid >> 2)) * NPROJ_IDX + 320 + (tid & 3)];
    for (int i = tid; i < 4096; i += 256) {
        int r = i >> 6, c = i & 63;
        ksh[r][c] = proj[(size_t)(s0 + r) * NPROJ_IDX + 256 + c];
    }
    float acc[4][4];
#pragma unroll
    for (int i = 0; i < 4; i++)
#pragma unroll
        for (int j = 0; j < 4; j++) acc[i][j] = 0.f;

    for (int h = 0; h < HIDX; h++) {
        __syncthreads();
        for (int i = tid; i < 4096; i += 256) {
            int r = i >> 6, c = i & 63;
            qsh[r][c] = proj[(size_t)(t0 + r) * NPROJ_IDX + h * DIDX + c];
        }
        __syncthreads();
        float dot[4][4];
#pragma unroll
        for (int i = 0; i < 4; i++)
#pragma unroll
            for (int j = 0; j < 4; j++) dot[i][j] = 0.f;
        for (int kk = 0; kk < 64; kk++) {
            float a[4], b[4];
#pragma unroll
            for (int i = 0; i < 4; i++) a[i] = qsh[tr + i][kk];
#pragma unroll
            for (int j = 0; j < 4; j++) b[j] = ksh[tc + j][kk];
#pragma unroll
            for (int i = 0; i < 4; i++)
#pragma unroll
                for (int j = 0; j < 4; j++) dot[i][j] += a[i] * b[j];
        }
#pragma unroll
        for (int i = 0; i < 4; i++)
#pragma unroll
            for (int j = 0; j < 4; j++)
                acc[i][j] += hsh[tr + i][h] * fmaxf(dot[i][j], 0.f);
    }
#pragma unroll
    for (int i = 0; i < 4; i++)
#pragma unroll
        for (int j = 0; j < 4; j++)
            out[(size_t)(t0 + tr + i) * TSEQ + (s0 + tc + j)] = acc[i][j] * 0.125f;
}

// ---------------- top-512 per row via bitonic sort ----------------
__global__ __launch_bounds__(1024) void topk_kernel(
    const float* __restrict__ idxs, int* __restrict__ topIdx)
{
    __shared__ unsigned long long key[2048];
    int t = blockIdx.x, tid = threadIdx.x;
    for (int i = tid; i < 2048; i += 1024) {
        unsigned long long kk = 0ull;
        if (i <= t) {
            float v = idxs[(size_t)t * TSEQ + i];
            kk = ((unsigned long long)fmono(v) << 32) | (unsigned int)(2047 - i);
        }
        key[i] = kk;
    }
    __syncthreads();
    for (int k = 2; k <= 2048; k <<= 1) {
        for (int j = k >> 1; j > 0; j >>= 1) {
            for (int i = tid; i < 2048; i += 1024) {
                int ixj = i ^ j;
                if (ixj > i) {
                    unsigned long long a = key[i], b = key[ixj];
                    bool descSeg = ((i & k) == 0);
                    if (descSeg ? (a < b) : (a > b)) { key[i] = b; key[ixj] = a; }
                }
            }
            __syncthreads();
        }
    }
    if (tid < KSEL)
        topIdx[(size_t)t * KSEL + tid] = 2047 - (int)(key[tid] & 0xFFFFFFFFu);
}

// ---------------- mask build ----------------
__global__ __launch_bounds__(256) void mask_zero_kernel(unsigned int* __restrict__ mask)
{
    int i = blockIdx.x * 256 + threadIdx.x;
    mask[i] = 0u;
}

__global__ __launch_bounds__(512) void mask_scatter_kernel(
    const int* __restrict__ topIdx, unsigned int* __restrict__ mask)
{
    int t = blockIdx.x, j = threadIdx.x;
    int s = topIdx[(size_t)t * KSEL + j];
    if (s <= t) atomicOr(&mask[t * 64 + (s >> 5)], 1u << (s & 31));
}

// ---------------- RoPE from fused qkv + transpose to [h][t][d], rounds outputs ----------------
__global__ __launch_bounds__(256) void rope_kernel(
    const float* __restrict__ qkv,
    float* __restrict__ qh, float* __restrict__ kh, float* __restrict__ vh)
{
    int idx = blockIdx.x * 256 + threadIdx.x;
    int t = idx >> 10;
    int hd = idx & 1023;
    int h = hd >> 6, d = hd & 63;
    int j = d & 31;
    double invd = exp(-((double)(2 * j) / 64.0) * log(10000.0));
    float ang = (float)((double)t * invd);
    float c = cosf(ang), s = sinf(ang);
    const float* row = qkv + (size_t)t * NPROJ_QKV;
    float q = row[hd], k = row[DMODEL + hd], v = row[2 * DMODEL + hd];
    float qr, kr;
    if (d < 32) {
        qr = q * c - row[hd + 32] * s;
        kr = k * c - row[DMODEL + hd + 32] * s;
    } else {
        qr = q * c + row[hd - 32] * s;
        kr = k * c + row[DMODEL + hd - 32] * s;
    }
    int o = ((h * TSEQ) + t) * HDIM + d;
    qh[o] = rtf(qr); kh[o] = rtf(kr); vh[o] = rtf(v);
}

// ---------------- dense masked flash attention (tf32 mma, pre-rounded inputs) ----------------
__global__ void __launch_bounds__(256, 2) attn_flash(
    const float* __restrict__ qh, const float* __restrict__ kh, const float* __restrict__ vh,
    const unsigned int* __restrict__ mask, float* __restrict__ av)
{
    __shared__ float Ks[64][68];
    __shared__ float Vs[64][68];
    __shared__ float Ps[64][68];
    __shared__ float rowM[64], rowL[64], rowScale[64];

    int qt = blockIdx.x, h = blockIdx.y;
    int t0 = qt * 64;
    int tid = threadIdx.x;
    int warpId = tid >> 5, lane = tid & 31;
    int grp = lane >> 2, tig = lane & 3;
    int wm = (warpId >> 1) * 16;
    int wn = (warpId & 1) * 32;

    const float* Q0 = qh + ((size_t)h * TSEQ + t0) * HDIM;
    uint32_t qf[8][4];
#pragma unroll
    for (int ks = 0; ks < 8; ks++) {
        int kb = ks * 8;
        qf[ks][0] = __float_as_uint(Q0[(wm + grp) * HDIM + kb + tig]);
        qf[ks][1] = __float_as_uint(Q0[(wm + grp + 8) * HDIM + kb + tig]);
        qf[ks][2] = __float_as_uint(Q0[(wm + grp) * HDIM + kb + tig + 4]);
        qf[ks][3] = __float_as_uint(Q0[(wm + grp + 8) * HDIM + kb + tig + 4]);
    }

    if (tid < 64) { rowM[tid] = -INFINITY; rowL[tid] = 0.f; }

    float oacc[4][4];
#pragma unroll
    for (int ni = 0; ni < 4; ni++)
#pragma unroll
        for (int q = 0; q < 4; q++) oacc[ni][q] = 0.f;

    const float* Kb = kh + (size_t)h * TSEQ * HDIM;
    const float* Vb = vh + (size_t)h * TSEQ * HDIM;

    for (int kt = 0; kt <= qt; kt++) {
        __syncthreads();
        for (int i = tid; i < 1024; i += 256) {
            int row = i >> 4, c4 = (i & 15) * 4;
            *(float4*)&Ks[row][c4] = *(const float4*)(Kb + (size_t)(kt * 64 + row) * HDIM + c4);
            *(float4*)&Vs[row][c4] = *(const float4*)(Vb + (size_t)(kt * 64 + row) * HDIM + c4);
        }
        __syncthreads();

        float sacc[4][4];
#pragma unroll
        for (int ni = 0; ni < 4; ni++)
#pragma unroll
            for (int q = 0; q < 4; q++) sacc[ni][q] = 0.f;
#pragma unroll
        for (int ks = 0; ks < 8; ks++) {
            int kb = ks * 8;
#pragma unroll
            for (int ni = 0; ni < 4; ni++) {
                int n = wn + ni * 8 + grp;
                uint32_t bf[2];
                bf[0] = __float_as_uint(Ks[n][kb + tig]);
                bf[1] = __float_as_uint(Ks[n][kb + tig + 4]);
                mma_tf32(sacc[ni], qf[ks], bf);
            }
        }

        int r0 = wm + grp, r1 = wm + grp + 8;
        unsigned int mw0 = mask[(t0 + r0) * 64 + kt * 2 + (wn >> 5)];
        unsigned int mw1 = mask[(t0 + r1) * 64 + kt * 2 + (wn >> 5)];
#pragma unroll
        for (int ni = 0; ni < 4; ni++) {
            int c = wn + ni * 8 + tig * 2;
            int b = ni * 8 + tig * 2;
            Ps[r0][c]     = ((mw0 >> b) & 1u)       ? sacc[ni][0] * 0.125f : -INFINITY;
            Ps[r0][c + 1] = ((mw0 >> (b + 1)) & 1u) ? sacc[ni][1] * 0.125f : -INFINITY;
            Ps[r1][c]     = ((mw1 >> b) & 1u)       ? sacc[ni][2] * 0.125f : -INFINITY;
            Ps[r1][c + 1] = ((mw1 >> (b + 1)) & 1u) ? sacc[ni][3] * 0.125f : -INFINITY;
        }
        __syncthreads();

        {
            int row = tid >> 2, seg = tid & 3;
            float m_old = rowM[row];
            float tmax = -INFINITY;
#pragma unroll
            for (int j = 0; j < 16; j++) tmax = fmaxf(tmax, Ps[row][seg * 16 + j]);
            tmax = fmaxf(tmax, __shfl_xor_sync(0xFFFFFFFFu, tmax, 1));
            tmax = fmaxf(tmax, __shfl_xor_sync(0xFFFFFFFFu, tmax, 2));
            float mnew = fmaxf(m_old, tmax);
            bool inval = (mnew == -INFINITY);
            float tsum = 0.f;
#pragma unroll
            for (int j = 0; j < 16; j++) {
                float v = Ps[row][seg * 16 + j];
                float p = inval ? 0.f : expf(v - mnew);
                Ps[row][seg * 16 + j] = rtf(p);
                tsum += p;
            }
            tsum += __shfl_xor_sync(0xFFFFFFFFu, tsum, 1);
            tsum += __shfl_xor_sync(0xFFFFFFFFu, tsum, 2);
            if (seg == 0) {
                float sc = inval ? 1.f : expf(m_old - mnew);
                rowScale[row] = sc;
                rowM[row] = mnew;
                rowL[row] = rowL[row] * sc + tsum;
            }
        }
        __syncthreads();

        float s0 = rowScale[wm + grp], s1 = rowScale[wm + grp + 8];
#pragma unroll
        for (int ni = 0; ni < 4; ni++) {
            oacc[ni][0] *= s0; oacc[ni][1] *= s0;
            oacc[ni][2] *= s1; oacc[ni][3] *= s1;
        }
#pragma unroll
        for (int ks = 0; ks < 8; ks++) {
            int kb = ks * 8;
            uint32_t pa[4];
            pa[0] = __float_as_uint(Ps[wm + grp][kb + tig]);
            pa[1] = __float_as_uint(Ps[wm + grp + 8][kb + tig]);
            pa[2] = __float_as_uint(Ps[wm + grp][kb + tig + 4]);
            pa[3] = __float_as_uint(Ps[wm + grp + 8][kb + tig + 4]);
#pragma unroll
            for (int ni = 0; ni < 4; ni++) {
                int n = wn + ni * 8 + grp;
                uint32_t vf[2];
                vf[0] = __float_as_uint(Vs[kb + tig][n]);
                vf[1] = __float_as_uint(Vs[kb + tig + 4][n]);
                mma_tf32(oacc[ni], pa, vf);
            }
        }
    }
    __syncthreads();

    float i0 = 1.f / rowL[wm + grp];
    float i1 = 1.f / rowL[wm + grp + 8];
#pragma unroll
    for (int ni = 0; ni < 4; ni++) {
        int c = wn + ni * 8 + tig * 2;
        size_t o0 = (size_t)(t0 + wm + grp) * DMODEL + h * HDIM + c;
        size_t o1 = (size_t)(t0 + wm + grp + 8) * DMODEL + h * HDIM + c;
        av[o0]     = rtf(oacc[ni][0] * i0);
        av[o0 + 1] = rtf(oacc[ni][1] * i0);
        av[o1]     = rtf(oacc[ni][2] * i1);
        av[o1 + 1] = rtf(oacc[ni][3] * i1);
    }
}

// ---------------- router (reads FULL-precision x2n) ----------------
__global__ __launch_bounds__(256) void router_kernel(
    const float* __restrict__ x2n, const float* __restrict__ rw, const float* __restrict__ rb,
    float* __restrict__ probs, int* __restrict__ topE, float* __restrict__ topG)
{
    int t = blockIdx.x, tid = threadIdx.x;
    __shared__ float red[256];
    __shared__ float lg[8];
    float acc[8];
#pragma unroll
    for (int e = 0; e < 8; e++) acc[e] = 0.f;
    const float* xr = x2n + (size_t)t * DMODEL;
    for (int d = tid; d < DMODEL; d += 256) {
        float xv = xr[d];
#pragma unroll
        for (int e = 0; e < 8; e++) acc[e] += xv * rw[(size_t)d * NEXP + e];
    }
    for (int e = 0; e < 8; e++) {
        red[tid] = acc[e]; __syncthreads();
        for (int o = 128; o > 0; o >>= 1) { if (tid < o) red[tid] += red[tid + o]; __syncthreads(); }
        if (tid == 0) lg[e] = red[0] + rb[e];
        __syncthreads();
    }
    if (tid == 0) {
        float m = lg[0];
        for (int e = 1; e < 8; e++) m = fmaxf(m, lg[e]);
        float p[8], s = 0.f;
        for (int e = 0; e < 8; e++) { p[e] = expf(lg[e] - m); s += p[e]; }
        for (int e = 0; e < 8; e++) p[e] /= s;
        int e0 = 0;
        for (int e = 1; e < 8; e++) if (p[e] > p[e0]) e0 = e;
        int e1 = -1;
        for (int e = 0; e < 8; e++) if (e != e0 && (e1 < 0 || p[e] > p[e1])) e1 = e;
        float denom = p[e0] + p[e1];
        for (int e = 0; e < 8; e++) probs[(size_t)t * NEXP + e] = p[e];
        topE[t * 2 + 0] = e0; topE[t * 2 + 1] = e1;
        topG[t * 2 + 0] = p[e0] / denom; topG[t * 2 + 1] = p[e1] / denom;
    }
}

// ---------------- deterministic grouping ----------------
__global__ void group_kernel(const int* __restrict__ topE, int* __restrict__ counts,
                             int* __restrict__ segoff, int* __restrict__ rowmap,
                             int* __restrict__ slotpos)
{
    int e = threadIdx.x;  // blockDim = 8
    int c = 0;
    for (int t = 0; t < TSEQ; t++)
        for (int s = 0; s < 2; s++)
            if (topE[t * 2 + s] == e) c++;
    counts[e] = c;
    __syncthreads();
    if (e == 0) {
        int o = 0;
        for (int i = 0; i < 8; i++) { segoff[i] = o; o += counts[i]; }
        segoff[8] = o;
    }
    __syncthreads();
    int pos = segoff[e];
    for (int t = 0; t < TSEQ; t++)
        for (int s = 0; s < 2; s++)
            if (topE[t * 2 + s] == e) {
                rowmap[pos] = t;
                slotpos[t * 2 + s] = pos;
                pos++;
            }
}

// ---------------- aux loss ----------------
__global__ __launch_bounds__(256) void aux_kernel(
    const float* __restrict__ probs, const int* __restrict__ counts, float* __restrict__ outAux)
{
    __shared__ float red[256];
    int tid = threadIdx.x;
    float a = 0.f;
    for (int e = 0; e < 8; e++) {
        float s = 0.f;
        for (int t = tid; t < TSEQ; t += 256) s += probs[(size_t)t * NEXP + e];
        red[tid] = s; __syncthreads();
        for (int o = 128; o > 0; o >>= 1) { if (tid < o) red[tid] += red[tid + o]; __syncthreads(); }
        if (tid == 0) a += (float)counts[e] * red[0];
        __syncthreads();
    }
    if (tid == 0) *outAux = 8.f * a / ((float)TSEQ * (float)TSEQ);
}

// ---------------- final combine ----------------
__global__ __launch_bounds__(256) void combine_kernel(
    const float* __restrict__ x1, const float* __restrict__ y,
    const int* __restrict__ slotpos, const float* __restrict__ topG,
    float* __restrict__ out)
{
    int idx = blockIdx.x * 256 + threadIdx.x;
    int t = idx >> 10, d = idx & 1023;
    int p0 = slotpos[t * 2 + 0], p1 = slotpos[t * 2 + 1];
    float g0 = topG[t * 2 + 0], g1 = topG[t * 2 + 1];
    out[idx] = x1[idx] + g0 * y[(size_t)p0 * DMODEL + d] + g1 * y[(size_t)p1 * DMODEL + d];
}

// ---------------- host launch ----------------
#define GETSYM(ptr, sym) do { void* _p_; cudaGetSymbolAddress(&_p_, sym); ptr = (decltype(ptr))_p_; } while (0)

extern "C" void kernel_launch(void* const* d_in, const int* in_sizes, int n_in,
                              void* d_out, int out_size)
{
    const float* x        = (const float*)d_in[0];
    const float* norm1_w  = (const float*)d_in[1];
    const float* norm2_w  = (const float*)d_in[2];
    const float* wq_idx   = (const float*)d_in[3];
    const float* wk_idx   = (const float*)d_in[4];
    const float* w_head   = (const float*)d_in[5];
    const float* wq       = (const float*)d_in[6];
    const float* wk       = (const float*)d_in[7];
    const float* wv       = (const float*)d_in[8];
    const float* wo       = (const float*)d_in[9];
    const float* router_w = (const float*)d_in[10];
    const float* router_b = (const float*)d_in[11];
    const float* w1       = (const float*)d_in[12];
    const float* b1       = (const float*)d_in[13];
    const float* w2       = (const float*)d_in[14];
    const float* b2       = (const float*)d_in[15];

    float* out    = (float*)d_out;
    float* auxp   = out + (size_t)TSEQ * DMODEL;
    float* idxout = auxp + 1;

    float *p_xn, *p_proj, *p_qkv, *p_qh, *p_kh, *p_vh;
    float *p_av, *p_x1, *p_x2n, *p_x2f, *p_probs, *p_topG, *p_mid, *p_y;
    float *p_w1c, *p_w2c, *p_woc, *p_wqkvc, *p_widxc;
    int *p_top, *p_topE, *p_counts, *p_segoff, *p_rowmap, *p_slotpos;
    unsigned int *p_mask;
    GETSYM(p_xn, g_xn); GETSYM(p_proj, g_proj_idx); GETSYM(p_qkv, g_qkv);
    GETSYM(p_qh, g_qh); GETSYM(p_kh, g_kh); GETSYM(p_vh, g_vh);
    GETSYM(p_top, g_top); GETSYM(p_av, g_av); GETSYM(p_x1, g_x1);
    GETSYM(p_x2n, g_x2n); GETSYM(p_x2f, g_x2f);
    GETSYM(p_probs, g_probs); GETSYM(p_topE, g_topE); GETSYM(p_topG, g_topG);
    GETSYM(p_counts, g_counts); GETSYM(p_segoff, g_segoff);
    GETSYM(p_rowmap, g_rowmap); GETSYM(p_slotpos, g_slotpos);
    GETSYM(p_mid, g_mid); GETSYM(p_y, g_yy); GETSYM(p_mask, g_mask);
    GETSYM(p_w1c, g_w1c); GETSYM(p_w2c, g_w2c); GETSYM(p_woc, g_woc);
    GETSYM(p_wqkvc, g_wqkvc); GETSYM(p_widxc, g_widxc);

    cudaFuncSetAttribute(tgemm, cudaFuncAttributeMaxDynamicSharedMemorySize, TG_SMEM_BYTES);

    // 0. weight rounding / packing
    {
        int n4 = NEXP * DMODEL * DFFN / 4;
        round4_kernel<<<(n4 + 255) / 256, 256>>>((const float4*)w1, (float4*)p_w1c, n4);
        round4_kernel<<<(n4 + 255) / 256, 256>>>((const float4*)w2, (float4*)p_w2c, n4);
        int m4 = DMODEL * DMODEL / 4;
        round4_kernel<<<(m4 + 255) / 256, 256>>>((const float4*)wo, (float4*)p_woc, m4);
        pack_qkv_kernel<<<(DMODEL * DMODEL) / 256, 256>>>(wq, wk, wv, p_wqkvc);
        pack_idx_kernel<<<(DMODEL * NPROJ_IDX + 255) / 256, 256>>>(wq_idx, wk_idx, w_head, p_widxc);
    }

    // 1. norm1 (no full-precision copy needed)
    rmsnorm_kernel<<<TSEQ, 256>>>(x, norm1_w, p_xn, nullptr);

    // 2. fused projections
    tgemm<<<dim3((NPROJ_IDX + 127) / 128, 16, 1), 256, TG_SMEM_BYTES>>>(
        p_xn, DMODEL, nullptr, p_widxc, 0, nullptr, 0,
        nullptr, p_proj, NPROJ_IDX, nullptr, TSEQ, NPROJ_IDX, DMODEL, 0);
    tgemm<<<dim3(NPROJ_QKV / 128, 16, 1), 256, TG_SMEM_BYTES>>>(
        p_xn, DMODEL, nullptr, p_wqkvc, 0, nullptr, 0,
        nullptr, p_qkv, NPROJ_QKV, nullptr, TSEQ, NPROJ_QKV, DMODEL, 0);

    // 3. indexer scores + top-512 + mask
    idx_kernel<<<dim3(32, 32), 256>>>(p_proj, idxout);
    topk_kernel<<<TSEQ, 1024>>>(idxout, p_top);
    mask_zero_kernel<<<(TSEQ * 64) / 256, 256>>>(p_mask);
    mask_scatter_kernel<<<TSEQ, KSEL>>>(p_top, p_mask);

    // 4. rope + transpose
    rope_kernel<<<(TSEQ * DMODEL) / 256, 256>>>(p_qkv, p_qh, p_kh, p_vh);

    // 5. dense masked flash attention
    attn_flash<<<dim3(TSEQ / 64, NHEAD), 256>>>(p_qh, p_kh, p_vh, p_mask, p_av);

    // 6. output projection + residual
    tgemm<<<dim3(8, 16, 1), 256, TG_SMEM_BYTES>>>(p_av, DMODEL, nullptr, p_woc, 0, nullptr, 0,
        x, p_x1, DMODEL, nullptr, TSEQ, DMODEL, DMODEL, 0);

    // 7. norm2 (rounded for GEMM + full for router) + router + grouping + aux
    rmsnorm_kernel<<<TSEQ, 256>>>(p_x1, norm2_w, p_x2n, p_x2f);
    router_kernel<<<TSEQ, 256>>>(p_x2f, router_w, router_b, p_probs, p_topE, p_topG);
    group_kernel<<<1, 8>>>(p_topE, p_counts, p_segoff, p_rowmap, p_slotpos);
    aux_kernel<<<1, 256>>>(p_probs, p_counts, auxp);

    // 8. MoE grouped GEMMs
    tgemm<<<dim3(DFFN / 128, 16, NEXP), 256, TG_SMEM_BYTES>>>(
        p_x2n, DMODEL, p_rowmap, p_w1c, (long long)DMODEL * DFFN, b1, DFFN,
        nullptr, p_mid, DFFN, p_segoff, 0, DFFN, DMODEL, 1);
    tgemm<<<dim3(DMODEL / 128, 16, NEXP), 256, TG_SMEM_BYTES>>>(
        p_mid, DFFN, nullptr, p_w2c, (long long)DFFN * DMODEL, b2, DMODEL,
        nullptr, p_y, DMODEL, p_segoff, 0, DMODEL, DFFN, 0);

    // 9. combine
    combine_kernel<<<(TSEQ * DMODEL) / 256, 256>>>(p_x1, p_y, p_slotpos, p_topG, out);
}

// round 6
// speedup vs baseline: 3.3453x; 1.1777x over previous
#include <cuda_runtime.h>
#include <math.h>
#include <stdint.h>

// ---------------- constants ----------------
static const int TSEQ = 2048;
static const int DMODEL = 1024;
static const int NHEAD = 16;
static const int HDIM = 64;
static const int DFFN = 4096;
static const int NEXP = 8;
static const int HIDX = 4;
static const int DIDX = 64;
static const int KSEL = 512;
static const int NPROJ_IDX = HIDX * DIDX + DIDX + HIDX;  // 324
static const int NPROJ_QKV = 3 * DMODEL;                 // 3072

// ---------------- device scratch ----------------
__device__ float g_xn[TSEQ * DMODEL];
__device__ float g_proj_idx[TSEQ * NPROJ_IDX];
__device__ float g_qkv[TSEQ * NPROJ_QKV];
__device__ float g_qh[TSEQ * DMODEL];
__device__ float g_kh[TSEQ * DMODEL];
__device__ float g_vh[TSEQ * DMODEL];
__device__ float g_av[TSEQ * DMODEL];
__device__ float g_x1[TSEQ * DMODEL];
__device__ float g_x2n[TSEQ * DMODEL];   // tf32-rounded (GEMM operand)
__device__ float g_x2f[TSEQ * DMODEL];   // full fp32 (router input)
__device__ float g_probs[TSEQ * NEXP];
__device__ int   g_topE[TSEQ * 2];
__device__ float g_topG[TSEQ * 2];
__device__ int   g_counts[NEXP];
__device__ int   g_segoff[NEXP + 1];
__device__ int   g_rowmap[TSEQ * 2];
__device__ int   g_slotpos[TSEQ * 2];
__device__ float g_mid[(size_t)(TSEQ * 2) * DFFN];
__device__ float g_yy[(size_t)(TSEQ * 2) * DMODEL];
__device__ unsigned int g_mask[TSEQ * (TSEQ / 32)];
// tf32-rounded weight copies
__device__ float g_w1c[(size_t)NEXP * DMODEL * DFFN];
__device__ float g_w2c[(size_t)NEXP * DFFN * DMODEL];
__device__ float g_woc[DMODEL * DMODEL];
__device__ float g_wqkvc[DMODEL * NPROJ_QKV];
__device__ float g_widxc[DMODEL * NPROJ_IDX];

// ---------------- helpers ----------------
__device__ __forceinline__ float gelu_tanh(float x) {
    float x3 = x * x * x;
    float u = 0.7978845608028654f * (x + 0.044715f * x3);
    return 0.5f * x * (1.0f + tanhf(u));
}

__device__ __forceinline__ unsigned int fmono(float f) {
    unsigned int u = __float_as_uint(f);
    return (u & 0x80000000u) ? ~u : (u | 0x80000000u);
}

__device__ __forceinline__ uint32_t f2tf32(float f) {
    uint32_t r;
    asm("cvt.rna.tf32.f32 %0, %1;" : "=r"(r) : "f"(f));
    return r;
}
__device__ __forceinline__ float rtf(float f) { return __uint_as_float(f2tf32(f)); }

__device__ __forceinline__ void cp16(uint32_t dst, const float* src, int sz) {
    asm volatile("cp.async.cg.shared.global [%0], [%1], 16, %2;" :: "r"(dst), "l"(src), "r"(sz));
}

__device__ __forceinline__ void mma_tf32(float* c, const uint32_t* a, const uint32_t* b) {
    asm volatile(
        "mma.sync.aligned.m16n8k8.row.col.f32.tf32.tf32.f32 "
        "{%0,%1,%2,%3}, {%4,%5,%6,%7}, {%8,%9}, {%0,%1,%2,%3};"
        : "+f"(c[0]), "+f"(c[1]), "+f"(c[2]), "+f"(c[3])
        : "r"(a[0]), "r"(a[1]), "r"(a[2]), "r"(a[3]), "r"(b[0]), "r"(b[1]));
}

// ---------------- weight conversion / packing ----------------
__global__ __launch_bounds__(256) void round4_kernel(
    const float4* __restrict__ in, float4* __restrict__ out, int n4)
{
    int i = blockIdx.x * 256 + threadIdx.x;
    if (i < n4) {
        float4 v = in[i];
        v.x = rtf(v.x); v.y = rtf(v.y); v.z = rtf(v.z); v.w = rtf(v.w);
        out[i] = v;
    }
}

__global__ __launch_bounds__(256) void pack_qkv_kernel(
    const float* __restrict__ wq, const float* __restrict__ wk, const float* __restrict__ wv,
    float* __restrict__ out)
{
    int i = blockIdx.x * 256 + threadIdx.x;  // over 1024*1024
    int d = i >> 10, c = i & 1023;
    out[(size_t)d * NPROJ_QKV + c] = rtf(wq[i]);
    out[(size_t)d * NPROJ_QKV + DMODEL + c] = rtf(wk[i]);
    out[(size_t)d * NPROJ_QKV + 2 * DMODEL + c] = rtf(wv[i]);
}

__global__ __launch_bounds__(256) void pack_idx_kernel(
    const float* __restrict__ wq_idx, const float* __restrict__ wk_idx,
    const float* __restrict__ w_head, float* __restrict__ out)
{
    int i = blockIdx.x * 256 + threadIdx.x;  // over 1024*324
    if (i >= DMODEL * NPROJ_IDX) return;
    int d = i / NPROJ_IDX, j = i - d * NPROJ_IDX;
    float v;
    if (j < 256) v = wq_idx[d * 256 + j];
    else if (j < 320) v = wk_idx[d * 64 + (j - 256)];
    else v = w_head[d * 4 + (j - 320)];
    out[i] = rtf(v);
}

// ---------------- unified tf32 tensor GEMM (pre-rounded operands, no in-loop CVT) ----------------
#define BKM 128
#define BKN 128
#define BKK 32
#define LDA_S 36
#define LDB_S 132
#define A_STAGE (BKM * LDA_S)
#define B_STAGE (BKK * LDB_S)
#define STAGE_FLOATS (A_STAGE + B_STAGE)
#define NSTAGE 2
#define TG_SMEM_BYTES (NSTAGE * STAGE_FLOATS * 4)

extern __shared__ float smem_dyn[];

__global__ void __launch_bounds__(256, 2) tgemm(
    const float* __restrict__ A, int lda,
    const int* __restrict__ rowmap,
    const float* __restrict__ Bbase, long long strideB,
    const float* __restrict__ biasBase, int biasStride,
    const float* __restrict__ residual,
    float* __restrict__ C, int ldc,
    const int* __restrict__ segoff,
    int M, int N, int K, int doGelu)
{
    int e = blockIdx.z;
    int s0 = 0, nrows = M;
    if (segoff) { s0 = segoff[e]; nrows = segoff[e + 1] - s0; }
    int rowTile = blockIdx.y;
    if (rowTile * BKM >= nrows) return;
    int colStart = blockIdx.x * BKN;
    const float* B = Bbase + (long long)e * strideB;

    int tid = threadIdx.x;
    int warpId = tid >> 5, lane = tid & 31;
    int grp = lane >> 2, tig = lane & 3;
    int wm = (warpId >> 2) * 64;
    int wn = (warpId & 3) * 32;

    uint32_t sbase = (uint32_t)__cvta_generic_to_shared(smem_dyn);

    const float* aSrc[4]; int aSz[4]; uint32_t aDst[4];
    const float* bSrc[4]; int bSz[4]; uint32_t bDst[4];
#pragma unroll
    for (int i = 0; i < 4; i++) {
        int c = tid + i * 256;
        int arow = c >> 3, akc = (c & 7) * 4;
        int lrow = rowTile * BKM + arow;
        bool v = lrow < nrows;
        int gidx = 0;
        if (v) {
            int base = s0 + lrow;
            gidx = rowmap ? rowmap[base] : base;
        }
        aSrc[i] = A + (size_t)gidx * lda + akc;
        aSz[i] = v ? 16 : 0;
        aDst[i] = (uint32_t)((arow * LDA_S + akc) * 4);

        int brow = c >> 5, bnc = (c & 31) * 4;
        int col = colStart + bnc;
        bool bv = (col + 4 <= N);
        bSz[i] = bv ? 16 : 0;
        bSrc[i] = B + (size_t)brow * N + (bv ? col : 0);
        bDst[i] = (uint32_t)((A_STAGE + brow * LDB_S + bnc) * 4);
    }

    float acc[4][4][4];
#pragma unroll
    for (int mi = 0; mi < 4; mi++)
#pragma unroll
        for (int ni = 0; ni < 4; ni++)
#pragma unroll
            for (int q = 0; q < 4; q++) acc[mi][ni][q] = 0.f;

    int KT = K / BKK;

#pragma unroll
    for (int p = 0; p < NSTAGE - 1; p++) {
        if (p < KT) {
            int k0 = p * BKK;
            uint32_t sb = sbase + (uint32_t)((p % NSTAGE) * STAGE_FLOATS * 4);
#pragma unroll
            for (int i = 0; i < 4; i++) cp16(sb + aDst[i], aSrc[i] + k0, aSz[i]);
#pragma unroll
            for (int i = 0; i < 4; i++) cp16(sb + bDst[i], bSrc[i] + (size_t)k0 * N, bSz[i]);
            asm volatile("cp.async.commit_group;");
        }
    }

    for (int it = 0; it < KT; it++) {
        if (it + NSTAGE - 1 < KT) {
            int k0 = (it + NSTAGE - 1) * BKK;
            uint32_t sb = sbase + (uint32_t)(((it + NSTAGE - 1) % NSTAGE) * STAGE_FLOATS * 4);
#pragma unroll
            for (int i = 0; i < 4; i++) cp16(sb + aDst[i], aSrc[i] + k0, aSz[i]);
#pragma unroll
            for (int i = 0; i < 4; i++) cp16(sb + bDst[i], bSrc[i] + (size_t)k0 * N, bSz[i]);
            asm volatile("cp.async.commit_group;");
            asm volatile("cp.async.wait_group 1;");
        } else {
            asm volatile("cp.async.wait_group 0;");
        }
        __syncthreads();

        const uint32_t* Ab = (const uint32_t*)(smem_dyn + (size_t)(it % NSTAGE) * STAGE_FLOATS);
        const uint32_t* Bb = Ab + A_STAGE;
#pragma unroll
        for (int ks = 0; ks < 4; ks++) {
            int kb = ks * 8;
            uint32_t af[4][4];
#pragma unroll
            for (int mi = 0; mi < 4; mi++) {
                int r = wm + mi * 16 + grp;
                af[mi][0] = Ab[r * LDA_S + kb + tig];
                af[mi][1] = Ab[(r + 8) * LDA_S + kb + tig];
                af[mi][2] = Ab[r * LDA_S + kb + tig + 4];
                af[mi][3] = Ab[(r + 8) * LDA_S + kb + tig + 4];
            }
            uint32_t bf[4][2];
#pragma unroll
            for (int ni = 0; ni < 4; ni++) {
                int ccol = wn + ni * 8 + grp;
                bf[ni][0] = Bb[(kb + tig) * LDB_S + ccol];
                bf[ni][1] = Bb[(kb + tig + 4) * LDB_S + ccol];
            }
#pragma unroll
            for (int mi = 0; mi < 4; mi++)
#pragma unroll
                for (int ni = 0; ni < 4; ni++)
                    mma_tf32(acc[mi][ni], af[mi], bf[ni]);
        }
        __syncthreads();
    }

    const float* bias = biasBase ? (biasBase + (long long)e * biasStride) : nullptr;
#pragma unroll
    for (int mi = 0; mi < 4; mi++) {
        int rbase = wm + mi * 16 + grp;
#pragma unroll
        for (int half = 0; half < 2; half++) {
            int r = rbase + half * 8;
            int lrow = rowTile * BKM + r;
            if (lrow >= nrows) continue;
            int grow = s0 + lrow;
#pragma unroll
            for (int ni = 0; ni < 4; ni++) {
                int col = colStart + wn + ni * 8 + tig * 2;
                float v0 = acc[mi][ni][half * 2 + 0];
                float v1 = acc[mi][ni][half * 2 + 1];
                if (bias) { v0 += bias[col]; v1 += bias[col + 1]; }
                if (doGelu) {
                    v0 = rtf(gelu_tanh(v0));
                    v1 = rtf(gelu_tanh(v1));
                }
                if (residual) {
                    v0 += residual[(size_t)grow * ldc + col];
                    v1 += residual[(size_t)grow * ldc + col + 1];
                }
                if (col < N)     C[(size_t)grow * ldc + col] = v0;
                if (col + 1 < N) C[(size_t)grow * ldc + col + 1] = v1;
            }
        }
    }
}

// ---------------- rmsnorm (rounded main output; optional full-precision copy) ----------------
__global__ __launch_bounds__(256) void rmsnorm_kernel(
    const float* __restrict__ x, const float* __restrict__ w,
    float* __restrict__ y, float* __restrict__ yfull)
{
    int t = blockIdx.x, tid = threadIdx.x;
    __shared__ float red[256];
    const float* xr = x + (size_t)t * DMODEL;
    float s = 0.f;
    for (int d = tid; d < DMODEL; d += 256) { float v = xr[d]; s += v * v; }
    red[tid] = s; __syncthreads();
    for (int o = 128; o > 0; o >>= 1) { if (tid < o) red[tid] += red[tid + o]; __syncthreads(); }
    float rms = rsqrtf(red[0] / (float)DMODEL + 1e-6f);
    float* yr = y + (size_t)t * DMODEL;
    for (int d = tid; d < DMODEL; d += 256) {
        float v = xr[d] * rms * w[d];
        yr[d] = rtf(v);
        if (yfull) yfull[(size_t)t * DMODEL + d] = v;
    }
}

// ---------------- indexer scores (reads fused proj buffer, stride 324) ----------------
__global__ __launch_bounds__(256) void idx_kernel(
    const float* __restrict__ proj, float* __restrict__ out)
{
    __shared__ float qsh[64][65];
    __shared__ float ksh[64][65];
    __shared__ float hsh[64][4];
    int t0 = blockIdx.y * 64, s0 = blockIdx.x * 64;
    int tid = threadIdx.x;
    const int tr = (tid >> 4) * 4, tc = (tid & 15) * 4;

    hsh[tid >> 2][tid & 3] = proj[(size_t)(t0 + (tid >> 2)) * NPROJ_IDX + 320 + (tid & 3)];
    for (int i = tid; i < 4096; i += 256) {
        int r = i >> 6, c = i & 63;
        ksh[r][c] = proj[(size_t)(s0 + r) * NPROJ_IDX + 256 + c];
    }
    float acc[4][4];
#pragma unroll
    for (int i = 0; i < 4; i++)
#pragma unroll
        for (int j = 0; j < 4; j++) acc[i][j] = 0.f;

    for (int h = 0; h < HIDX; h++) {
        __syncthreads();
        for (int i = tid; i < 4096; i += 256) {
            int r = i >> 6, c = i & 63;
            qsh[r][c] = proj[(size_t)(t0 + r) * NPROJ_IDX + h * DIDX + c];
        }
        __syncthreads();
        float dot[4][4];
#pragma unroll
        for (int i = 0; i < 4; i++)
#pragma unroll
            for (int j = 0; j < 4; j++) dot[i][j] = 0.f;
        for (int kk = 0; kk < 64; kk++) {
            float a[4], b[4];
#pragma unroll
            for (int i = 0; i < 4; i++) a[i] = qsh[tr + i][kk];
#pragma unroll
            for (int j = 0; j < 4; j++) b[j] = ksh[tc + j][kk];
#pragma unroll
            for (int i = 0; i < 4; i++)
#pragma unroll
                for (int j = 0; j < 4; j++) dot[i][j] += a[i] * b[j];
        }
#pragma unroll
        for (int i = 0; i < 4; i++)
#pragma unroll
            for (int j = 0; j < 4; j++)
                acc[i][j] += hsh[tr + i][h] * fmaxf(dot[i][j], 0.f);
    }
#pragma unroll
    for (int i = 0; i < 4; i++)
#pragma unroll
        for (int j = 0; j < 4; j++)
            out[(size_t)(t0 + tr + i) * TSEQ + (s0 + tc + j)] = acc[i][j] * 0.125f;
}

// ---------------- fused top-512 radix-select + mask build ----------------
// One block (512 threads) per query row. Finds the exact 512th-largest
// u64 key (mono(value)<<32 | (2047-i)) via 8-bit radix passes, then builds
// the 64 mask words with ballots. Selection set identical to a full sort.
__global__ __launch_bounds__(512) void topk_mask_kernel(
    const float* __restrict__ idxs, unsigned int* __restrict__ mask)
{
    __shared__ unsigned long long keys[2048];
    __shared__ unsigned int hist[256];
    __shared__ unsigned int sh_k;
    __shared__ unsigned long long sh_prefix;

    int t = blockIdx.x, tid = threadIdx.x;

    for (int i = tid; i < 2048; i += 512) {
        unsigned long long kk = 0ull;
        if (i <= t) {
            float v = idxs[(size_t)t * TSEQ + i];
            kk = ((unsigned long long)fmono(v) << 32) | (unsigned int)(2047 - i);
        }
        keys[i] = kk;
    }
    if (tid == 0) { sh_k = (unsigned int)KSEL; sh_prefix = 0ull; }
    __syncthreads();

    // bits [31:11] of every key are zero, so skip digits at shifts 24/16.
    const int shifts[6] = {56, 48, 40, 32, 8, 0};
    unsigned long long prefix_mask = 0ull;
#pragma unroll
    for (int p = 0; p < 6; p++) {
        int shift = shifts[p];
        if (tid < 256) hist[tid] = 0u;
        __syncthreads();
        unsigned long long pref = sh_prefix;
        for (int i = tid; i < 2048; i += 512) {
            unsigned long long key = keys[i];
            if ((key & prefix_mask) == pref)
                atomicAdd(&hist[(unsigned int)(key >> shift) & 255u], 1u);
        }
        __syncthreads();
        // suffix sums: hist[d] = count of candidates with digit >= d
        for (int off = 1; off < 256; off <<= 1) {
            unsigned int add = 0u;
            if (tid < 256 && tid + off < 256) add = hist[tid + off];
            __syncthreads();
            if (tid < 256) hist[tid] += add;
            __syncthreads();
        }
        unsigned int k = sh_k;
        if (tid < 256) {
            unsigned int s_here = hist[tid];
            unsigned int s_next = (tid == 255) ? 0u : hist[tid + 1];
            if (s_here >= k && s_next < k) {
                sh_prefix = pref | ((unsigned long long)tid << shift);
                sh_k = k - s_next;
            }
        }
        __syncthreads();
        prefix_mask |= (0xFFull << shift);
    }

    unsigned long long thr = sh_prefix;
    int lane = tid & 31, w = tid >> 5;   // 16 warps, 64 mask words
    for (int word = w; word < 64; word += 16) {
        int i = word * 32 + lane;
        bool sel = (i <= t) && (keys[i] >= thr);
        unsigned int bal = __ballot_sync(0xFFFFFFFFu, sel);
        if (lane == 0) mask[t * 64 + word] = bal;
    }
}

// ---------------- RoPE from fused qkv + transpose to [h][t][d], rounds outputs ----------------
__global__ __launch_bounds__(256) void rope_kernel(
    const float* __restrict__ qkv,
    float* __restrict__ qh, float* __restrict__ kh, float* __restrict__ vh)
{
    int idx = blockIdx.x * 256 + threadIdx.x;
    int t = idx >> 10;
    int hd = idx & 1023;
    int h = hd >> 6, d = hd & 63;
    int j = d & 31;
    double invd = exp(-((double)(2 * j) / 64.0) * log(10000.0));
    float ang = (float)((double)t * invd);
    float c = cosf(ang), s = sinf(ang);
    const float* row = qkv + (size_t)t * NPROJ_QKV;
    float q = row[hd], k = row[DMODEL + hd], v = row[2 * DMODEL + hd];
    float qr, kr;
    if (d < 32) {
        qr = q * c - row[hd + 32] * s;
        kr = k * c - row[DMODEL + hd + 32] * s;
    } else {
        qr = q * c + row[hd - 32] * s;
        kr = k * c + row[DMODEL + hd - 32] * s;
    }
    int o = ((h * TSEQ) + t) * HDIM + d;
    qh[o] = rtf(qr); kh[o] = rtf(kr); vh[o] = rtf(v);
}

// ---------------- dense masked flash attention (tf32 mma, pre-rounded inputs) ----------------
// heavy tiles (large qt) scheduled first: qt = gridDim.x-1-blockIdx.x
__global__ void __launch_bounds__(256, 2) attn_flash(
    const float* __restrict__ qh, const float* __restrict__ kh, const float* __restrict__ vh,
    const unsigned int* __restrict__ mask, float* __restrict__ av)
{
    __shared__ float Ks[64][68];
    __shared__ float Vs[64][68];
    __shared__ float Ps[64][68];
    __shared__ float rowM[64], rowL[64], rowScale[64];

    int qt = gridDim.x - 1 - blockIdx.x, h = blockIdx.y;
    int t0 = qt * 64;
    int tid = threadIdx.x;
    int warpId = tid >> 5, lane = tid & 31;
    int grp = lane >> 2, tig = lane & 3;
    int wm = (warpId >> 1) * 16;
    int wn = (warpId & 1) * 32;

    const float* Q0 = qh + ((size_t)h * TSEQ + t0) * HDIM;
    uint32_t qf[8][4];
#pragma unroll
    for (int ks = 0; ks < 8; ks++) {
        int kb = ks * 8;
        qf[ks][0] = __float_as_uint(Q0[(wm + grp) * HDIM + kb + tig]);
        qf[ks][1] = __float_as_uint(Q0[(wm + grp + 8) * HDIM + kb + tig]);
        qf[ks][2] = __float_as_uint(Q0[(wm + grp) * HDIM + kb + tig + 4]);
        qf[ks][3] = __float_as_uint(Q0[(wm + grp + 8) * HDIM + kb + tig + 4]);
    }

    if (tid < 64) { rowM[tid] = -INFINITY; rowL[tid] = 0.f; }

    float oacc[4][4];
#pragma unroll
    for (int ni = 0; ni < 4; ni++)
#pragma unroll
        for (int q = 0; q < 4; q++) oacc[ni][q] = 0.f;

    const float* Kb = kh + (size_t)h * TSEQ * HDIM;
    const float* Vb = vh + (size_t)h * TSEQ * HDIM;

    for (int kt = 0; kt <= qt; kt++) {
        __syncthreads();
        for (int i = tid; i < 1024; i += 256) {
            int row = i >> 4, c4 = (i & 15) * 4;
            *(float4*)&Ks[row][c4] = *(const float4*)(Kb + (size_t)(kt * 64 + row) * HDIM + c4);
            *(float4*)&Vs[row][c4] = *(const float4*)(Vb + (size_t)(kt * 64 + row) * HDIM + c4);
        }
        __syncthreads();

        float sacc[4][4];
#pragma unroll
        for (int ni = 0; ni < 4; ni++)
#pragma unroll
            for (int q = 0; q < 4; q++) sacc[ni][q] = 0.f;
#pragma unroll
        for (int ks = 0; ks < 8; ks++) {
            int kb = ks * 8;
#pragma unroll
            for (int ni = 0; ni < 4; ni++) {
                int n = wn + ni * 8 + grp;
                uint32_t bf[2];
                bf[0] = __float_as_uint(Ks[n][kb + tig]);
                bf[1] = __float_as_uint(Ks[n][kb + tig + 4]);
                mma_tf32(sacc[ni], qf[ks], bf);
            }
        }

        int r0 = wm + grp, r1 = wm + grp + 8;
        unsigned int mw0 = mask[(t0 + r0) * 64 + kt * 2 + (wn >> 5)];
        unsigned int mw1 = mask[(t0 + r1) * 64 + kt * 2 + (wn >> 5)];
#pragma unroll
        for (int ni = 0; ni < 4; ni++) {
            int c = wn + ni * 8 + tig * 2;
            int b = ni * 8 + tig * 2;
            Ps[r0][c]     = ((mw0 >> b) & 1u)       ? sacc[ni][0] * 0.125f : -INFINITY;
            Ps[r0][c + 1] = ((mw0 >> (b + 1)) & 1u) ? sacc[ni][1] * 0.125f : -INFINITY;
            Ps[r1][c]     = ((mw1 >> b) & 1u)       ? sacc[ni][2] * 0.125f : -INFINITY;
            Ps[r1][c + 1] = ((mw1 >> (b + 1)) & 1u) ? sacc[ni][3] * 0.125f : -INFINITY;
        }
        __syncthreads();

        {
            int row = tid >> 2, seg = tid & 3;
            float m_old = rowM[row];
            float tmax = -INFINITY;
#pragma unroll
            for (int j = 0; j < 16; j++) tmax = fmaxf(tmax, Ps[row][seg * 16 + j]);
            tmax = fmaxf(tmax, __shfl_xor_sync(0xFFFFFFFFu, tmax, 1));
            tmax = fmaxf(tmax, __shfl_xor_sync(0xFFFFFFFFu, tmax, 2));
            float mnew = fmaxf(m_old, tmax);
            bool inval = (mnew == -INFINITY);
            float tsum = 0.f;
#pragma unroll
            for (int j = 0; j < 16; j++) {
                float v = Ps[row][seg * 16 + j];
                float p = inval ? 0.f : expf(v - mnew);
                Ps[row][seg * 16 + j] = rtf(p);
                tsum += p;
            }
            tsum += __shfl_xor_sync(0xFFFFFFFFu, tsum, 1);
            tsum += __shfl_xor_sync(0xFFFFFFFFu, tsum, 2);
            if (seg == 0) {
                float sc = inval ? 1.f : expf(m_old - mnew);
                rowScale[row] = sc;
                rowM[row] = mnew;
                rowL[row] = rowL[row] * sc + tsum;
            }
        }
        __syncthreads();

        float s0 = rowScale[wm + grp], s1 = rowScale[wm + grp + 8];
#pragma unroll
        for (int ni = 0; ni < 4; ni++) {
            oacc[ni][0] *= s0; oacc[ni][1] *= s0;
            oacc[ni][2] *= s1; oacc[ni][3] *= s1;
        }
#pragma unroll
        for (int ks = 0; ks < 8; ks++) {
            int kb = ks * 8;
            uint32_t pa[4];
            pa[0] = __float_as_uint(Ps[wm + grp][kb + tig]);
            pa[1] = __float_as_uint(Ps[wm + grp + 8][kb + tig]);
            pa[2] = __float_as_uint(Ps[wm + grp][kb + tig + 4]);
            pa[3] = __float_as_uint(Ps[wm + grp + 8][kb + tig + 4]);
#pragma unroll
            for (int ni = 0; ni < 4; ni++) {
                int n = wn + ni * 8 + grp;
                uint32_t vf[2];
                vf[0] = __float_as_uint(Vs[kb + tig][n]);
                vf[1] = __float_as_uint(Vs[kb + tig + 4][n]);
                mma_tf32(oacc[ni], pa, vf);
            }
        }
    }
    __syncthreads();

    float i0 = 1.f / rowL[wm + grp];
    float i1 = 1.f / rowL[wm + grp + 8];
#pragma unroll
    for (int ni = 0; ni < 4; ni++) {
        int c = wn + ni * 8 + tig * 2;
        size_t o0 = (size_t)(t0 + wm + grp) * DMODEL + h * HDIM + c;
        size_t o1 = (size_t)(t0 + wm + grp + 8) * DMODEL + h * HDIM + c;
        av[o0]     = rtf(oacc[ni][0] * i0);
        av[o0 + 1] = rtf(oacc[ni][1] * i0);
        av[o1]     = rtf(oacc[ni][2] * i1);
        av[o1 + 1] = rtf(oacc[ni][3] * i1);
    }
}

// ---------------- router (reads FULL-precision x2n) ----------------
__global__ __launch_bounds__(256) void router_kernel(
    const float* __restrict__ x2n, const float* __restrict__ rw, const float* __restrict__ rb,
    float* __restrict__ probs, int* __restrict__ topE, float* __restrict__ topG)
{
    int t = blockIdx.x, tid = threadIdx.x;
    __shared__ float red[256];
    __shared__ float lg[8];
    float acc[8];
#pragma unroll
    for (int e = 0; e < 8; e++) acc[e] = 0.f;
    const float* xr = x2n + (size_t)t * DMODEL;
    for (int d = tid; d < DMODEL; d += 256) {
        float xv = xr[d];
#pragma unroll
        for (int e = 0; e < 8; e++) acc[e] += xv * rw[(size_t)d * NEXP + e];
    }
    for (int e = 0; e < 8; e++) {
        red[tid] = acc[e]; __syncthreads();
        for (int o = 128; o > 0; o >>= 1) { if (tid < o) red[tid] += red[tid + o]; __syncthreads(); }
        if (tid == 0) lg[e] = red[0] + rb[e];
        __syncthreads();
    }
    if (tid == 0) {
        float m = lg[0];
        for (int e = 1; e < 8; e++) m = fmaxf(m, lg[e]);
        float p[8], s = 0.f;
        for (int e = 0; e < 8; e++) { p[e] = expf(lg[e] - m); s += p[e]; }
        for (int e = 0; e < 8; e++) p[e] /= s;
        int e0 = 0;
        for (int e = 1; e < 8; e++) if (p[e] > p[e0]) e0 = e;
        int e1 = -1;
        for (int e = 0; e < 8; e++) if (e != e0 && (e1 < 0 || p[e] > p[e1])) e1 = e;
        float denom = p[e0] + p[e1];
        for (int e = 0; e < 8; e++) probs[(size_t)t * NEXP + e] = p[e];
        topE[t * 2 + 0] = e0; topE[t * 2 + 1] = e1;
        topG[t * 2 + 0] = p[e0] / denom; topG[t * 2 + 1] = p[e1] / denom;
    }
}

// ---------------- deterministic grouping (smem staged) ----------------
__global__ __launch_bounds__(256) void group_kernel(
    const int* __restrict__ topE, int* __restrict__ counts,
    int* __restrict__ segoff, int* __restrict__ rowmap,
    int* __restrict__ slotpos)
{
    __shared__ short sE[TSEQ * 2];
    __shared__ int sSeg[NEXP + 1];
    int tid = threadIdx.x;
    for (int i = tid; i < TSEQ * 2; i += 256) sE[i] = (short)topE[i];
    __syncthreads();
    if (tid < 8) {
        int e = tid;
        int c = 0;
        for (int i = 0; i < TSEQ * 2; i++) c += (sE[i] == e);
        counts[e] = c;
        sSeg[e] = c;
    }
    __syncthreads();
    if (tid == 0) {
        int o = 0;
        for (int i = 0; i < 8; i++) { int c = sSeg[i]; sSeg[i] = o; segoff[i] = o; o += c; }
        sSeg[8] = o; segoff[8] = o;
    }
    __syncthreads();
    if (tid < 8) {
        int e = tid;
        int pos = sSeg[e];
        for (int i = 0; i < TSEQ * 2; i++) {
            if (sE[i] == e) {
                rowmap[pos] = i >> 1;
                slotpos[i] = pos;
                pos++;
            }
        }
    }
}

// ---------------- aux loss ----------------
__global__ __launch_bounds__(256) void aux_kernel(
    const float* __restrict__ probs, const int* __restrict__ counts, float* __restrict__ outAux)
{
    __shared__ float red[256];
    int tid = threadIdx.x;
    float a = 0.f;
    for (int e = 0; e < 8; e++) {
        float s = 0.f;
        for (int t = tid; t < TSEQ; t += 256) s += probs[(size_t)t * NEXP + e];
        red[tid] = s; __syncthreads();
        for (int o = 128; o > 0; o >>= 1) { if (tid < o) red[tid] += red[tid + o]; __syncthreads(); }
        if (tid == 0) a += (float)counts[e] * red[0];
        __syncthreads();
    }
    if (tid == 0) *outAux = 8.f * a / ((float)TSEQ * (float)TSEQ);
}

// ---------------- final combine ----------------
__global__ __launch_bounds__(256) void combine_kernel(
    const float* __restrict__ x1, const float* __restrict__ y,
    const int* __restrict__ slotpos, const float* __restrict__ topG,
    float* __restrict__ out)
{
    int idx = blockIdx.x * 256 + threadIdx.x;
    int t = idx >> 10, d = idx & 1023;
    int p0 = slotpos[t * 2 + 0], p1 = slotpos[t * 2 + 1];
    float g0 = topG[t * 2 + 0], g1 = topG[t * 2 + 1];
    out[idx] = x1[idx] + g0 * y[(size_t)p0 * DMODEL + d] + g1 * y[(size_t)p1 * DMODEL + d];
}

// ---------------- host launch ----------------
#define GETSYM(ptr, sym) do { void* _p_; cudaGetSymbolAddress(&_p_, sym); ptr = (decltype(ptr))_p_; } while (0)

extern "C" void kernel_launch(void* const* d_in, const int* in_sizes, int n_in,
                              void* d_out, int out_size)
{
    const float* x        = (const float*)d_in[0];
    const float* norm1_w  = (const float*)d_in[1];
    const float* norm2_w  = (const float*)d_in[2];
    const float* wq_idx   = (const float*)d_in[3];
    const float* wk_idx   = (const float*)d_in[4];
    const float* w_head   = (const float*)d_in[5];
    const float* wq       = (const float*)d_in[6];
    const float* wk       = (const float*)d_in[7];
    const float* wv       = (const float*)d_in[8];
    const float* wo       = (const float*)d_in[9];
    const float* router_w = (const float*)d_in[10];
    const float* router_b = (const float*)d_in[11];
    const float* w1       = (const float*)d_in[12];
    const float* b1       = (const float*)d_in[13];
    const float* w2       = (const float*)d_in[14];
    const float* b2       = (const float*)d_in[15];

    float* out    = (float*)d_out;
    float* auxp   = out + (size_t)TSEQ * DMODEL;
    float* idxout = auxp + 1;

    float *p_xn, *p_proj, *p_qkv, *p_qh, *p_kh, *p_vh;
    float *p_av, *p_x1, *p_x2n, *p_x2f, *p_probs, *p_topG, *p_mid, *p_y;
    float *p_w1c, *p_w2c, *p_woc, *p_wqkvc, *p_widxc;
    int *p_topE, *p_counts, *p_segoff, *p_rowmap, *p_slotpos;
    unsigned int *p_mask;
    GETSYM(p_xn, g_xn); GETSYM(p_proj, g_proj_idx); GETSYM(p_qkv, g_qkv);
    GETSYM(p_qh, g_qh); GETSYM(p_kh, g_kh); GETSYM(p_vh, g_vh);
    GETSYM(p_av, g_av); GETSYM(p_x1, g_x1);
    GETSYM(p_x2n, g_x2n); GETSYM(p_x2f, g_x2f);
    GETSYM(p_probs, g_probs); GETSYM(p_topE, g_topE); GETSYM(p_topG, g_topG);
    GETSYM(p_counts, g_counts); GETSYM(p_segoff, g_segoff);
    GETSYM(p_rowmap, g_rowmap); GETSYM(p_slotpos, g_slotpos);
    GETSYM(p_mid, g_mid); GETSYM(p_y, g_yy); GETSYM(p_mask, g_mask);
    GETSYM(p_w1c, g_w1c); GETSYM(p_w2c, g_w2c); GETSYM(p_woc, g_woc);
    GETSYM(p_wqkvc, g_wqkvc); GETSYM(p_widxc, g_widxc);

    cudaFuncSetAttribute(tgemm, cudaFuncAttributeMaxDynamicSharedMemorySize, TG_SMEM_BYTES);

    // 0. weight rounding / packing
    {
        int n4 = NEXP * DMODEL * DFFN / 4;
        round4_kernel<<<(n4 + 255) / 256, 256>>>((const float4*)w1, (float4*)p_w1c, n4);
        round4_kernel<<<(n4 + 255) / 256, 256>>>((const float4*)w2, (float4*)p_w2c, n4);
        int m4 = DMODEL * DMODEL / 4;
        round4_kernel<<<(m4 + 255) / 256, 256>>>((const float4*)wo, (float4*)p_woc, m4);
        pack_qkv_kernel<<<(DMODEL * DMODEL) / 256, 256>>>(wq, wk, wv, p_wqkvc);
        pack_idx_kernel<<<(DMODEL * NPROJ_IDX + 255) / 256, 256>>>(wq_idx, wk_idx, w_head, p_widxc);
    }

    // 1. norm1
    rmsnorm_kernel<<<TSEQ, 256>>>(x, norm1_w, p_xn, nullptr);

    // 2. fused projections
    tgemm<<<dim3((NPROJ_IDX + 127) / 128, 16, 1), 256, TG_SMEM_BYTES>>>(
        p_xn, DMODEL, nullptr, p_widxc, 0, nullptr, 0,
        nullptr, p_proj, NPROJ_IDX, nullptr, TSEQ, NPROJ_IDX, DMODEL, 0);
    tgemm<<<dim3(NPROJ_QKV / 128, 16, 1), 256, TG_SMEM_BYTES>>>(
        p_xn, DMODEL, nullptr, p_wqkvc, 0, nullptr, 0,
        nullptr, p_qkv, NPROJ_QKV, nullptr, TSEQ, NPROJ_QKV, DMODEL, 0);

    // 3. indexer scores + fused top-512 mask
    idx_kernel<<<dim3(32, 32), 256>>>(p_proj, idxout);
    topk_mask_kernel<<<TSEQ, 512>>>(idxout, p_mask);

    // 4. rope + transpose
    rope_kernel<<<(TSEQ * DMODEL) / 256, 256>>>(p_qkv, p_qh, p_kh, p_vh);

    // 5. dense masked flash attention (heavy tiles first)
    attn_flash<<<dim3(TSEQ / 64, NHEAD), 256>>>(p_qh, p_kh, p_vh, p_mask, p_av);

    // 6. output projection + residual
    tgemm<<<dim3(8, 16, 1), 256, TG_SMEM_BYTES>>>(p_av, DMODEL, nullptr, p_woc, 0, nullptr, 0,
        x, p_x1, DMODEL, nullptr, TSEQ, DMODEL, DMODEL, 0);

    // 7. norm2 + router + grouping + aux
    rmsnorm_kernel<<<TSEQ, 256>>>(p_x1, norm2_w, p_x2n, p_x2f);
    router_kernel<<<TSEQ, 256>>>(p_x2f, router_w, router_b, p_probs, p_topE, p_topG);
    group_kernel<<<1, 256>>>(p_topE, p_counts, p_segoff, p_rowmap, p_slotpos);
    aux_kernel<<<1, 256>>>(p_probs, p_counts, auxp);

    // 8. MoE grouped GEMMs
    tgemm<<<dim3(DFFN / 128, 16, NEXP), 256, TG_SMEM_BYTES>>>(
        p_x2n, DMODEL, p_rowmap, p_w1c, (long long)DMODEL * DFFN, b1, DFFN,
        nullptr, p_mid, DFFN, p_segoff, 0, DFFN, DMODEL, 1);
    tgemm<<<dim3(DMODEL / 128, 16, NEXP), 256, TG_SMEM_BYTES>>>(
        p_mid, DFFN, nullptr, p_w2c, (long long)DFFN * DMODEL, b2, DMODEL,
        nullptr, p_y, DMODEL, p_segoff, 0, DMODEL, DFFN, 0);

    // 9. combine
    combine_kernel<<<(TSEQ * DMODEL) / 256, 256>>>(p_x1, p_y, p_slotpos, p_topG, out);
}

// round 7
// speedup vs baseline: 3.4453x; 1.0299x over previous
#include <cuda_runtime.h>
#include <math.h>
#include <stdint.h>

// ---------------- constants ----------------
static const int TSEQ = 2048;
static const int DMODEL = 1024;
static const int NHEAD = 16;
static const int HDIM = 64;
static const int DFFN = 4096;
static const int NEXP = 8;
static const int HIDX = 4;
static const int DIDX = 64;
static const int KSEL = 512;
static const int NPROJ_IDX = HIDX * DIDX + DIDX + HIDX;  // 324
static const int NPROJ_QKV = 3 * DMODEL;                 // 3072

// ---------------- device scratch ----------------
__device__ float g_xn[TSEQ * DMODEL];
__device__ float g_proj_idx[TSEQ * NPROJ_IDX];
__device__ float g_qkv[TSEQ * NPROJ_QKV];
__device__ float g_qh[TSEQ * DMODEL];
__device__ float g_kh[TSEQ * DMODEL];
__device__ float g_vh[TSEQ * DMODEL];
__device__ float g_av[TSEQ * DMODEL];
__device__ float g_x1[TSEQ * DMODEL];
__device__ float g_x2n[TSEQ * DMODEL];   // tf32-rounded (GEMM operand)
__device__ float g_x2f[TSEQ * DMODEL];   // full fp32 (router input)
__device__ float g_probs[TSEQ * NEXP];
__device__ int   g_topE[TSEQ * 2];
__device__ float g_topG[TSEQ * 2];
__device__ int   g_counts[NEXP];
__device__ int   g_segoff[NEXP + 1];
__device__ int   g_rowmap[TSEQ * 2];
__device__ int   g_slotpos[TSEQ * 2];
__device__ float g_mid[(size_t)(TSEQ * 2) * DFFN];
__device__ float g_yy[(size_t)(TSEQ * 2) * DMODEL];
__device__ unsigned int g_mask[TSEQ * (TSEQ / 32)];
// tf32-rounded weight copies
__device__ float g_w1c[(size_t)NEXP * DMODEL * DFFN];
__device__ float g_w2c[(size_t)NEXP * DFFN * DMODEL];
__device__ float g_woc[DMODEL * DMODEL];
__device__ float g_wqkvc[DMODEL * NPROJ_QKV];
__device__ float g_widxc[DMODEL * NPROJ_IDX];

// ---------------- helpers ----------------
__device__ __forceinline__ float gelu_tanh(float x) {
    float x3 = x * x * x;
    float u = 0.7978845608028654f * (x + 0.044715f * x3);
    return 0.5f * x * (1.0f + tanhf(u));
}

__device__ __forceinline__ unsigned int fmono(float f) {
    unsigned int u = __float_as_uint(f);
    return (u & 0x80000000u) ? ~u : (u | 0x80000000u);
}

__device__ __forceinline__ uint32_t f2tf32(float f) {
    uint32_t r;
    asm("cvt.rna.tf32.f32 %0, %1;" : "=r"(r) : "f"(f));
    return r;
}
__device__ __forceinline__ float rtf(float f) { return __uint_as_float(f2tf32(f)); }

__device__ __forceinline__ void cp16(uint32_t dst, const float* src, int sz) {
    asm volatile("cp.async.cg.shared.global [%0], [%1], 16, %2;" :: "r"(dst), "l"(src), "r"(sz));
}

__device__ __forceinline__ void mma_tf32(float* c, const uint32_t* a, const uint32_t* b) {
    asm volatile(
        "mma.sync.aligned.m16n8k8.row.col.f32.tf32.tf32.f32 "
        "{%0,%1,%2,%3}, {%4,%5,%6,%7}, {%8,%9}, {%0,%1,%2,%3};"
        : "+f"(c[0]), "+f"(c[1]), "+f"(c[2]), "+f"(c[3])
        : "r"(a[0]), "r"(a[1]), "r"(a[2]), "r"(a[3]), "r"(b[0]), "r"(b[1]));
}

// ---------------- weight conversion / packing ----------------
__global__ __launch_bounds__(256) void round4_kernel(
    const float4* __restrict__ in, float4* __restrict__ out, int n4)
{
    int i = blockIdx.x * 256 + threadIdx.x;
    if (i < n4) {
        float4 v = in[i];
        v.x = rtf(v.x); v.y = rtf(v.y); v.z = rtf(v.z); v.w = rtf(v.w);
        out[i] = v;
    }
}

__global__ __launch_bounds__(256) void pack_qkv_kernel(
    const float* __restrict__ wq, const float* __restrict__ wk, const float* __restrict__ wv,
    float* __restrict__ out)
{
    int i = blockIdx.x * 256 + threadIdx.x;  // over 1024*1024
    int d = i >> 10, c = i & 1023;
    out[(size_t)d * NPROJ_QKV + c] = rtf(wq[i]);
    out[(size_t)d * NPROJ_QKV + DMODEL + c] = rtf(wk[i]);
    out[(size_t)d * NPROJ_QKV + 2 * DMODEL + c] = rtf(wv[i]);
}

__global__ __launch_bounds__(256) void pack_idx_kernel(
    const float* __restrict__ wq_idx, const float* __restrict__ wk_idx,
    const float* __restrict__ w_head, float* __restrict__ out)
{
    int i = blockIdx.x * 256 + threadIdx.x;  // over 1024*324
    if (i >= DMODEL * NPROJ_IDX) return;
    int d = i / NPROJ_IDX, j = i - d * NPROJ_IDX;
    float v;
    if (j < 256) v = wq_idx[d * 256 + j];
    else if (j < 320) v = wk_idx[d * 64 + (j - 256)];
    else v = w_head[d * 4 + (j - 320)];
    out[i] = rtf(v);
}

// ---------------- unified tf32 tensor GEMM (3-stage cp.async, 2 CTAs/SM) ----------------
#define BKM 128
#define BKN 128
#define BKK 32
#define LDA_S 36
#define LDB_S 132
#define A_STAGE (BKM * LDA_S)
#define B_STAGE (BKK * LDB_S)
#define STAGE_FLOATS (A_STAGE + B_STAGE)
#define NSTAGE 3
#define TG_SMEM_BYTES (NSTAGE * STAGE_FLOATS * 4)

extern __shared__ float smem_dyn[];

__global__ void __launch_bounds__(256, 2) tgemm(
    const float* __restrict__ A, int lda,
    const int* __restrict__ rowmap,
    const float* __restrict__ Bbase, long long strideB,
    const float* __restrict__ biasBase, int biasStride,
    const float* __restrict__ residual,
    float* __restrict__ C, int ldc,
    const int* __restrict__ segoff,
    int M, int N, int K, int doGelu)
{
    int e = blockIdx.z;
    int s0 = 0, nrows = M;
    if (segoff) { s0 = segoff[e]; nrows = segoff[e + 1] - s0; }
    int rowTile = blockIdx.y;
    if (rowTile * BKM >= nrows) return;
    int colStart = blockIdx.x * BKN;
    const float* B = Bbase + (long long)e * strideB;

    int tid = threadIdx.x;
    int warpId = tid >> 5, lane = tid & 31;
    int grp = lane >> 2, tig = lane & 3;
    int wm = (warpId >> 2) * 64;
    int wn = (warpId & 3) * 32;

    uint32_t sbase = (uint32_t)__cvta_generic_to_shared(smem_dyn);

    const float* aSrc[4]; int aSz[4]; uint32_t aDst[4];
    const float* bSrc[4]; int bSz[4]; uint32_t bDst[4];
#pragma unroll
    for (int i = 0; i < 4; i++) {
        int c = tid + i * 256;
        int arow = c >> 3, akc = (c & 7) * 4;
        int lrow = rowTile * BKM + arow;
        bool v = lrow < nrows;
        int gidx = 0;
        if (v) {
            int base = s0 + lrow;
            gidx = rowmap ? rowmap[base] : base;
        }
        aSrc[i] = A + (size_t)gidx * lda + akc;
        aSz[i] = v ? 16 : 0;
        aDst[i] = (uint32_t)((arow * LDA_S + akc) * 4);

        int brow = c >> 5, bnc = (c & 31) * 4;
        int col = colStart + bnc;
        bool bv = (col + 4 <= N);
        bSz[i] = bv ? 16 : 0;
        bSrc[i] = B + (size_t)brow * N + (bv ? col : 0);
        bDst[i] = (uint32_t)((A_STAGE + brow * LDB_S + bnc) * 4);
    }

    float acc[4][4][4];
#pragma unroll
    for (int mi = 0; mi < 4; mi++)
#pragma unroll
        for (int ni = 0; ni < 4; ni++)
#pragma unroll
            for (int q = 0; q < 4; q++) acc[mi][ni][q] = 0.f;

    int KT = K / BKK;

#pragma unroll
    for (int p = 0; p < NSTAGE - 1; p++) {
        if (p < KT) {
            int k0 = p * BKK;
            uint32_t sb = sbase + (uint32_t)((p % NSTAGE) * STAGE_FLOATS * 4);
#pragma unroll
            for (int i = 0; i < 4; i++) cp16(sb + aDst[i], aSrc[i] + k0, aSz[i]);
#pragma unroll
            for (int i = 0; i < 4; i++) cp16(sb + bDst[i], bSrc[i] + (size_t)k0 * N, bSz[i]);
            asm volatile("cp.async.commit_group;");
        }
    }

    for (int it = 0; it < KT; it++) {
        if (it + NSTAGE - 1 < KT) {
            int k0 = (it + NSTAGE - 1) * BKK;
            uint32_t sb = sbase + (uint32_t)(((it + NSTAGE - 1) % NSTAGE) * STAGE_FLOATS * 4);
#pragma unroll
            for (int i = 0; i < 4; i++) cp16(sb + aDst[i], aSrc[i] + k0, aSz[i]);
#pragma unroll
            for (int i = 0; i < 4; i++) cp16(sb + bDst[i], bSrc[i] + (size_t)k0 * N, bSz[i]);
            asm volatile("cp.async.commit_group;");
        }
        int pend = KT - 1 - it;
        if (pend > NSTAGE - 1) pend = NSTAGE - 1;
        if (pend >= 2)      asm volatile("cp.async.wait_group 2;");
        else if (pend == 1) asm volatile("cp.async.wait_group 1;");
        else                asm volatile("cp.async.wait_group 0;");
        __syncthreads();

        const uint32_t* Ab = (const uint32_t*)(smem_dyn + (size_t)(it % NSTAGE) * STAGE_FLOATS);
        const uint32_t* Bb = Ab + A_STAGE;
#pragma unroll
        for (int ks = 0; ks < 4; ks++) {
            int kb = ks * 8;
            uint32_t af[4][4];
#pragma unroll
            for (int mi = 0; mi < 4; mi++) {
                int r = wm + mi * 16 + grp;
                af[mi][0] = Ab[r * LDA_S + kb + tig];
                af[mi][1] = Ab[(r + 8) * LDA_S + kb + tig];
                af[mi][2] = Ab[r * LDA_S + kb + tig + 4];
                af[mi][3] = Ab[(r + 8) * LDA_S + kb + tig + 4];
            }
            uint32_t bf[4][2];
#pragma unroll
            for (int ni = 0; ni < 4; ni++) {
                int ccol = wn + ni * 8 + grp;
                bf[ni][0] = Bb[(kb + tig) * LDB_S + ccol];
                bf[ni][1] = Bb[(kb + tig + 4) * LDB_S + ccol];
            }
#pragma unroll
            for (int mi = 0; mi < 4; mi++)
#pragma unroll
                for (int ni = 0; ni < 4; ni++)
                    mma_tf32(acc[mi][ni], af[mi], bf[ni]);
        }
        __syncthreads();
    }

    const float* bias = biasBase ? (biasBase + (long long)e * biasStride) : nullptr;
#pragma unroll
    for (int mi = 0; mi < 4; mi++) {
        int rbase = wm + mi * 16 + grp;
#pragma unroll
        for (int half = 0; half < 2; half++) {
            int r = rbase + half * 8;
            int lrow = rowTile * BKM + r;
            if (lrow >= nrows) continue;
            int grow = s0 + lrow;
#pragma unroll
            for (int ni = 0; ni < 4; ni++) {
                int col = colStart + wn + ni * 8 + tig * 2;
                float v0 = acc[mi][ni][half * 2 + 0];
                float v1 = acc[mi][ni][half * 2 + 1];
                if (bias) { v0 += bias[col]; v1 += bias[col + 1]; }
                if (doGelu) {
                    v0 = rtf(gelu_tanh(v0));
                    v1 = rtf(gelu_tanh(v1));
                }
                if (residual) {
                    v0 += residual[(size_t)grow * ldc + col];
                    v1 += residual[(size_t)grow * ldc + col + 1];
                }
                if (col < N)     C[(size_t)grow * ldc + col] = v0;
                if (col + 1 < N) C[(size_t)grow * ldc + col + 1] = v1;
            }
        }
    }
}

// ---------------- rmsnorm (rounded main output; optional full-precision copy) ----------------
__global__ __launch_bounds__(256) void rmsnorm_kernel(
    const float* __restrict__ x, const float* __restrict__ w,
    float* __restrict__ y, float* __restrict__ yfull)
{
    int t = blockIdx.x, tid = threadIdx.x;
    __shared__ float red[256];
    const float* xr = x + (size_t)t * DMODEL;
    float s = 0.f;
    for (int d = tid; d < DMODEL; d += 256) { float v = xr[d]; s += v * v; }
    red[tid] = s; __syncthreads();
    for (int o = 128; o > 0; o >>= 1) { if (tid < o) red[tid] += red[tid + o]; __syncthreads(); }
    float rms = rsqrtf(red[0] / (float)DMODEL + 1e-6f);
    float* yr = y + (size_t)t * DMODEL;
    for (int d = tid; d < DMODEL; d += 256) {
        float v = xr[d] * rms * w[d];
        yr[d] = rtf(v);
        if (yfull) yfull[(size_t)t * DMODEL + d] = v;
    }
}

// ---------------- indexer scores (reads fused proj buffer, stride 324) ----------------
__global__ __launch_bounds__(256) void idx_kernel(
    const float* __restrict__ proj, float* __restrict__ out)
{
    __shared__ float qsh[64][65];
    __shared__ float ksh[64][65];
    __shared__ float hsh[64][4];
    int t0 = blockIdx.y * 64, s0 = blockIdx.x * 64;
    int tid = threadIdx.x;
    const int tr = (tid >> 4) * 4, tc = (tid & 15) * 4;

    hsh[tid >> 2][tid & 3] = proj[(size_t)(t0 + (tid >> 2)) * NPROJ_IDX + 320 + (tid & 3)];
    for (int i = tid; i < 4096; i += 256) {
        int r = i >> 6, c = i & 63;
        ksh[r][c] = proj[(size_t)(s0 + r) * NPROJ_IDX + 256 + c];
    }
    float acc[4][4];
#pragma unroll
    for (int i = 0; i < 4; i++)
#pragma unroll
        for (int j = 0; j < 4; j++) acc[i][j] = 0.f;

    for (int h = 0; h < HIDX; h++) {
        __syncthreads();
        for (int i = tid; i < 4096; i += 256) {
            int r = i >> 6, c = i & 63;
            qsh[r][c] = proj[(size_t)(t0 + r) * NPROJ_IDX + h * DIDX + c];
        }
        __syncthreads();
        float dot[4][4];
#pragma unroll
        for (int i = 0; i < 4; i++)
#pragma unroll
            for (int j = 0; j < 4; j++) dot[i][j] = 0.f;
        for (int kk = 0; kk < 64; kk++) {
            float a[4], b[4];
#pragma unroll
            for (int i = 0; i < 4; i++) a[i] = qsh[tr + i][kk];
#pragma unroll
            for (int j = 0; j < 4; j++) b[j] = ksh[tc + j][kk];
#pragma unroll
            for (int i = 0; i < 4; i++)
#pragma unroll
                for (int j = 0; j < 4; j++) dot[i][j] += a[i] * b[j];
        }
#pragma unroll
        for (int i = 0; i < 4; i++)
#pragma unroll
            for (int j = 0; j < 4; j++)
                acc[i][j] += hsh[tr + i][h] * fmaxf(dot[i][j], 0.f);
    }
#pragma unroll
    for (int i = 0; i < 4; i++)
#pragma unroll
        for (int j = 0; j < 4; j++)
            out[(size_t)(t0 + tr + i) * TSEQ + (s0 + tc + j)] = acc[i][j] * 0.125f;
}

// ---------------- fused top-512 radix-select + mask build ----------------
__global__ __launch_bounds__(512) void topk_mask_kernel(
    const float* __restrict__ idxs, unsigned int* __restrict__ mask)
{
    __shared__ unsigned long long keys[2048];
    __shared__ unsigned int hist[256];
    __shared__ unsigned int sh_k;
    __shared__ unsigned long long sh_prefix;

    int t = blockIdx.x, tid = threadIdx.x;

    for (int i = tid; i < 2048; i += 512) {
        unsigned long long kk = 0ull;
        if (i <= t) {
            float v = idxs[(size_t)t * TSEQ + i];
            kk = ((unsigned long long)fmono(v) << 32) | (unsigned int)(2047 - i);
        }
        keys[i] = kk;
    }
    if (tid == 0) { sh_k = (unsigned int)KSEL; sh_prefix = 0ull; }
    __syncthreads();

    const int shifts[6] = {56, 48, 40, 32, 8, 0};
    unsigned long long prefix_mask = 0ull;
#pragma unroll
    for (int p = 0; p < 6; p++) {
        int shift = shifts[p];
        if (tid < 256) hist[tid] = 0u;
        __syncthreads();
        unsigned long long pref = sh_prefix;
        for (int i = tid; i < 2048; i += 512) {
            unsigned long long key = keys[i];
            if ((key & prefix_mask) == pref)
                atomicAdd(&hist[(unsigned int)(key >> shift) & 255u], 1u);
        }
        __syncthreads();
        for (int off = 1; off < 256; off <<= 1) {
            unsigned int add = 0u;
            if (tid < 256 && tid + off < 256) add = hist[tid + off];
            __syncthreads();
            if (tid < 256) hist[tid] += add;
            __syncthreads();
        }
        unsigned int k = sh_k;
        if (tid < 256) {
            unsigned int s_here = hist[tid];
            unsigned int s_next = (tid == 255) ? 0u : hist[tid + 1];
            if (s_here >= k && s_next < k) {
                sh_prefix = pref | ((unsigned long long)tid << shift);
                sh_k = k - s_next;
            }
        }
        __syncthreads();
        prefix_mask |= (0xFFull << shift);
    }

    unsigned long long thr = sh_prefix;
    int lane = tid & 31, w = tid >> 5;
    for (int word = w; word < 64; word += 16) {
        int i = word * 32 + lane;
        bool sel = (i <= t) && (keys[i] >= thr);
        unsigned int bal = __ballot_sync(0xFFFFFFFFu, sel);
        if (lane == 0) mask[t * 64 + word] = bal;
    }
}

// ---------------- RoPE from fused qkv + transpose to [h][t][d], rounds outputs ----------------
__global__ __launch_bounds__(256) void rope_kernel(
    const float* __restrict__ qkv,
    float* __restrict__ qh, float* __restrict__ kh, float* __restrict__ vh)
{
    int idx = blockIdx.x * 256 + threadIdx.x;
    int t = idx >> 10;
    int hd = idx & 1023;
    int h = hd >> 6, d = hd & 63;
    int j = d & 31;
    double invd = exp(-((double)(2 * j) / 64.0) * log(10000.0));
    float ang = (float)((double)t * invd);
    float c = cosf(ang), s = sinf(ang);
    const float* row = qkv + (size_t)t * NPROJ_QKV;
    float q = row[hd], k = row[DMODEL + hd], v = row[2 * DMODEL + hd];
    float qr, kr;
    if (d < 32) {
        qr = q * c - row[hd + 32] * s;
        kr = k * c - row[DMODEL + hd + 32] * s;
    } else {
        qr = q * c + row[hd - 32] * s;
        kr = k * c + row[DMODEL + hd - 32] * s;
    }
    int o = ((h * TSEQ) + t) * HDIM + d;
    qh[o] = rtf(qr); kh[o] = rtf(kr); vh[o] = rtf(v);
}

// ---------------- dense masked flash attention (tf32 mma, 128-row q tiles) ----------------
// grid (TSEQ/128, NHEAD), 256 threads = 8 warps, warp w owns rows [w*16, w*16+16),
// full 64-col K span per warp. Heavy tiles first: qt = gridDim.x-1-blockIdx.x.
__global__ void __launch_bounds__(256, 2) attn_flash(
    const float* __restrict__ qh, const float* __restrict__ kh, const float* __restrict__ vh,
    const unsigned int* __restrict__ mask, float* __restrict__ av)
{
    __shared__ float Ks[64][68];
    __shared__ float Vs[64][68];
    __shared__ float Ps[128][68];
    __shared__ float rowM[128], rowL[128], rowScale[128];

    int qt = gridDim.x - 1 - blockIdx.x, h = blockIdx.y;
    int t0 = qt * 128;
    int tid = threadIdx.x;
    int warpId = tid >> 5, lane = tid & 31;
    int grp = lane >> 2, tig = lane & 3;
    int wm = warpId * 16;

    const float* Q0 = qh + ((size_t)h * TSEQ + t0) * HDIM;
    uint32_t qf[8][4];
#pragma unroll
    for (int ks = 0; ks < 8; ks++) {
        int kb = ks * 8;
        qf[ks][0] = __float_as_uint(Q0[(wm + grp) * HDIM + kb + tig]);
        qf[ks][1] = __float_as_uint(Q0[(wm + grp + 8) * HDIM + kb + tig]);
        qf[ks][2] = __float_as_uint(Q0[(wm + grp) * HDIM + kb + tig + 4]);
        qf[ks][3] = __float_as_uint(Q0[(wm + grp + 8) * HDIM + kb + tig + 4]);
    }

    if (tid < 128) { rowM[tid] = -INFINITY; rowL[tid] = 0.f; }

    float oacc[8][4];
#pragma unroll
    for (int ni = 0; ni < 8; ni++)
#pragma unroll
        for (int q = 0; q < 4; q++) oacc[ni][q] = 0.f;

    const float* Kb = kh + (size_t)h * TSEQ * HDIM;
    const float* Vb = vh + (size_t)h * TSEQ * HDIM;

    int ktMax = 2 * qt + 1;   // last k tile covering rows t0..t0+127
    for (int kt = 0; kt <= ktMax; kt++) {
        __syncthreads();
        for (int i = tid; i < 1024; i += 256) {
            int row = i >> 4, c4 = (i & 15) * 4;
            *(float4*)&Ks[row][c4] = *(const float4*)(Kb + (size_t)(kt * 64 + row) * HDIM + c4);
            *(float4*)&Vs[row][c4] = *(const float4*)(Vb + (size_t)(kt * 64 + row) * HDIM + c4);
        }
        __syncthreads();

        // S = Q @ K^T : each warp 16 rows x 64 cols
        float sacc[8][4];
#pragma unroll
        for (int ni = 0; ni < 8; ni++)
#pragma unroll
            for (int q = 0; q < 4; q++) sacc[ni][q] = 0.f;
#pragma unroll
        for (int ks = 0; ks < 8; ks++) {
            int kb = ks * 8;
#pragma unroll
            for (int ni = 0; ni < 8; ni++) {
                int n = ni * 8 + grp;
                uint32_t bf[2];
                bf[0] = __float_as_uint(Ks[n][kb + tig]);
                bf[1] = __float_as_uint(Ks[n][kb + tig + 4]);
                mma_tf32(sacc[ni], qf[ks], bf);
            }
        }

        int r0 = wm + grp, r1 = wm + grp + 8;
        unsigned int mw0[2], mw1[2];
        mw0[0] = mask[(t0 + r0) * 64 + kt * 2];
        mw0[1] = mask[(t0 + r0) * 64 + kt * 2 + 1];
        mw1[0] = mask[(t0 + r1) * 64 + kt * 2];
        mw1[1] = mask[(t0 + r1) * 64 + kt * 2 + 1];
#pragma unroll
        for (int ni = 0; ni < 8; ni++) {
            int c = ni * 8 + tig * 2;
            int wsel = c >> 5, b = c & 31;
            Ps[r0][c]     = ((mw0[wsel] >> b) & 1u)       ? sacc[ni][0] * 0.125f : -INFINITY;
            Ps[r0][c + 1] = ((mw0[wsel] >> (b + 1)) & 1u) ? sacc[ni][1] * 0.125f : -INFINITY;
            Ps[r1][c]     = ((mw1[wsel] >> b) & 1u)       ? sacc[ni][2] * 0.125f : -INFINITY;
            Ps[r1][c + 1] = ((mw1[wsel] >> (b + 1)) & 1u) ? sacc[ni][3] * 0.125f : -INFINITY;
        }
        __syncthreads();

        // online softmax: 4 threads per row, 2 row-passes (256 threads, 128 rows)
#pragma unroll
        for (int rr = 0; rr < 2; rr++) {
            int row = (tid >> 2) + rr * 64, seg = tid & 3;
            float m_old = rowM[row];
            float tmax = -INFINITY;
#pragma unroll
            for (int j = 0; j < 16; j++) tmax = fmaxf(tmax, Ps[row][seg * 16 + j]);
            tmax = fmaxf(tmax, __shfl_xor_sync(0xFFFFFFFFu, tmax, 1));
            tmax = fmaxf(tmax, __shfl_xor_sync(0xFFFFFFFFu, tmax, 2));
            float mnew = fmaxf(m_old, tmax);
            bool inval = (mnew == -INFINITY);
            float tsum = 0.f;
#pragma unroll
            for (int j = 0; j < 16; j++) {
                float v = Ps[row][seg * 16 + j];
                float p = inval ? 0.f : expf(v - mnew);
                Ps[row][seg * 16 + j] = rtf(p);
                tsum += p;
            }
            tsum += __shfl_xor_sync(0xFFFFFFFFu, tsum, 1);
            tsum += __shfl_xor_sync(0xFFFFFFFFu, tsum, 2);
            if (seg == 0) {
                float sc = inval ? 1.f : expf(m_old - mnew);
                rowScale[row] = sc;
                rowM[row] = mnew;
                rowL[row] = rowL[row] * sc + tsum;
            }
        }
        __syncthreads();

        float s0 = rowScale[wm + grp], s1 = rowScale[wm + grp + 8];
#pragma unroll
        for (int ni = 0; ni < 8; ni++) {
            oacc[ni][0] *= s0; oacc[ni][1] *= s0;
            oacc[ni][2] *= s1; oacc[ni][3] *= s1;
        }
#pragma unroll
        for (int ks = 0; ks < 8; ks++) {
            int kb = ks * 8;
            uint32_t pa[4];
            pa[0] = __float_as_uint(Ps[wm + grp][kb + tig]);
            pa[1] = __float_as_uint(Ps[wm + grp + 8][kb + tig]);
            pa[2] = __float_as_uint(Ps[wm + grp][kb + tig + 4]);
            pa[3] = __float_as_uint(Ps[wm + grp + 8][kb + tig + 4]);
#pragma unroll
            for (int ni = 0; ni < 8; ni++) {
                int n = ni * 8 + grp;
                uint32_t vf[2];
                vf[0] = __float_as_uint(Vs[kb + tig][n]);
                vf[1] = __float_as_uint(Vs[kb + tig + 4][n]);
                mma_tf32(oacc[ni], pa, vf);
            }
        }
    }
    __syncthreads();

    float i0 = 1.f / rowL[wm + grp];
    float i1 = 1.f / rowL[wm + grp + 8];
#pragma unroll
    for (int ni = 0; ni < 8; ni++) {
        int c = ni * 8 + tig * 2;
        size_t o0 = (size_t)(t0 + wm + grp) * DMODEL + h * HDIM + c;
        size_t o1 = (size_t)(t0 + wm + grp + 8) * DMODEL + h * HDIM + c;
        av[o0]     = rtf(oacc[ni][0] * i0);
        av[o0 + 1] = rtf(oacc[ni][1] * i0);
        av[o1]     = rtf(oacc[ni][2] * i1);
        av[o1 + 1] = rtf(oacc[ni][3] * i1);
    }
}

// ---------------- router (reads FULL-precision x2n) ----------------
__global__ __launch_bounds__(256) void router_kernel(
    const float* __restrict__ x2n, const float* __restrict__ rw, const float* __restrict__ rb,
    float* __restrict__ probs, int* __restrict__ topE, float* __restrict__ topG)
{
    int t = blockIdx.x, tid = threadIdx.x;
    __shared__ float red[256];
    __shared__ float lg[8];
    float acc[8];
#pragma unroll
    for (int e = 0; e < 8; e++) acc[e] = 0.f;
    const float* xr = x2n + (size_t)t * DMODEL;
    for (int d = tid; d < DMODEL; d += 256) {
        float xv = xr[d];
#pragma unroll
        for (int e = 0; e < 8; e++) acc[e] += xv * rw[(size_t)d * NEXP + e];
    }
    for (int e = 0; e < 8; e++) {
        red[tid] = acc[e]; __syncthreads();
        for (int o = 128; o > 0; o >>= 1) { if (tid < o) red[tid] += red[tid + o]; __syncthreads(); }
        if (tid == 0) lg[e] = red[0] + rb[e];
        __syncthreads();
    }
    if (tid == 0) {
        float m = lg[0];
        for (int e = 1; e < 8; e++) m = fmaxf(m, lg[e]);
        float p[8], s = 0.f;
        for (int e = 0; e < 8; e++) { p[e] = expf(lg[e] - m); s += p[e]; }
        for (int e = 0; e < 8; e++) p[e] /= s;
        int e0 = 0;
        for (int e = 1; e < 8; e++) if (p[e] > p[e0]) e0 = e;
        int e1 = -1;
        for (int e = 0; e < 8; e++) if (e != e0 && (e1 < 0 || p[e] > p[e1])) e1 = e;
        float denom = p[e0] + p[e1];
        for (int e = 0; e < 8; e++) probs[(size_t)t * NEXP + e] = p[e];
        topE[t * 2 + 0] = e0; topE[t * 2 + 1] = e1;
        topG[t * 2 + 0] = p[e0] / denom; topG[t * 2 + 1] = p[e1] / denom;
    }
}

// ---------------- deterministic grouping (warp-ballot scan, order-preserving) ----------------
__global__ __launch_bounds__(256) void group_kernel(
    const int* __restrict__ topE, int* __restrict__ counts,
    int* __restrict__ segoff, int* __restrict__ rowmap,
    int* __restrict__ slotpos)
{
    __shared__ short sE[TSEQ * 2];
    __shared__ int sSeg[NEXP + 1];
    __shared__ int sCnt[NEXP];
    int tid = threadIdx.x;
    int lane = tid & 31, w = tid >> 5;   // 8 warps, warp w owns expert w
    for (int i = tid; i < TSEQ * 2; i += 256) sE[i] = (short)topE[i];
    __syncthreads();

    // count
    {
        int e = w;
        int c = 0;
        for (int i0 = 0; i0 < TSEQ * 2; i0 += 32) {
            unsigned int m = __ballot_sync(0xFFFFFFFFu, sE[i0 + lane] == e);
            c += __popc(m);
        }
        if (lane == 0) { counts[e] = c; sCnt[e] = c; }
    }
    __syncthreads();
    if (tid == 0) {
        int o = 0;
        for (int i = 0; i < 8; i++) { sSeg[i] = o; segoff[i] = o; o += sCnt[i]; }
        sSeg[8] = o; segoff[8] = o;
    }
    __syncthreads();

    // scatter (index order preserved within expert)
    {
        int e = w;
        int pos = sSeg[e];
        unsigned int ltmask = (1u << lane) - 1u;
        for (int i0 = 0; i0 < TSEQ * 2; i0 += 32) {
            int i = i0 + lane;
            bool match = (sE[i] == e);
            unsigned int m = __ballot_sync(0xFFFFFFFFu, match);
            if (match) {
                int off = __popc(m & ltmask);
                rowmap[pos + off] = i >> 1;
                slotpos[i] = pos + off;
            }
            pos += __popc(m);
        }
    }
}

// ---------------- aux loss ----------------
__global__ __launch_bounds__(256) void aux_kernel(
    const float* __restrict__ probs, const int* __restrict__ counts, float* __restrict__ outAux)
{
    __shared__ float red[256];
    int tid = threadIdx.x;
    float a = 0.f;
    for (int e = 0; e < 8; e++) {
        float s = 0.f;
        for (int t = tid; t < TSEQ; t += 256) s += probs[(size_t)t * NEXP + e];
        red[tid] = s; __syncthreads();
        for (int o = 128; o > 0; o >>= 1) { if (tid < o) red[tid] += red[tid + o]; __syncthreads(); }
        if (tid == 0) a += (float)counts[e] * red[0];
        __syncthreads();
    }
    if (tid == 0) *outAux = 8.f * a / ((float)TSEQ * (float)TSEQ);
}

// ---------------- final combine ----------------
__global__ __launch_bounds__(256) void combine_kernel(
    const float* __restrict__ x1, const float* __restrict__ y,
    const int* __restrict__ slotpos, const float* __restrict__ topG,
    float* __restrict__ out)
{
    int idx = blockIdx.x * 256 + threadIdx.x;
    int t = idx >> 10, d = idx & 1023;
    int p0 = slotpos[t * 2 + 0], p1 = slotpos[t * 2 + 1];
    float g0 = topG[t * 2 + 0], g1 = topG[t * 2 + 1];
    out[idx] = x1[idx] + g0 * y[(size_t)p0 * DMODEL + d] + g1 * y[(size_t)p1 * DMODEL + d];
}

// ---------------- host launch ----------------
#define GETSYM(ptr, sym) do { void* _p_; cudaGetSymbolAddress(&_p_, sym); ptr = (decltype(ptr))_p_; } while (0)

extern "C" void kernel_launch(void* const* d_in, const int* in_sizes, int n_in,
                              void* d_out, int out_size)
{
    const float* x        = (const float*)d_in[0];
    const float* norm1_w  = (const float*)d_in[1];
    const float* norm2_w  = (const float*)d_in[2];
    const float* wq_idx   = (const float*)d_in[3];
    const float* wk_idx   = (const float*)d_in[4];
    const float* w_head   = (const float*)d_in[5];
    const float* wq       = (const float*)d_in[6];
    const float* wk       = (const float*)d_in[7];
    const float* wv       = (const float*)d_in[8];
    const float* wo       = (const float*)d_in[9];
    const float* router_w = (const float*)d_in[10];
    const float* router_b = (const float*)d_in[11];
    const float* w1       = (const float*)d_in[12];
    const float* b1       = (const float*)d_in[13];
    const float* w2       = (const float*)d_in[14];
    const float* b2       = (const float*)d_in[15];

    float* out    = (float*)d_out;
    float* auxp   = out + (size_t)TSEQ * DMODEL;
    float* idxout = auxp + 1;

    float *p_xn, *p_proj, *p_qkv, *p_qh, *p_kh, *p_vh;
    float *p_av, *p_x1, *p_x2n, *p_x2f, *p_probs, *p_topG, *p_mid, *p_y;
    float *p_w1c, *p_w2c, *p_woc, *p_wqkvc, *p_widxc;
    int *p_topE, *p_counts, *p_segoff, *p_rowmap, *p_slotpos;
    unsigned int *p_mask;
    GETSYM(p_xn, g_xn); GETSYM(p_proj, g_proj_idx); GETSYM(p_qkv, g_qkv);
    GETSYM(p_qh, g_qh); GETSYM(p_kh, g_kh); GETSYM(p_vh, g_vh);
    GETSYM(p_av, g_av); GETSYM(p_x1, g_x1);
    GETSYM(p_x2n, g_x2n); GETSYM(p_x2f, g_x2f);
    GETSYM(p_probs, g_probs); GETSYM(p_topE, g_topE); GETSYM(p_topG, g_topG);
    GETSYM(p_counts, g_counts); GETSYM(p_segoff, g_segoff);
    GETSYM(p_rowmap, g_rowmap); GETSYM(p_slotpos, g_slotpos);
    GETSYM(p_mid, g_mid); GETSYM(p_y, g_yy); GETSYM(p_mask, g_mask);
    GETSYM(p_w1c, g_w1c); GETSYM(p_w2c, g_w2c); GETSYM(p_woc, g_woc);
    GETSYM(p_wqkvc, g_wqkvc); GETSYM(p_widxc, g_widxc);

    cudaFuncSetAttribute(tgemm, cudaFuncAttributeMaxDynamicSharedMemorySize, TG_SMEM_BYTES);

    // 0. weight rounding / packing
    {
        int n4 = NEXP * DMODEL * DFFN / 4;
        round4_kernel<<<(n4 + 255) / 256, 256>>>((const float4*)w1, (float4*)p_w1c, n4);
        round4_kernel<<<(n4 + 255) / 256, 256>>>((const float4*)w2, (float4*)p_w2c, n4);
        int m4 = DMODEL * DMODEL / 4;
        round4_kernel<<<(m4 + 255) / 256, 256>>>((const float4*)wo, (float4*)p_woc, m4);
        pack_qkv_kernel<<<(DMODEL * DMODEL) / 256, 256>>>(wq, wk, wv, p_wqkvc);
        pack_idx_kernel<<<(DMODEL * NPROJ_IDX + 255) / 256, 256>>>(wq_idx, wk_idx, w_head, p_widxc);
    }

    // 1. norm1
    rmsnorm_kernel<<<TSEQ, 256>>>(x, norm1_w, p_xn, nullptr);

    // 2. fused projections
    tgemm<<<dim3((NPROJ_IDX + 127) / 128, 16, 1), 256, TG_SMEM_BYTES>>>(
        p_xn, DMODEL, nullptr, p_widxc, 0, nullptr, 0,
        nullptr, p_proj, NPROJ_IDX, nullptr, TSEQ, NPROJ_IDX, DMODEL, 0);
    tgemm<<<dim3(NPROJ_QKV / 128, 16, 1), 256, TG_SMEM_BYTES>>>(
        p_xn, DMODEL, nullptr, p_wqkvc, 0, nullptr, 0,
        nullptr, p_qkv, NPROJ_QKV, nullptr, TSEQ, NPROJ_QKV, DMODEL, 0);

    // 3. indexer scores + fused top-512 mask
    idx_kernel<<<dim3(32, 32), 256>>>(p_proj, idxout);
    topk_mask_kernel<<<TSEQ, 512>>>(idxout, p_mask);

    // 4. rope + transpose
    rope_kernel<<<(TSEQ * DMODEL) / 256, 256>>>(p_qkv, p_qh, p_kh, p_vh);

    // 5. dense masked flash attention (128-row q tiles, heavy first)
    attn_flash<<<dim3(TSEQ / 128, NHEAD), 256>>>(p_qh, p_kh, p_vh, p_mask, p_av);

    // 6. output projection + residual
    tgemm<<<dim3(8, 16, 1), 256, TG_SMEM_BYTES>>>(p_av, DMODEL, nullptr, p_woc, 0, nullptr, 0,
        x, p_x1, DMODEL, nullptr, TSEQ, DMODEL, DMODEL, 0);

    // 7. norm2 + router + grouping + aux
    rmsnorm_kernel<<<TSEQ, 256>>>(p_x1, norm2_w, p_x2n, p_x2f);
    router_kernel<<<TSEQ, 256>>>(p_x2f, router_w, router_b, p_probs, p_topE, p_topG);
    group_kernel<<<1, 256>>>(p_topE, p_counts, p_segoff, p_rowmap, p_slotpos);
    aux_kernel<<<1, 256>>>(p_probs, p_counts, auxp);

    // 8. MoE grouped GEMMs
    tgemm<<<dim3(DFFN / 128, 16, NEXP), 256, TG_SMEM_BYTES>>>(
        p_x2n, DMODEL, p_rowmap, p_w1c, (long long)DMODEL * DFFN, b1, DFFN,
        nullptr, p_mid, DFFN, p_segoff, 0, DFFN, DMODEL, 1);
    tgemm<<<dim3(DMODEL / 128, 16, NEXP), 256, TG_SMEM_BYTES>>>(
        p_mid, DFFN, nullptr, p_w2c, (long long)DFFN * DMODEL, b2, DMODEL,
        nullptr, p_y, DMODEL, p_segoff, 0, DMODEL, DFFN, 0);

    // 9. combine
    combine_kernel<<<(TSEQ * DMODEL) / 256, 256>>>(p_x1, p_y, p_slotpos, p_topG, out);
}

// round 8
// speedup vs baseline: 3.6596x; 1.0622x over previous
#include <cuda_runtime.h>
#include <math.h>
#include <stdint.h>

// ---------------- constants ----------------
static const int TSEQ = 2048;
static const int DMODEL = 1024;
static const int NHEAD = 16;
static const int HDIM = 64;
static const int DFFN = 4096;
static const int NEXP = 8;
static const int HIDX = 4;
static const int DIDX = 64;
static const int KSEL = 512;
static const int NPROJ_IDX = HIDX * DIDX + DIDX + HIDX;  // 324
static const int NPROJ_QKV = 3 * DMODEL;                 // 3072

// ---------------- device scratch ----------------
__device__ float g_xn[TSEQ * DMODEL];
__device__ float g_proj_idx[TSEQ * NPROJ_IDX];
__device__ float g_qkv[TSEQ * NPROJ_QKV];
__device__ float g_qh[TSEQ * DMODEL];
__device__ float g_kh[TSEQ * DMODEL];
__device__ float g_vh[TSEQ * DMODEL];
__device__ float g_av[TSEQ * DMODEL];
__device__ float g_x1[TSEQ * DMODEL];
__device__ float g_x2n[TSEQ * DMODEL];   // tf32-rounded (GEMM operand)
__device__ float g_x2f[TSEQ * DMODEL];   // full fp32 (router input)
__device__ float g_probs[TSEQ * NEXP];
__device__ int   g_topE[TSEQ * 2];
__device__ float g_topG[TSEQ * 2];
__device__ int   g_counts[NEXP];
__device__ int   g_segoff[NEXP + 1];
__device__ int   g_rowmap[TSEQ * 2];
__device__ int   g_slotpos[TSEQ * 2];
__device__ float g_mid[(size_t)(TSEQ * 2) * DFFN];
__device__ float g_yy[(size_t)(TSEQ * 2) * DMODEL];
__device__ unsigned int g_mask[TSEQ * (TSEQ / 32)];
// tf32-rounded weight copies (small ones only; w1/w2 are converted in-GEMM)
__device__ float g_woc[DMODEL * DMODEL];
__device__ float g_wqkvc[DMODEL * NPROJ_QKV];
__device__ float g_widxc[DMODEL * NPROJ_IDX];

// ---------------- helpers ----------------
__device__ __forceinline__ float gelu_tanh(float x) {
    float x3 = x * x * x;
    float u = 0.7978845608028654f * (x + 0.044715f * x3);
    return 0.5f * x * (1.0f + tanhf(u));
}

__device__ __forceinline__ unsigned int fmono(float f) {
    unsigned int u = __float_as_uint(f);
    return (u & 0x80000000u) ? ~u : (u | 0x80000000u);
}

__device__ __forceinline__ uint32_t f2tf32(float f) {
    uint32_t r;
    asm("cvt.rna.tf32.f32 %0, %1;" : "=r"(r) : "f"(f));
    return r;
}
__device__ __forceinline__ float rtf(float f) { return __uint_as_float(f2tf32(f)); }

__device__ __forceinline__ void cp16(uint32_t dst, const float* src, int sz) {
    asm volatile("cp.async.cg.shared.global [%0], [%1], 16, %2;" :: "r"(dst), "l"(src), "r"(sz));
}

__device__ __forceinline__ void mma_tf32(float* c, const uint32_t* a, const uint32_t* b) {
    asm volatile(
        "mma.sync.aligned.m16n8k8.row.col.f32.tf32.tf32.f32 "
        "{%0,%1,%2,%3}, {%4,%5,%6,%7}, {%8,%9}, {%0,%1,%2,%3};"
        : "+f"(c[0]), "+f"(c[1]), "+f"(c[2]), "+f"(c[3])
        : "r"(a[0]), "r"(a[1]), "r"(a[2]), "r"(a[3]), "r"(b[0]), "r"(b[1]));
}

// ---------------- weight conversion / packing (small weights only) ----------------
__global__ __launch_bounds__(256) void round4_kernel(
    const float4* __restrict__ in, float4* __restrict__ out, int n4)
{
    int i = blockIdx.x * 256 + threadIdx.x;
    if (i < n4) {
        float4 v = in[i];
        v.x = rtf(v.x); v.y = rtf(v.y); v.z = rtf(v.z); v.w = rtf(v.w);
        out[i] = v;
    }
}

__global__ __launch_bounds__(256) void pack_qkv_kernel(
    const float* __restrict__ wq, const float* __restrict__ wk, const float* __restrict__ wv,
    float* __restrict__ out)
{
    int i = blockIdx.x * 256 + threadIdx.x;  // over 1024*1024
    int d = i >> 10, c = i & 1023;
    out[(size_t)d * NPROJ_QKV + c] = rtf(wq[i]);
    out[(size_t)d * NPROJ_QKV + DMODEL + c] = rtf(wk[i]);
    out[(size_t)d * NPROJ_QKV + 2 * DMODEL + c] = rtf(wv[i]);
}

__global__ __launch_bounds__(256) void pack_idx_kernel(
    const float* __restrict__ wq_idx, const float* __restrict__ wk_idx,
    const float* __restrict__ w_head, float* __restrict__ out)
{
    int i = blockIdx.x * 256 + threadIdx.x;  // over 1024*324
    if (i >= DMODEL * NPROJ_IDX) return;
    int d = i / NPROJ_IDX, j = i - d * NPROJ_IDX;
    float v;
    if (j < 256) v = wq_idx[d * 256 + j];
    else if (j < 320) v = wk_idx[d * 64 + (j - 256)];
    else v = w_head[d * 4 + (j - 320)];
    out[i] = rtf(v);
}

// ---------------- unified tf32 tensor GEMM ----------------
// CVTB=1: B operand is raw fp32, rounded to tf32 at fragment load (bit-identical
// to loading a pre-rounded copy). A operand is always pre-rounded by its producer.
#define BKM 128
#define BKN 128
#define BKK 32
#define LDA_S 36
#define LDB_S 132
#define A_STAGE (BKM * LDA_S)
#define B_STAGE (BKK * LDB_S)
#define STAGE_FLOATS (A_STAGE + B_STAGE)
#define NSTAGE 3
#define TG_SMEM_BYTES (NSTAGE * STAGE_FLOATS * 4)

extern __shared__ float smem_dyn[];

template <int CVTB>
__global__ void __launch_bounds__(256, 2) tgemm(
    const float* __restrict__ A, int lda,
    const int* __restrict__ rowmap,
    const float* __restrict__ Bbase, long long strideB,
    const float* __restrict__ biasBase, int biasStride,
    const float* __restrict__ residual,
    float* __restrict__ C, int ldc,
    const int* __restrict__ segoff,
    int M, int N, int K, int doGelu)
{
    int e = blockIdx.z;
    int s0 = 0, nrows = M;
    if (segoff) { s0 = segoff[e]; nrows = segoff[e + 1] - s0; }
    int rowTile = blockIdx.y;
    if (rowTile * BKM >= nrows) return;
    int colStart = blockIdx.x * BKN;
    const float* B = Bbase + (long long)e * strideB;

    int tid = threadIdx.x;
    int warpId = tid >> 5, lane = tid & 31;
    int grp = lane >> 2, tig = lane & 3;
    int wm = (warpId >> 2) * 64;
    int wn = (warpId & 3) * 32;

    uint32_t sbase = (uint32_t)__cvta_generic_to_shared(smem_dyn);

    const float* aSrc[4]; int aSz[4]; uint32_t aDst[4];
    const float* bSrc[4]; int bSz[4]; uint32_t bDst[4];
#pragma unroll
    for (int i = 0; i < 4; i++) {
        int c = tid + i * 256;
        int arow = c >> 3, akc = (c & 7) * 4;
        int lrow = rowTile * BKM + arow;
        bool v = lrow < nrows;
        int gidx = 0;
        if (v) {
            int base = s0 + lrow;
            gidx = rowmap ? rowmap[base] : base;
        }
        aSrc[i] = A + (size_t)gidx * lda + akc;
        aSz[i] = v ? 16 : 0;
        aDst[i] = (uint32_t)((arow * LDA_S + akc) * 4);

        int brow = c >> 5, bnc = (c & 31) * 4;
        int col = colStart + bnc;
        bool bv = (col + 4 <= N);
        bSz[i] = bv ? 16 : 0;
        bSrc[i] = B + (size_t)brow * N + (bv ? col : 0);
        bDst[i] = (uint32_t)((A_STAGE + brow * LDB_S + bnc) * 4);
    }

    float acc[4][4][4];
#pragma unroll
    for (int mi = 0; mi < 4; mi++)
#pragma unroll
        for (int ni = 0; ni < 4; ni++)
#pragma unroll
            for (int q = 0; q < 4; q++) acc[mi][ni][q] = 0.f;

    int KT = K / BKK;

#pragma unroll
    for (int p = 0; p < NSTAGE - 1; p++) {
        if (p < KT) {
            int k0 = p * BKK;
            uint32_t sb = sbase + (uint32_t)((p % NSTAGE) * STAGE_FLOATS * 4);
#pragma unroll
            for (int i = 0; i < 4; i++) cp16(sb + aDst[i], aSrc[i] + k0, aSz[i]);
#pragma unroll
            for (int i = 0; i < 4; i++) cp16(sb + bDst[i], bSrc[i] + (size_t)k0 * N, bSz[i]);
            asm volatile("cp.async.commit_group;");
        }
    }

    for (int it = 0; it < KT; it++) {
        if (it + NSTAGE - 1 < KT) {
            int k0 = (it + NSTAGE - 1) * BKK;
            uint32_t sb = sbase + (uint32_t)(((it + NSTAGE - 1) % NSTAGE) * STAGE_FLOATS * 4);
#pragma unroll
            for (int i = 0; i < 4; i++) cp16(sb + aDst[i], aSrc[i] + k0, aSz[i]);
#pragma unroll
            for (int i = 0; i < 4; i++) cp16(sb + bDst[i], bSrc[i] + (size_t)k0 * N, bSz[i]);
            asm volatile("cp.async.commit_group;");
        }
        int pend = KT - 1 - it;
        if (pend > NSTAGE - 1) pend = NSTAGE - 1;
        if (pend >= 2)      asm volatile("cp.async.wait_group 2;");
        else if (pend == 1) asm volatile("cp.async.wait_group 1;");
        else                asm volatile("cp.async.wait_group 0;");
        __syncthreads();

        const uint32_t* Ab = (const uint32_t*)(smem_dyn + (size_t)(it % NSTAGE) * STAGE_FLOATS);
        const uint32_t* Bb = Ab + A_STAGE;
#pragma unroll
        for (int ks = 0; ks < 4; ks++) {
            int kb = ks * 8;
            uint32_t af[4][4];
#pragma unroll
            for (int mi = 0; mi < 4; mi++) {
                int r = wm + mi * 16 + grp;
                af[mi][0] = Ab[r * LDA_S + kb + tig];
                af[mi][1] = Ab[(r + 8) * LDA_S + kb + tig];
                af[mi][2] = Ab[r * LDA_S + kb + tig + 4];
                af[mi][3] = Ab[(r + 8) * LDA_S + kb + tig + 4];
            }
            uint32_t bf[4][2];
#pragma unroll
            for (int ni = 0; ni < 4; ni++) {
                int ccol = wn + ni * 8 + grp;
                uint32_t r0 = Bb[(kb + tig) * LDB_S + ccol];
                uint32_t r1 = Bb[(kb + tig + 4) * LDB_S + ccol];
                if (CVTB) {
                    bf[ni][0] = f2tf32(__uint_as_float(r0));
                    bf[ni][1] = f2tf32(__uint_as_float(r1));
                } else {
                    bf[ni][0] = r0;
                    bf[ni][1] = r1;
                }
            }
#pragma unroll
            for (int mi = 0; mi < 4; mi++)
#pragma unroll
                for (int ni = 0; ni < 4; ni++)
                    mma_tf32(acc[mi][ni], af[mi], bf[ni]);
        }
        __syncthreads();
    }

    const float* bias = biasBase ? (biasBase + (long long)e * biasStride) : nullptr;
#pragma unroll
    for (int mi = 0; mi < 4; mi++) {
        int rbase = wm + mi * 16 + grp;
#pragma unroll
        for (int half = 0; half < 2; half++) {
            int r = rbase + half * 8;
            int lrow = rowTile * BKM + r;
            if (lrow >= nrows) continue;
            int grow = s0 + lrow;
#pragma unroll
            for (int ni = 0; ni < 4; ni++) {
                int col = colStart + wn + ni * 8 + tig * 2;
                float v0 = acc[mi][ni][half * 2 + 0];
                float v1 = acc[mi][ni][half * 2 + 1];
                if (bias) { v0 += bias[col]; v1 += bias[col + 1]; }
                if (doGelu) {
                    v0 = rtf(gelu_tanh(v0));
                    v1 = rtf(gelu_tanh(v1));
                }
                if (residual) {
                    v0 += residual[(size_t)grow * ldc + col];
                    v1 += residual[(size_t)grow * ldc + col + 1];
                }
                if (col < N)     C[(size_t)grow * ldc + col] = v0;
                if (col + 1 < N) C[(size_t)grow * ldc + col + 1] = v1;
            }
        }
    }
}

// ---------------- rmsnorm (rounded main output; optional full-precision copy) ----------------
__global__ __launch_bounds__(256) void rmsnorm_kernel(
    const float* __restrict__ x, const float* __restrict__ w,
    float* __restrict__ y, float* __restrict__ yfull)
{
    int t = blockIdx.x, tid = threadIdx.x;
    __shared__ float red[256];
    const float* xr = x + (size_t)t * DMODEL;
    float s = 0.f;
    for (int d = tid; d < DMODEL; d += 256) { float v = xr[d]; s += v * v; }
    red[tid] = s; __syncthreads();
    for (int o = 128; o > 0; o >>= 1) { if (tid < o) red[tid] += red[tid + o]; __syncthreads(); }
    float rms = rsqrtf(red[0] / (float)DMODEL + 1e-6f);
    float* yr = y + (size_t)t * DMODEL;
    for (int d = tid; d < DMODEL; d += 256) {
        float v = xr[d] * rms * w[d];
        yr[d] = rtf(v);
        if (yfull) yfull[(size_t)t * DMODEL + d] = v;
    }
}

// ---------------- indexer scores (transposed smem, vectorized LDS; fp32, bit-identical) ----------------
__global__ __launch_bounds__(256) void idx_kernel(
    const float* __restrict__ proj, float* __restrict__ out)
{
    __shared__ float qshT[64][68];   // [kk][t-row], stride 68 (16B-aligned rows)
    __shared__ float kshT[64][68];   // [kk][s-row]
    __shared__ float hsh[64][4];
    int t0 = blockIdx.y * 64, s0 = blockIdx.x * 64;
    int tid = threadIdx.x;
    const int tr = (tid >> 4) * 4, tc = (tid & 15) * 4;

    hsh[tid >> 2][tid & 3] = proj[(size_t)(t0 + (tid >> 2)) * NPROJ_IDX + 320 + (tid & 3)];
    for (int i = tid; i < 4096; i += 256) {
        int r = i >> 6, c = i & 63;
        kshT[c][r] = proj[(size_t)(s0 + r) * NPROJ_IDX + 256 + c];
    }
    float acc[4][4];
#pragma unroll
    for (int i = 0; i < 4; i++)
#pragma unroll
        for (int j = 0; j < 4; j++) acc[i][j] = 0.f;

    for (int h = 0; h < HIDX; h++) {
        __syncthreads();
        for (int i = tid; i < 4096; i += 256) {
            int r = i >> 6, c = i & 63;
            qshT[c][r] = proj[(size_t)(t0 + r) * NPROJ_IDX + h * DIDX + c];
        }
        __syncthreads();
        float dot[4][4];
#pragma unroll
        for (int i = 0; i < 4; i++)
#pragma unroll
            for (int j = 0; j < 4; j++) dot[i][j] = 0.f;
        for (int kk = 0; kk < 64; kk++) {
            float4 a4 = *(const float4*)&qshT[kk][tr];
            float4 b4 = *(const float4*)&kshT[kk][tc];
            float a[4] = {a4.x, a4.y, a4.z, a4.w};
            float b[4] = {b4.x, b4.y, b4.z, b4.w};
#pragma unroll
            for (int i = 0; i < 4; i++)
#pragma unroll
                for (int j = 0; j < 4; j++) dot[i][j] += a[i] * b[j];
        }
#pragma unroll
        for (int i = 0; i < 4; i++)
#pragma unroll
            for (int j = 0; j < 4; j++)
                acc[i][j] += hsh[tr + i][h] * fmaxf(dot[i][j], 0.f);
    }
#pragma unroll
    for (int i = 0; i < 4; i++)
#pragma unroll
        for (int j = 0; j < 4; j++)
            out[(size_t)(t0 + tr + i) * TSEQ + (s0 + tc + j)] = acc[i][j] * 0.125f;
}

// ---------------- fused top-512 radix-select + mask build ----------------
__global__ __launch_bounds__(512) void topk_mask_kernel(
    const float* __restrict__ idxs, unsigned int* __restrict__ mask)
{
    __shared__ unsigned long long keys[2048];
    __shared__ unsigned int hist[256];
    __shared__ unsigned int sh_k;
    __shared__ unsigned long long sh_prefix;

    int t = blockIdx.x, tid = threadIdx.x;

    for (int i = tid; i < 2048; i += 512) {
        unsigned long long kk = 0ull;
        if (i <= t) {
            float v = idxs[(size_t)t * TSEQ + i];
            kk = ((unsigned long long)fmono(v) << 32) | (unsigned int)(2047 - i);
        }
        keys[i] = kk;
    }
    if (tid == 0) { sh_k = (unsigned int)KSEL; sh_prefix = 0ull; }
    __syncthreads();

    const int shifts[6] = {56, 48, 40, 32, 8, 0};
    unsigned long long prefix_mask = 0ull;
#pragma unroll
    for (int p = 0; p < 6; p++) {
        int shift = shifts[p];
        if (tid < 256) hist[tid] = 0u;
        __syncthreads();
        unsigned long long pref = sh_prefix;
        for (int i = tid; i < 2048; i += 512) {
            unsigned long long key = keys[i];
            if ((key & prefix_mask) == pref)
                atomicAdd(&hist[(unsigned int)(key >> shift) & 255u], 1u);
        }
        __syncthreads();
        for (int off = 1; off < 256; off <<= 1) {
            unsigned int add = 0u;
            if (tid < 256 && tid + off < 256) add = hist[tid + off];
            __syncthreads();
            if (tid < 256) hist[tid] += add;
            __syncthreads();
        }
        unsigned int k = sh_k;
        if (tid < 256) {
            unsigned int s_here = hist[tid];
            unsigned int s_next = (tid == 255) ? 0u : hist[tid + 1];
            if (s_here >= k && s_next < k) {
                sh_prefix = pref | ((unsigned long long)tid << shift);
                sh_k = k - s_next;
            }
        }
        __syncthreads();
        prefix_mask |= (0xFFull << shift);
    }

    unsigned long long thr = sh_prefix;
    int lane = tid & 31, w = tid >> 5;
    for (int word = w; word < 64; word += 16) {
        int i = word * 32 + lane;
        bool sel = (i <= t) && (keys[i] >= thr);
        unsigned int bal = __ballot_sync(0xFFFFFFFFu, sel);
        if (lane == 0) mask[t * 64 + word] = bal;
    }
}

// ---------------- RoPE from fused qkv + transpose to [h][t][d], rounds outputs ----------------
__global__ __launch_bounds__(256) void rope_kernel(
    const float* __restrict__ qkv,
    float* __restrict__ qh, float* __restrict__ kh, float* __restrict__ vh)
{
    int idx = blockIdx.x * 256 + threadIdx.x;
    int t = idx >> 10;
    int hd = idx & 1023;
    int h = hd >> 6, d = hd & 63;
    int j = d & 31;
    double invd = exp(-((double)(2 * j) / 64.0) * log(10000.0));
    float ang = (float)((double)t * invd);
    float c = cosf(ang), s = sinf(ang);
    const float* row = qkv + (size_t)t * NPROJ_QKV;
    float q = row[hd], k = row[DMODEL + hd], v = row[2 * DMODEL + hd];
    float qr, kr;
    if (d < 32) {
        qr = q * c - row[hd + 32] * s;
        kr = k * c - row[DMODEL + hd + 32] * s;
    } else {
        qr = q * c + row[hd - 32] * s;
        kr = k * c + row[DMODEL + hd - 32] * s;
    }
    int o = ((h * TSEQ) + t) * HDIM + d;
    qh[o] = rtf(qr); kh[o] = rtf(kr); vh[o] = rtf(v);
}

// ---------------- dense masked flash attention (tf32 mma, 128-row q tiles) ----------------
__global__ void __launch_bounds__(256, 2) attn_flash(
    const float* __restrict__ qh, const float* __restrict__ kh, const float* __restrict__ vh,
    const unsigned int* __restrict__ mask, float* __restrict__ av)
{
    __shared__ float Ks[64][68];
    __shared__ float Vs[64][68];
    __shared__ float Ps[128][68];
    __shared__ float rowM[128], rowL[128], rowScale[128];

    int qt = gridDim.x - 1 - blockIdx.x, h = blockIdx.y;
    int t0 = qt * 128;
    int tid = threadIdx.x;
    int warpId = tid >> 5, lane = tid & 31;
    int grp = lane >> 2, tig = lane & 3;
    int wm = warpId * 16;

    const float* Q0 = qh + ((size_t)h * TSEQ + t0) * HDIM;
    uint32_t qf[8][4];
#pragma unroll
    for (int ks = 0; ks < 8; ks++) {
        int kb = ks * 8;
        qf[ks][0] = __float_as_uint(Q0[(wm + grp) * HDIM + kb + tig]);
        qf[ks][1] = __float_as_uint(Q0[(wm + grp + 8) * HDIM + kb + tig]);
        qf[ks][2] = __float_as_uint(Q0[(wm + grp) * HDIM + kb + tig + 4]);
        qf[ks][3] = __float_as_uint(Q0[(wm + grp + 8) * HDIM + kb + tig + 4]);
    }

    if (tid < 128) { rowM[tid] = -INFINITY; rowL[tid] = 0.f; }

    float oacc[8][4];
#pragma unroll
    for (int ni = 0; ni < 8; ni++)
#pragma unroll
        for (int q = 0; q < 4; q++) oacc[ni][q] = 0.f;

    const float* Kb = kh + (size_t)h * TSEQ * HDIM;
    const float* Vb = vh + (size_t)h * TSEQ * HDIM;

    int ktMax = 2 * qt + 1;
    for (int kt = 0; kt <= ktMax; kt++) {
        __syncthreads();
        for (int i = tid; i < 1024; i += 256) {
            int row = i >> 4, c4 = (i & 15) * 4;
            *(float4*)&Ks[row][c4] = *(const float4*)(Kb + (size_t)(kt * 64 + row) * HDIM + c4);
            *(float4*)&Vs[row][c4] = *(const float4*)(Vb + (size_t)(kt * 64 + row) * HDIM + c4);
        }
        __syncthreads();

        float sacc[8][4];
#pragma unroll
        for (int ni = 0; ni < 8; ni++)
#pragma unroll
            for (int q = 0; q < 4; q++) sacc[ni][q] = 0.f;
#pragma unroll
        for (int ks = 0; ks < 8; ks++) {
            int kb = ks * 8;
#pragma unroll
            for (int ni = 0; ni < 8; ni++) {
                int n = ni * 8 + grp;
                uint32_t bf[2];
                bf[0] = __float_as_uint(Ks[n][kb + tig]);
                bf[1] = __float_as_uint(Ks[n][kb + tig + 4]);
                mma_tf32(sacc[ni], qf[ks], bf);
            }
        }

        int r0 = wm + grp, r1 = wm + grp + 8;
        unsigned int mw0[2], mw1[2];
        mw0[0] = mask[(t0 + r0) * 64 + kt * 2];
        mw0[1] = mask[(t0 + r0) * 64 + kt * 2 + 1];
        mw1[0] = mask[(t0 + r1) * 64 + kt * 2];
        mw1[1] = mask[(t0 + r1) * 64 + kt * 2 + 1];
#pragma unroll
        for (int ni = 0; ni < 8; ni++) {
            int c = ni * 8 + tig * 2;
            int wsel = c >> 5, b = c & 31;
            Ps[r0][c]     = ((mw0[wsel] >> b) & 1u)       ? sacc[ni][0] * 0.125f : -INFINITY;
            Ps[r0][c + 1] = ((mw0[wsel] >> (b + 1)) & 1u) ? sacc[ni][1] * 0.125f : -INFINITY;
            Ps[r1][c]     = ((mw1[wsel] >> b) & 1u)       ? sacc[ni][2] * 0.125f : -INFINITY;
            Ps[r1][c + 1] = ((mw1[wsel] >> (b + 1)) & 1u) ? sacc[ni][3] * 0.125f : -INFINITY;
        }
        __syncthreads();

#pragma unroll
        for (int rr = 0; rr < 2; rr++) {
            int row = (tid >> 2) + rr * 64, seg = tid & 3;
            float m_old = rowM[row];
            float tmax = -INFINITY;
#pragma unroll
            for (int j = 0; j < 16; j++) tmax = fmaxf(tmax, Ps[row][seg * 16 + j]);
            tmax = fmaxf(tmax, __shfl_xor_sync(0xFFFFFFFFu, tmax, 1));
            tmax = fmaxf(tmax, __shfl_xor_sync(0xFFFFFFFFu, tmax, 2));
            float mnew = fmaxf(m_old, tmax);
            bool inval = (mnew == -INFINITY);
            float tsum = 0.f;
#pragma unroll
            for (int j = 0; j < 16; j++) {
                float v = Ps[row][seg * 16 + j];
                float p = inval ? 0.f : expf(v - mnew);
                Ps[row][seg * 16 + j] = rtf(p);
                tsum += p;
            }
            tsum += __shfl_xor_sync(0xFFFFFFFFu, tsum, 1);
            tsum += __shfl_xor_sync(0xFFFFFFFFu, tsum, 2);
            if (seg == 0) {
                float sc = inval ? 1.f : expf(m_old - mnew);
                rowScale[row] = sc;
                rowM[row] = mnew;
                rowL[row] = rowL[row] * sc + tsum;
            }
        }
        __syncthreads();

        float s0 = rowScale[wm + grp], s1 = rowScale[wm + grp + 8];
#pragma unroll
        for (int ni = 0; ni < 8; ni++) {
            oacc[ni][0] *= s0; oacc[ni][1] *= s0;
            oacc[ni][2] *= s1; oacc[ni][3] *= s1;
        }
#pragma unroll
        for (int ks = 0; ks < 8; ks++) {
            int kb = ks * 8;
            uint32_t pa[4];
            pa[0] = __float_as_uint(Ps[wm + grp][kb + tig]);
            pa[1] = __float_as_uint(Ps[wm + grp + 8][kb + tig]);
            pa[2] = __float_as_uint(Ps[wm + grp][kb + tig + 4]);
            pa[3] = __float_as_uint(Ps[wm + grp + 8][kb + tig + 4]);
#pragma unroll
            for (int ni = 0; ni < 8; ni++) {
                int n = ni * 8 + grp;
                uint32_t vf[2];
                vf[0] = __float_as_uint(Vs[kb + tig][n]);
                vf[1] = __float_as_uint(Vs[kb + tig + 4][n]);
                mma_tf32(oacc[ni], pa, vf);
            }
        }
    }
    __syncthreads();

    float i0 = 1.f / rowL[wm + grp];
    float i1 = 1.f / rowL[wm + grp + 8];
#pragma unroll
    for (int ni = 0; ni < 8; ni++) {
        int c = ni * 8 + tig * 2;
        size_t o0 = (size_t)(t0 + wm + grp) * DMODEL + h * HDIM + c;
        size_t o1 = (size_t)(t0 + wm + grp + 8) * DMODEL + h * HDIM + c;
        av[o0]     = rtf(oacc[ni][0] * i0);
        av[o0 + 1] = rtf(oacc[ni][1] * i0);
        av[o1]     = rtf(oacc[ni][2] * i1);
        av[o1 + 1] = rtf(oacc[ni][3] * i1);
    }
}

// ---------------- router (reads FULL-precision x2n) ----------------
__global__ __launch_bounds__(256) void router_kernel(
    const float* __restrict__ x2n, const float* __restrict__ rw, const float* __restrict__ rb,
    float* __restrict__ probs, int* __restrict__ topE, float* __restrict__ topG)
{
    int t = blockIdx.x, tid = threadIdx.x;
    __shared__ float red[256];
    __shared__ float lg[8];
    float acc[8];
#pragma unroll
    for (int e = 0; e < 8; e++) acc[e] = 0.f;
    const float* xr = x2n + (size_t)t * DMODEL;
    for (int d = tid; d < DMODEL; d += 256) {
        float xv = xr[d];
#pragma unroll
        for (int e = 0; e < 8; e++) acc[e] += xv * rw[(size_t)d * NEXP + e];
    }
    for (int e = 0; e < 8; e++) {
        red[tid] = acc[e]; __syncthreads();
        for (int o = 128; o > 0; o >>= 1) { if (tid < o) red[tid] += red[tid + o]; __syncthreads(); }
        if (tid == 0) lg[e] = red[0] + rb[e];
        __syncthreads();
    }
    if (tid == 0) {
        float m = lg[0];
        for (int e = 1; e < 8; e++) m = fmaxf(m, lg[e]);
        float p[8], s = 0.f;
        for (int e = 0; e < 8; e++) { p[e] = expf(lg[e] - m); s += p[e]; }
        for (int e = 0; e < 8; e++) p[e] /= s;
        int e0 = 0;
        for (int e = 1; e < 8; e++) if (p[e] > p[e0]) e0 = e;
        int e1 = -1;
        for (int e = 0; e < 8; e++) if (e != e0 && (e1 < 0 || p[e] > p[e1])) e1 = e;
        float denom = p[e0] + p[e1];
        for (int e = 0; e < 8; e++) probs[(size_t)t * NEXP + e] = p[e];
        topE[t * 2 + 0] = e0; topE[t * 2 + 1] = e1;
        topG[t * 2 + 0] = p[e0] / denom; topG[t * 2 + 1] = p[e1] / denom;
    }
}

// ---------------- deterministic grouping (warp-ballot scan, order-preserving) ----------------
__global__ __launch_bounds__(256) void group_kernel(
    const int* __restrict__ topE, int* __restrict__ counts,
    int* __restrict__ segoff, int* __restrict__ rowmap,
    int* __restrict__ slotpos)
{
    __shared__ short sE[TSEQ * 2];
    __shared__ int sSeg[NEXP + 1];
    __shared__ int sCnt[NEXP];
    int tid = threadIdx.x;
    int lane = tid & 31, w = tid >> 5;
    for (int i = tid; i < TSEQ * 2; i += 256) sE[i] = (short)topE[i];
    __syncthreads();

    {
        int e = w;
        int c = 0;
        for (int i0 = 0; i0 < TSEQ * 2; i0 += 32) {
            unsigned int m = __ballot_sync(0xFFFFFFFFu, sE[i0 + lane] == e);
            c += __popc(m);
        }
        if (lane == 0) { counts[e] = c; sCnt[e] = c; }
    }
    __syncthreads();
    if (tid == 0) {
        int o = 0;
        for (int i = 0; i < 8; i++) { sSeg[i] = o; segoff[i] = o; o += sCnt[i]; }
        sSeg[8] = o; segoff[8] = o;
    }
    __syncthreads();

    {
        int e = w;
        int pos = sSeg[e];
        unsigned int ltmask = (1u << lane) - 1u;
        for (int i0 = 0; i0 < TSEQ * 2; i0 += 32) {
            int i = i0 + lane;
            bool match = (sE[i] == e);
            unsigned int m = __ballot_sync(0xFFFFFFFFu, match);
            if (match) {
                int off = __popc(m & ltmask);
                rowmap[pos + off] = i >> 1;
                slotpos[i] = pos + off;
            }
            pos += __popc(m);
        }
    }
}

// ---------------- aux loss ----------------
__global__ __launch_bounds__(256) void aux_kernel(
    const float* __restrict__ probs, const int* __restrict__ counts, float* __restrict__ outAux)
{
    __shared__ float red[256];
    int tid = threadIdx.x;
    float a = 0.f;
    for (int e = 0; e < 8; e++) {
        float s = 0.f;
        for (int t = tid; t < TSEQ; t += 256) s += probs[(size_t)t * NEXP + e];
        red[tid] = s; __syncthreads();
        for (int o = 128; o > 0; o >>= 1) { if (tid < o) red[tid] += red[tid + o]; __syncthreads(); }
        if (tid == 0) a += (float)counts[e] * red[0];
        __syncthreads();
    }
    if (tid == 0) *outAux = 8.f * a / ((float)TSEQ * (float)TSEQ);
}

// ---------------- final combine ----------------
__global__ __launch_bounds__(256) void combine_kernel(
    const float* __restrict__ x1, const float* __restrict__ y,
    const int* __restrict__ slotpos, const float* __restrict__ topG,
    float* __restrict__ out)
{
    int idx = blockIdx.x * 256 + threadIdx.x;
    int t = idx >> 10, d = idx & 1023;
    int p0 = slotpos[t * 2 + 0], p1 = slotpos[t * 2 + 1];
    float g0 = topG[t * 2 + 0], g1 = topG[t * 2 + 1];
    out[idx] = x1[idx] + g0 * y[(size_t)p0 * DMODEL + d] + g1 * y[(size_t)p1 * DMODEL + d];
}

// ---------------- host launch ----------------
#define GETSYM(ptr, sym) do { void* _p_; cudaGetSymbolAddress(&_p_, sym); ptr = (decltype(ptr))_p_; } while (0)

extern "C" void kernel_launch(void* const* d_in, const int* in_sizes, int n_in,
                              void* d_out, int out_size)
{
    const float* x        = (const float*)d_in[0];
    const float* norm1_w  = (const float*)d_in[1];
    const float* norm2_w  = (const float*)d_in[2];
    const float* wq_idx   = (const float*)d_in[3];
    const float* wk_idx   = (const float*)d_in[4];
    const float* w_head   = (const float*)d_in[5];
    const float* wq       = (const float*)d_in[6];
    const float* wk       = (const float*)d_in[7];
    const float* wv       = (const float*)d_in[8];
    const float* wo       = (const float*)d_in[9];
    const float* router_w = (const float*)d_in[10];
    const float* router_b = (const float*)d_in[11];
    const float* w1       = (const float*)d_in[12];
    const float* b1       = (const float*)d_in[13];
    const float* w2       = (const float*)d_in[14];
    const float* b2       = (const float*)d_in[15];

    float* out    = (float*)d_out;
    float* auxp   = out + (size_t)TSEQ * DMODEL;
    float* idxout = auxp + 1;

    float *p_xn, *p_proj, *p_qkv, *p_qh, *p_kh, *p_vh;
    float *p_av, *p_x1, *p_x2n, *p_x2f, *p_probs, *p_topG, *p_mid, *p_y;
    float *p_woc, *p_wqkvc, *p_widxc;
    int *p_topE, *p_counts, *p_segoff, *p_rowmap, *p_slotpos;
    unsigned int *p_mask;
    GETSYM(p_xn, g_xn); GETSYM(p_proj, g_proj_idx); GETSYM(p_qkv, g_qkv);
    GETSYM(p_qh, g_qh); GETSYM(p_kh, g_kh); GETSYM(p_vh, g_vh);
    GETSYM(p_av, g_av); GETSYM(p_x1, g_x1);
    GETSYM(p_x2n, g_x2n); GETSYM(p_x2f, g_x2f);
    GETSYM(p_probs, g_probs); GETSYM(p_topE, g_topE); GETSYM(p_topG, g_topG);
    GETSYM(p_counts, g_counts); GETSYM(p_segoff, g_segoff);
    GETSYM(p_rowmap, g_rowmap); GETSYM(p_slotpos, g_slotpos);
    GETSYM(p_mid, g_mid); GETSYM(p_y, g_yy); GETSYM(p_mask, g_mask);
    GETSYM(p_woc, g_woc); GETSYM(p_wqkvc, g_wqkvc); GETSYM(p_widxc, g_widxc);

    cudaFuncSetAttribute(tgemm<0>, cudaFuncAttributeMaxDynamicSharedMemorySize, TG_SMEM_BYTES);
    cudaFuncSetAttribute(tgemm<1>, cudaFuncAttributeMaxDynamicSharedMemorySize, TG_SMEM_BYTES);

    // 0. small weight rounding / packing (w1/w2 are converted inside the MoE GEMMs)
    {
        int m4 = DMODEL * DMODEL / 4;
        round4_kernel<<<(m4 + 255) / 256, 256>>>((const float4*)wo, (float4*)p_woc, m4);
        pack_qkv_kernel<<<(DMODEL * DMODEL) / 256, 256>>>(wq, wk, wv, p_wqkvc);
        pack_idx_kernel<<<(DMODEL * NPROJ_IDX + 255) / 256, 256>>>(wq_idx, wk_idx, w_head, p_widxc);
    }

    // 1. norm1
    rmsnorm_kernel<<<TSEQ, 256>>>(x, norm1_w, p_xn, nullptr);

    // 2. fused projections
    tgemm<0><<<dim3((NPROJ_IDX + 127) / 128, 16, 1), 256, TG_SMEM_BYTES>>>(
        p_xn, DMODEL, nullptr, p_widxc, 0, nullptr, 0,
        nullptr, p_proj, NPROJ_IDX, nullptr, TSEQ, NPROJ_IDX, DMODEL, 0);
    tgemm<0><<<dim3(NPROJ_QKV / 128, 16, 1), 256, TG_SMEM_BYTES>>>(
        p_xn, DMODEL, nullptr, p_wqkvc, 0, nullptr, 0,
        nullptr, p_qkv, NPROJ_QKV, nullptr, TSEQ, NPROJ_QKV, DMODEL, 0);

    // 3. indexer scores + fused top-512 mask
    idx_kernel<<<dim3(32, 32), 256>>>(p_proj, idxout);
    topk_mask_kernel<<<TSEQ, 512>>>(idxout, p_mask);

    // 4. rope + transpose
    rope_kernel<<<(TSEQ * DMODEL) / 256, 256>>>(p_qkv, p_qh, p_kh, p_vh);

    // 5. dense masked flash attention (128-row q tiles, heavy first)
    attn_flash<<<dim3(TSEQ / 128, NHEAD), 256>>>(p_qh, p_kh, p_vh, p_mask, p_av);

    // 6. output projection + residual
    tgemm<0><<<dim3(8, 16, 1), 256, TG_SMEM_BYTES>>>(p_av, DMODEL, nullptr, p_woc, 0, nullptr, 0,
        x, p_x1, DMODEL, nullptr, TSEQ, DMODEL, DMODEL, 0);

    // 7. norm2 + router + grouping + aux
    rmsnorm_kernel<<<TSEQ, 256>>>(p_x1, norm2_w, p_x2n, p_x2f);
    router_kernel<<<TSEQ, 256>>>(p_x2f, router_w, router_b, p_probs, p_topE, p_topG);
    group_kernel<<<1, 256>>>(p_topE, p_counts, p_segoff, p_rowmap, p_slotpos);
    aux_kernel<<<1, 256>>>(p_probs, p_counts, auxp);

    // 8. MoE grouped GEMMs (raw weights, tf32 cvt at fragment load)
    tgemm<1><<<dim3(DFFN / 128, 16, NEXP), 256, TG_SMEM_BYTES>>>(
        p_x2n, DMODEL, p_rowmap, w1, (long long)DMODEL * DFFN, b1, DFFN,
        nullptr, p_mid, DFFN, p_segoff, 0, DFFN, DMODEL, 1);
    tgemm<1><<<dim3(DMODEL / 128, 16, NEXP), 256, TG_SMEM_BYTES>>>(
        p_mid, DFFN, nullptr, w2, (long long)DFFN * DMODEL, b2, DMODEL,
        nullptr, p_y, DMODEL, p_segoff, 0, DMODEL, DFFN, 0);

    // 9. combine
    combine_kernel<<<(TSEQ * DMODEL) / 256, 256>>>(p_x1, p_y, p_slotpos, p_topG, out);
}